// round 2
// baseline (speedup 1.0000x reference)
#include <cuda_runtime.h>
#include <cuda_bf16.h>
#include <math.h>

// Problem dims (fixed by the dataset)
#define BB 4
#define SS 2048
#define DD 1024
#define HH 4096
#define MM (BB*SS)          // 8192 rows

// ---------------------------------------------------------------------------
// Scratch (static device globals; no allocation in kernel_launch)
// 16B-aligned for float4 paths.
// ---------------------------------------------------------------------------
__device__ __align__(16) float g_t  [(size_t)MM*DD];   // t / rlin / a / u
__device__ __align__(16) float g_xb [(size_t)MM*DD];   // xb / ilin / b / h
__device__ __align__(16) float g_yb [(size_t)MM*DD];   // yb / z
__device__ __align__(16) float g_xc [(size_t)MM*DD];   // conv output
__device__ __align__(16) float g_h1 [(size_t)MM*DD];   // h1
__device__ __align__(16) float g_b1 [(size_t)MM*HH];   // g  / ff
__device__ __align__(16) float g_b2 [(size_t)MM*HH];   // v

// ---------------------------------------------------------------------------
// Math helpers (match JAX semantics: gelu approximate=True, stable softplus)
// ---------------------------------------------------------------------------
__device__ __forceinline__ float geluf(float x) {
    const float c = 0.7978845608028654f; // sqrt(2/pi)
    float x3 = x * x * x;
    float t  = tanhf(c * (x + 0.044715f * x3));
    return 0.5f * x * (1.0f + t);
}
__device__ __forceinline__ float sigmoidf(float x) {
    return 1.0f / (1.0f + expf(-x));
}
__device__ __forceinline__ float softplusf(float x) {
    return fmaxf(x, 0.0f) + log1pf(expf(-fabsf(x)));
}

// ---------------------------------------------------------------------------
// SGEMM: C[M,N] = act(A[M,K] @ B[K,N]) (+ residual)
// 128x128 tile, BK=8, 256 threads, 8x8 microtile, float4 everywhere.
// All shapes here are multiples of the tiles -> no bounds checks.
// ACT: 0 = none, 1 = gelu. RES: add residual R (same layout as C).
// ---------------------------------------------------------------------------
#define BM 128
#define BN 128
#define BK 8

template<int ACT, bool RES>
__global__ void __launch_bounds__(256)
sgemm_kernel(const float* __restrict__ A, const float* __restrict__ B,
             const float* __restrict__ R, float* __restrict__ C,
             int M, int N, int K)
{
    __shared__ __align__(16) float As[BK][BM + 4];
    __shared__ __align__(16) float Bs[BK][BN];

    const int bm  = blockIdx.y * BM;
    const int bn  = blockIdx.x * BN;
    const int tid = threadIdx.x;

    const int aRow  = tid >> 1;          // 0..127
    const int aCol4 = (tid & 1) << 2;    // 0 or 4
    const int bRow  = tid >> 5;          // 0..7
    const int bCol4 = (tid & 31) << 2;   // 0..124

    const int ty = tid >> 4;             // 0..15
    const int tx = tid & 15;             // 0..15

    float acc[8][8];
    #pragma unroll
    for (int i = 0; i < 8; i++)
        #pragma unroll
        for (int j = 0; j < 8; j++) acc[i][j] = 0.0f;

    for (int k0 = 0; k0 < K; k0 += BK) {
        float4 av = *(const float4*)(A + (size_t)(bm + aRow) * K + k0 + aCol4);
        float4 bv = *(const float4*)(B + (size_t)(k0 + bRow) * N + bn + bCol4);
        __syncthreads();
        As[aCol4 + 0][aRow] = av.x;
        As[aCol4 + 1][aRow] = av.y;
        As[aCol4 + 2][aRow] = av.z;
        As[aCol4 + 3][aRow] = av.w;
        *(float4*)&Bs[bRow][bCol4] = bv;
        __syncthreads();

        #pragma unroll
        for (int k = 0; k < BK; k++) {
            float a[8], b[8];
            #pragma unroll
            for (int i = 0; i < 8; i++) a[i] = As[k][ty * 8 + i];
            #pragma unroll
            for (int j = 0; j < 8; j++) b[j] = Bs[k][tx * 8 + j];
            #pragma unroll
            for (int i = 0; i < 8; i++)
                #pragma unroll
                for (int j = 0; j < 8; j++)
                    acc[i][j] = fmaf(a[i], b[j], acc[i][j]);
        }
    }

    #pragma unroll
    for (int i = 0; i < 8; i++) {
        const size_t row = (size_t)(bm + ty * 8 + i);
        #pragma unroll
        for (int j = 0; j < 8; j += 4) {
            const int col = bn + tx * 8 + j;
            float4 v = make_float4(acc[i][j], acc[i][j+1], acc[i][j+2], acc[i][j+3]);
            if (ACT == 1) {
                v.x = geluf(v.x); v.y = geluf(v.y);
                v.z = geluf(v.z); v.w = geluf(v.w);
            }
            if (RES) {
                float4 r = *(const float4*)(R + row * N + col);
                v.x += r.x; v.y += r.y; v.z += r.z; v.w += r.w;
            }
            *(float4*)(C + row * N + col) = v;
        }
    }
}

// ---------------------------------------------------------------------------
// RMSNorm: one block per row, D=1024
// ---------------------------------------------------------------------------
__global__ void rmsnorm_kernel(const float* __restrict__ x,
                               const float* __restrict__ w,
                               float* __restrict__ o, int D)
{
    const int row = blockIdx.x;
    const float* xr = x + (size_t)row * D;
    float ss = 0.0f;
    for (int i = threadIdx.x; i < D; i += blockDim.x) {
        float v = xr[i];
        ss = fmaf(v, v, ss);
    }
    // warp reduce
    #pragma unroll
    for (int off = 16; off > 0; off >>= 1)
        ss += __shfl_xor_sync(0xffffffff, ss, off);
    __shared__ float red[32];
    const int lane = threadIdx.x & 31, wid = threadIdx.x >> 5;
    if (lane == 0) red[wid] = ss;
    __syncthreads();
    const int nw = blockDim.x >> 5;
    if (wid == 0) {
        float s = (lane < nw) ? red[lane] : 0.0f;
        #pragma unroll
        for (int off = 16; off > 0; off >>= 1)
            s += __shfl_xor_sync(0xffffffff, s, off);
        if (lane == 0) red[0] = s;
    }
    __syncthreads();
    const float inv = rsqrtf(red[0] / (float)D + 1e-6f);
    float* orow = o + (size_t)row * D;
    for (int i = threadIdx.x; i < D; i += blockDim.x)
        orow[i] = xr[i] * inv * w[i];
}

// ---------------------------------------------------------------------------
// Causal depthwise conv, K=4 taps
// ---------------------------------------------------------------------------
__global__ void conv_kernel(const float* __restrict__ in,
                            const float* __restrict__ cw,
                            const float* __restrict__ cb,
                            float* __restrict__ out)
{
    const size_t idx = (size_t)blockIdx.x * blockDim.x + threadIdx.x;
    const size_t total = (size_t)MM * DD;
    if (idx >= total) return;
    const int d = (int)(idx % DD);
    const int s = (int)((idx / DD) % SS);
    float acc = cb[d];
    #pragma unroll
    for (int k = 0; k < 4; k++) {
        const int sp = s + k - 3;
        if (sp >= 0)
            acc = fmaf(cw[k * DD + d], in[idx - (size_t)(3 - k) * DD], acc);
    }
    out[idx] = acc;
}

// ---------------------------------------------------------------------------
// RG-LRU gates: a = exp(-8*softplus(lam)*sigmoid(rlin)),
//               b = sqrt(max(1-a^2,1e-12)) * sigmoid(ilin) * xc
// In-place over rlin/ilin buffers.
// ---------------------------------------------------------------------------
__global__ void gates_kernel(float* __restrict__ rlin_a,   // in: rlin, out: a
                             float* __restrict__ ilin_b,   // in: ilin, out: b
                             const float* __restrict__ xc,
                             const float* __restrict__ lam)
{
    const size_t idx = (size_t)blockIdx.x * blockDim.x + threadIdx.x;
    if (idx >= (size_t)MM * DD) return;
    const int d = (int)(idx % DD);
    const float r  = sigmoidf(rlin_a[idx]);
    const float ii = sigmoidf(ilin_b[idx]);
    const float a  = expf(-8.0f * softplusf(lam[d]) * r);
    const float b  = sqrtf(fmaxf(1.0f - a * a, 1e-12f)) * ii * xc[idx];
    rlin_a[idx] = a;
    ilin_b[idx] = b;
}

// ---------------------------------------------------------------------------
// Sequential diagonal scan: h_s = a_s*h_{s-1} + b_s  (in-place over b)
// One thread per (batch, channel): 4096 threads, coalesced over d.
// ---------------------------------------------------------------------------
__global__ void scan_kernel(const float* __restrict__ a, float* __restrict__ b)
{
    const int c = blockIdx.x * blockDim.x + threadIdx.x;
    if (c >= BB * DD) return;
    const int batch = c / DD, d = c % DD;
    const float* ap = a + (size_t)batch * SS * DD + d;
    float*       bp = b + (size_t)batch * SS * DD + d;
    float h = 0.0f;
    for (int s = 0; s < SS; s++) {
        const size_t off = (size_t)s * DD;
        h = fmaf(ap[off], h, bp[off]);
        bp[off] = h;
    }
}

// z = h * yb (in-place over yb)
__global__ void mul_kernel(const float* __restrict__ h, float* __restrict__ yb)
{
    const size_t idx = (size_t)blockIdx.x * blockDim.x + threadIdx.x;
    if (idx >= (size_t)MM * DD) return;
    yb[idx] = h[idx] * yb[idx];
}

// ff = gelu(g) * v (in-place over g)
__global__ void ffnact_kernel(float* __restrict__ g, const float* __restrict__ v)
{
    const size_t idx = (size_t)blockIdx.x * blockDim.x + threadIdx.x;
    if (idx >= (size_t)MM * HH) return;
    g[idx] = geluf(g[idx]) * v[idx];
}

// ---------------------------------------------------------------------------
// Launch
// ---------------------------------------------------------------------------
extern "C" void kernel_launch(void* const* d_in, const int* in_sizes, int n_in,
                              void* d_out, int out_size)
{
    const float* x       = (const float*)d_in[0];
    const float* norm1_w = (const float*)d_in[1];
    const float* Wx      = (const float*)d_in[2];
    const float* Wy      = (const float*)d_in[3];
    const float* conv_w  = (const float*)d_in[4];
    const float* conv_b  = (const float*)d_in[5];
    const float* Wi      = (const float*)d_in[6];
    const float* Wa      = (const float*)d_in[7];
    const float* lam     = (const float*)d_in[8];
    const float* Wo      = (const float*)d_in[9];
    const float* norm2_w = (const float*)d_in[10];
    const float* Wg      = (const float*)d_in[11];
    const float* Wu      = (const float*)d_in[12];
    const float* Wd      = (const float*)d_in[13];
    float* out = (float*)d_out;

    float *t, *xb, *yb, *xc, *h1, *b1, *b2;
    if (cudaGetSymbolAddress((void**)&t,  g_t)  != cudaSuccess) return;
    if (cudaGetSymbolAddress((void**)&xb, g_xb) != cudaSuccess) return;
    if (cudaGetSymbolAddress((void**)&yb, g_yb) != cudaSuccess) return;
    if (cudaGetSymbolAddress((void**)&xc, g_xc) != cudaSuccess) return;
    if (cudaGetSymbolAddress((void**)&h1, g_h1) != cudaSuccess) return;
    if (cudaGetSymbolAddress((void**)&b1, g_b1) != cudaSuccess) return;
    if (cudaGetSymbolAddress((void**)&b2, g_b2) != cudaSuccess) return;

    const dim3 gD(DD / BN, MM / BM);   // C is M x 1024
    const dim3 gH(HH / BN, MM / BM);   // C is M x 4096
    const size_t nMD = (size_t)MM * DD;
    const size_t nMH = (size_t)MM * HH;
    const int EW = 256;
    const int gMD = (int)((nMD + EW - 1) / EW);
    const int gMH = (int)((nMH + EW - 1) / EW);

    // 1) t = rmsnorm(x, norm1_w)
    rmsnorm_kernel<<<MM, 256>>>(x, norm1_w, t, DD);
    // 2) xb = t @ Wx              (M=8192, N=1024, K=1024)
    sgemm_kernel<0, false><<<gD, 256>>>(t, Wx, nullptr, xb, MM, DD, DD);
    // 3) yb = gelu(t @ Wy)
    sgemm_kernel<1, false><<<gD, 256>>>(t, Wy, nullptr, yb, MM, DD, DD);
    // 4) xc = causal_depthwise_conv(xb)
    conv_kernel<<<gMD, EW>>>(xb, conv_w, conv_b, xc);
    // 5) rlin = xc @ Wa -> t ; 6) ilin = xc @ Wi -> xb
    sgemm_kernel<0, false><<<gD, 256>>>(xc, Wa, nullptr, t,  MM, DD, DD);
    sgemm_kernel<0, false><<<gD, 256>>>(xc, Wi, nullptr, xb, MM, DD, DD);
    // 7) gates: t -> a, xb -> b
    gates_kernel<<<gMD, EW>>>(t, xb, xc, lam);
    // 8) scan: xb -> h (in place)
    scan_kernel<<<(BB * DD + 255) / 256, 256>>>(t, xb);
    // 9) z = h * yb (into yb)
    mul_kernel<<<gMD, EW>>>(xb, yb);
    // 10) h1 = x + z @ Wo         (M=8192, N=1024, K=1024)
    sgemm_kernel<0, true><<<gD, 256>>>(yb, Wo, x, h1, MM, DD, DD);
    // 11) u = rmsnorm(h1, norm2_w) -> t
    rmsnorm_kernel<<<MM, 256>>>(h1, norm2_w, t, DD);
    // 12) g = u @ Wg -> b1        (M=8192, N=4096, K=1024)  [dims FIXED]
    sgemm_kernel<0, false><<<gH, 256>>>(t, Wg, nullptr, b1, MM, HH, DD);
    // 13) v = u @ Wu -> b2        (M=8192, N=4096, K=1024)  [dims FIXED]
    sgemm_kernel<0, false><<<gH, 256>>>(t, Wu, nullptr, b2, MM, HH, DD);
    // 14) ff = gelu(g) * v -> b1
    ffnact_kernel<<<gMH, EW>>>(b1, b2);
    // 15) out = h1 + ff @ Wd      (M=8192, N=1024, K=4096)  [dims FIXED]
    sgemm_kernel<0, true><<<gD, 256>>>(b1, Wd, h1, out, MM, DD, HH);
}

// round 4
// speedup vs baseline: 2.1492x; 2.1492x over previous
#include <cuda_runtime.h>
#include <cuda_bf16.h>
#include <math.h>
#include <stdint.h>

// Problem dims (fixed by the dataset)
#define BB 4
#define SS 2048
#define DD 1024
#define HH 4096
#define MM (BB*SS)          // 8192 rows

// ---------------------------------------------------------------------------
// Scratch (static device globals; no allocation in kernel_launch)
// ---------------------------------------------------------------------------
__device__ __align__(16) float g_t  [(size_t)MM*DD];
__device__ __align__(16) float g_xb [(size_t)MM*DD];
__device__ __align__(16) float g_yb [(size_t)MM*DD];
__device__ __align__(16) float g_xc [(size_t)MM*DD];
__device__ __align__(16) float g_h1 [(size_t)MM*DD];
__device__ __align__(16) float g_b1 [(size_t)MM*HH];
__device__ __align__(16) float g_b2 [(size_t)MM*HH];

// bf16 split buffers for GEMM A operands (sized for the largest, 8192x4096)
__device__ __align__(16) __nv_bfloat16 g_ah[(size_t)MM*HH];
__device__ __align__(16) __nv_bfloat16 g_al[(size_t)MM*HH];
// bf16 split+transposed weights, packed arena
#define WOFF_X  ((size_t)0)
#define WOFF_Y  ((size_t)1*1024*1024)
#define WOFF_A  ((size_t)2*1024*1024)
#define WOFF_I  ((size_t)3*1024*1024)
#define WOFF_O  ((size_t)4*1024*1024)
#define WOFF_G  ((size_t)5*1024*1024)
#define WOFF_U  ((size_t)9*1024*1024)
#define WOFF_D  ((size_t)13*1024*1024)
__device__ __align__(16) __nv_bfloat16 g_wh[(size_t)17*1024*1024];
__device__ __align__(16) __nv_bfloat16 g_wl[(size_t)17*1024*1024];

// ---------------------------------------------------------------------------
// Math helpers
// ---------------------------------------------------------------------------
__device__ __forceinline__ float geluf(float x) {
    const float c = 0.7978845608028654f; // sqrt(2/pi)
    float x3 = x * x * x;
    float t  = tanhf(c * (x + 0.044715f * x3));
    return 0.5f * x * (1.0f + t);
}
__device__ __forceinline__ float sigmoidf(float x) {
    return 1.0f / (1.0f + expf(-x));
}
__device__ __forceinline__ float softplusf(float x) {
    return fmaxf(x, 0.0f) + log1pf(expf(-fabsf(x)));
}

// ---------------------------------------------------------------------------
// PTX helpers (baseline compute_103 features only: cp.async, ldmatrix, mma.sync)
// ---------------------------------------------------------------------------
__device__ __forceinline__ uint32_t smem_u32(const void* p) {
    uint32_t a;
    asm("{ .reg .u64 t; cvta.to.shared.u64 t, %1; cvt.u32.u64 %0, t; }" : "=r"(a) : "l"(p));
    return a;
}
__device__ __forceinline__ void cp_async16(uint32_t dst, const void* src) {
    asm volatile("cp.async.cg.shared.global [%0], [%1], 16;" :: "r"(dst), "l"(src) : "memory");
}
__device__ __forceinline__ void ldm_x4(uint32_t& r0, uint32_t& r1, uint32_t& r2, uint32_t& r3,
                                       uint32_t addr) {
    asm volatile("ldmatrix.sync.aligned.m8n8.x4.shared.b16 {%0,%1,%2,%3}, [%4];"
                 : "=r"(r0), "=r"(r1), "=r"(r2), "=r"(r3) : "r"(addr));
}
__device__ __forceinline__ void ldm_x2(uint32_t& r0, uint32_t& r1, uint32_t addr) {
    asm volatile("ldmatrix.sync.aligned.m8n8.x2.shared.b16 {%0,%1}, [%2];"
                 : "=r"(r0), "=r"(r1) : "r"(addr));
}
__device__ __forceinline__ void mma16816(float* c, const uint32_t* a, const uint32_t* b) {
    asm volatile(
        "mma.sync.aligned.m16n8k16.row.col.f32.bf16.bf16.f32 "
        "{%0,%1,%2,%3}, {%4,%5,%6,%7}, {%8,%9}, {%0,%1,%2,%3};"
        : "+f"(c[0]), "+f"(c[1]), "+f"(c[2]), "+f"(c[3])
        : "r"(a[0]), "r"(a[1]), "r"(a[2]), "r"(a[3]), "r"(b[0]), "r"(b[1]));
}

// ---------------------------------------------------------------------------
// Split-bf16 HMMA GEMM: C[M,N] = act(A @ W^T) (+R)
//   A as Ah/Al bf16 [M,K] row-major; W as Bh/Bl bf16 [N,K] row-major.
//   C = Ah*Bh + Al*Bh + Ah*Bl (fp32 accum).
// CTA 128x128, BK=32, 8 warps (2Mx4N), warp tile 64x32, 2-stage cp.async.
// SMEM per tile: 128 rows x 80B (64B data + 16B pad; stride 20 banks -> no
// ldmatrix conflicts). Stage = 4 tiles * 10240B = 40960B; 2 stages = 81920B.
// ---------------------------------------------------------------------------
#define GSTRIDE 80u
#define TILE_B  10240u
#define STG_B   40960u
#define GEMM_SMEM (2*STG_B)

template<int ACT, bool RES>
__global__ void __launch_bounds__(256, 1)
hmma_gemm(const __nv_bfloat16* __restrict__ Ah, const __nv_bfloat16* __restrict__ Al,
          const __nv_bfloat16* __restrict__ Bh, const __nv_bfloat16* __restrict__ Bl,
          const float* __restrict__ R, float* __restrict__ C,
          int N_, int K)
{
    extern __shared__ char smem[];
    const uint32_t sb = smem_u32(smem);
    const int tid  = threadIdx.x;
    const int wid  = tid >> 5;
    const int lane = tid & 31;
    const int bm = blockIdx.y * 128;
    const int bn = blockIdx.x * 128;
    const int wr = wid >> 2;          // 0..1 : warp row (64 rows)
    const int wc = wid & 3;           // 0..3 : warp col (32 cols)

    const int nch = K >> 5;           // BK = 32

    auto fill = [&](int ch) {
        const int k0 = ch << 5;
        const uint32_t st = sb + (uint32_t)(ch & 1) * STG_B;
        // A tiles: 512 chunks of 16B each (hi & lo)
        #pragma unroll
        for (int r = 0; r < 2; r++) {
            const int c = tid + (r << 8);
            const int row = c >> 2, kc = c & 3;
            const uint32_t dst = st + (uint32_t)row * GSTRIDE + (uint32_t)(kc << 4);
            const size_t  src = (size_t)(bm + row) * K + k0 + (kc << 3);
            cp_async16(dst,          Ah + src);
            cp_async16(dst + TILE_B, Al + src);
        }
        // B tiles: 512 chunks of 16B each (hi & lo)
        #pragma unroll
        for (int r = 0; r < 2; r++) {
            const int c = tid + (r << 8);
            const int row = c >> 2, kc = c & 3;
            const uint32_t dst = st + 2*TILE_B + (uint32_t)row * GSTRIDE + (uint32_t)(kc << 4);
            const size_t  src = (size_t)(bn + row) * K + k0 + (kc << 3);
            cp_async16(dst,          Bh + src);
            cp_async16(dst + TILE_B, Bl + src);
        }
        asm volatile("cp.async.commit_group;" ::: "memory");
    };

    float acc[4][4][4];
    #pragma unroll
    for (int i = 0; i < 4; i++)
        #pragma unroll
        for (int j = 0; j < 4; j++)
            #pragma unroll
            for (int q = 0; q < 4; q++) acc[i][j][q] = 0.0f;

    fill(0);
    if (nch > 1) fill(1);

    const int l16  = lane & 15;
    const int ahi  = (lane >> 4) << 4;      // +16B for lanes 16-31 (k high half)
    const int bl8  = lane & 7;
    const int bhi  = ((lane >> 3) & 1) << 4;

    for (int i = 0; i < nch; i++) {
        if (i + 1 < nch) asm volatile("cp.async.wait_group 1;" ::: "memory");
        else             asm volatile("cp.async.wait_group 0;" ::: "memory");
        __syncthreads();

        const uint32_t st  = sb + (uint32_t)(i & 1) * STG_B;
        const uint32_t sAh = st;
        const uint32_t sAl = st + TILE_B;
        const uint32_t sBh = st + 2*TILE_B;
        const uint32_t sBl = st + 3*TILE_B;

        #pragma unroll
        for (int ks = 0; ks < 2; ks++) {
            uint32_t ah[4][4], al[4][4], bh[4][2], bl[4][2];
            #pragma unroll
            for (int mt = 0; mt < 4; mt++) {
                const uint32_t ra = (uint32_t)(wr*64 + mt*16 + l16) * GSTRIDE
                                  + (uint32_t)(ks*32 + ahi);
                ldm_x4(ah[mt][0], ah[mt][1], ah[mt][2], ah[mt][3], sAh + ra);
                ldm_x4(al[mt][0], al[mt][1], al[mt][2], al[mt][3], sAl + ra);
            }
            #pragma unroll
            for (int nt = 0; nt < 4; nt++) {
                const uint32_t rb = (uint32_t)(wc*32 + nt*8 + bl8) * GSTRIDE
                                  + (uint32_t)(ks*32 + bhi);
                ldm_x2(bh[nt][0], bh[nt][1], sBh + rb);
                ldm_x2(bl[nt][0], bl[nt][1], sBl + rb);
            }
            #pragma unroll
            for (int mt = 0; mt < 4; mt++)
                #pragma unroll
                for (int nt = 0; nt < 4; nt++) {
                    mma16816(acc[mt][nt], ah[mt], bh[nt]);
                    mma16816(acc[mt][nt], al[mt], bh[nt]);
                    mma16816(acc[mt][nt], ah[mt], bl[nt]);
                }
        }
        __syncthreads();
        if (i + 2 < nch) fill(i + 2);
    }

    // Epilogue: fragment (mt,nt): rows bm+wr*64+mt*16+{lane/4, +8},
    //           cols bn+wc*32+nt*8+(lane%4)*2
    const int erow = lane >> 2;
    const int ecol = (lane & 3) << 1;
    #pragma unroll
    for (int mt = 0; mt < 4; mt++) {
        #pragma unroll
        for (int nt = 0; nt < 4; nt++) {
            const int r0 = bm + wr*64 + mt*16 + erow;
            const int cc = bn + wc*32 + nt*8 + ecol;
            float v0 = acc[mt][nt][0], v1 = acc[mt][nt][1];
            float v2 = acc[mt][nt][2], v3 = acc[mt][nt][3];
            if (ACT == 1) { v0 = geluf(v0); v1 = geluf(v1); v2 = geluf(v2); v3 = geluf(v3); }
            if (RES) {
                const float2 ra = *(const float2*)(R + (size_t)r0 * N_ + cc);
                const float2 rb = *(const float2*)(R + (size_t)(r0+8) * N_ + cc);
                v0 += ra.x; v1 += ra.y; v2 += rb.x; v3 += rb.y;
            }
            *(float2*)(C + (size_t)r0     * N_ + cc) = make_float2(v0, v1);
            *(float2*)(C + (size_t)(r0+8) * N_ + cc) = make_float2(v2, v3);
        }
    }
}

// ---------------------------------------------------------------------------
// fp32 -> (hi,lo) bf16 split, elementwise (vectorized by 4)
// ---------------------------------------------------------------------------
__global__ void split_kernel(const float* __restrict__ in,
                             __nv_bfloat16* __restrict__ hi,
                             __nv_bfloat16* __restrict__ lo, size_t n4)
{
    const size_t i = (size_t)blockIdx.x * blockDim.x + threadIdx.x;
    if (i >= n4) return;
    const float4 v = *(const float4*)(in + i * 4);
    __nv_bfloat16 h0 = __float2bfloat16(v.x), h1 = __float2bfloat16(v.y);
    __nv_bfloat16 h2 = __float2bfloat16(v.z), h3 = __float2bfloat16(v.w);
    __nv_bfloat16 l0 = __float2bfloat16(v.x - __bfloat162float(h0));
    __nv_bfloat16 l1 = __float2bfloat16(v.y - __bfloat162float(h1));
    __nv_bfloat16 l2 = __float2bfloat16(v.z - __bfloat162float(h2));
    __nv_bfloat16 l3 = __float2bfloat16(v.w - __bfloat162float(h3));
    __nv_bfloat162* hp = (__nv_bfloat162*)(hi + i * 4);
    __nv_bfloat162* lp = (__nv_bfloat162*)(lo + i * 4);
    hp[0] = __nv_bfloat162{h0, h1}; hp[1] = __nv_bfloat162{h2, h3};
    lp[0] = __nv_bfloat162{l0, l1}; lp[1] = __nv_bfloat162{l2, l3};
}

// ---------------------------------------------------------------------------
// Weight transpose + split: W [Kd, Nd] fp32 -> Th/Tl [Nd, Kd] bf16
// ---------------------------------------------------------------------------
__global__ void tsplit_kernel(const float* __restrict__ W,
                              __nv_bfloat16* __restrict__ Th,
                              __nv_bfloat16* __restrict__ Tl,
                              int Kd, int Nd)
{
    __shared__ float tile[32][33];
    const int n0 = blockIdx.x * 32, k0 = blockIdx.y * 32;
    const int tx = threadIdx.x, ty = threadIdx.y;   // (32, 8)
    #pragma unroll
    for (int i = 0; i < 32; i += 8)
        tile[ty + i][tx] = W[(size_t)(k0 + ty + i) * Nd + n0 + tx];
    __syncthreads();
    #pragma unroll
    for (int i = 0; i < 32; i += 8) {
        const float v = tile[tx][ty + i];
        const __nv_bfloat16 h = __float2bfloat16(v);
        const __nv_bfloat16 l = __float2bfloat16(v - __bfloat162float(h));
        const size_t o = (size_t)(n0 + ty + i) * Kd + k0 + tx;
        Th[o] = h; Tl[o] = l;
    }
}

// ---------------------------------------------------------------------------
// RMSNorm
// ---------------------------------------------------------------------------
__global__ void rmsnorm_kernel(const float* __restrict__ x,
                               const float* __restrict__ w,
                               float* __restrict__ o, int D)
{
    const int row = blockIdx.x;
    const float* xr = x + (size_t)row * D;
    float ss = 0.0f;
    for (int i = threadIdx.x; i < D; i += blockDim.x) {
        float v = xr[i];
        ss = fmaf(v, v, ss);
    }
    #pragma unroll
    for (int off = 16; off > 0; off >>= 1)
        ss += __shfl_xor_sync(0xffffffff, ss, off);
    __shared__ float red[32];
    const int lane = threadIdx.x & 31, wid = threadIdx.x >> 5;
    if (lane == 0) red[wid] = ss;
    __syncthreads();
    const int nw = blockDim.x >> 5;
    if (wid == 0) {
        float s = (lane < nw) ? red[lane] : 0.0f;
        #pragma unroll
        for (int off = 16; off > 0; off >>= 1)
            s += __shfl_xor_sync(0xffffffff, s, off);
        if (lane == 0) red[0] = s;
    }
    __syncthreads();
    const float inv = rsqrtf(red[0] / (float)D + 1e-6f);
    float* orow = o + (size_t)row * D;
    for (int i = threadIdx.x; i < D; i += blockDim.x)
        orow[i] = xr[i] * inv * w[i];
}

// ---------------------------------------------------------------------------
// Causal depthwise conv, K=4 taps
// ---------------------------------------------------------------------------
__global__ void conv_kernel(const float* __restrict__ in,
                            const float* __restrict__ cw,
                            const float* __restrict__ cb,
                            float* __restrict__ out)
{
    const size_t idx = (size_t)blockIdx.x * blockDim.x + threadIdx.x;
    if (idx >= (size_t)MM * DD) return;
    const int d = (int)(idx % DD);
    const int s = (int)((idx / DD) % SS);
    float acc = cb[d];
    #pragma unroll
    for (int k = 0; k < 4; k++) {
        const int sp = s + k - 3;
        if (sp >= 0)
            acc = fmaf(cw[k * DD + d], in[idx - (size_t)(3 - k) * DD], acc);
    }
    out[idx] = acc;
}

// ---------------------------------------------------------------------------
// RG-LRU gates
// ---------------------------------------------------------------------------
__global__ void gates_kernel(float* __restrict__ rlin_a,
                             float* __restrict__ ilin_b,
                             const float* __restrict__ xc,
                             const float* __restrict__ lam)
{
    const size_t idx = (size_t)blockIdx.x * blockDim.x + threadIdx.x;
    if (idx >= (size_t)MM * DD) return;
    const int d = (int)(idx % DD);
    const float r  = sigmoidf(rlin_a[idx]);
    const float ii = sigmoidf(ilin_b[idx]);
    const float a  = expf(-8.0f * softplusf(lam[d]) * r);
    const float b  = sqrtf(fmaxf(1.0f - a * a, 1e-12f)) * ii * xc[idx];
    rlin_a[idx] = a;
    ilin_b[idx] = b;
}

// ---------------------------------------------------------------------------
// Sequential diagonal scan (in-place over b)
// ---------------------------------------------------------------------------
__global__ void scan_kernel(const float* __restrict__ a, float* __restrict__ b)
{
    const int c = blockIdx.x * blockDim.x + threadIdx.x;
    if (c >= BB * DD) return;
    const int batch = c / DD, d = c % DD;
    const float* ap = a + (size_t)batch * SS * DD + d;
    float*       bp = b + (size_t)batch * SS * DD + d;
    float h = 0.0f;
    for (int s = 0; s < SS; s++) {
        const size_t off = (size_t)s * DD;
        h = fmaf(ap[off], h, bp[off]);
        bp[off] = h;
    }
}

__global__ void mul_kernel(const float* __restrict__ h, float* __restrict__ yb)
{
    const size_t idx = (size_t)blockIdx.x * blockDim.x + threadIdx.x;
    if (idx >= (size_t)MM * DD) return;
    yb[idx] = h[idx] * yb[idx];
}

__global__ void ffnact_kernel(float* __restrict__ g, const float* __restrict__ v)
{
    const size_t idx = (size_t)blockIdx.x * blockDim.x + threadIdx.x;
    if (idx >= (size_t)MM * HH) return;
    g[idx] = geluf(g[idx]) * v[idx];
}

// ---------------------------------------------------------------------------
// Launch
// ---------------------------------------------------------------------------
extern "C" void kernel_launch(void* const* d_in, const int* in_sizes, int n_in,
                              void* d_out, int out_size)
{
    const float* x       = (const float*)d_in[0];
    const float* norm1_w = (const float*)d_in[1];
    const float* Wx      = (const float*)d_in[2];
    const float* Wy      = (const float*)d_in[3];
    const float* conv_w  = (const float*)d_in[4];
    const float* conv_b  = (const float*)d_in[5];
    const float* Wi      = (const float*)d_in[6];
    const float* Wa      = (const float*)d_in[7];
    const float* lam     = (const float*)d_in[8];
    const float* Wo      = (const float*)d_in[9];
    const float* norm2_w = (const float*)d_in[10];
    const float* Wg      = (const float*)d_in[11];
    const float* Wu      = (const float*)d_in[12];
    const float* Wd      = (const float*)d_in[13];
    float* out = (float*)d_out;

    float *t, *xb, *yb, *xc, *h1, *b1, *b2;
    __nv_bfloat16 *ah, *al, *wh, *wl;
    cudaGetSymbolAddress((void**)&t,  g_t);
    cudaGetSymbolAddress((void**)&xb, g_xb);
    cudaGetSymbolAddress((void**)&yb, g_yb);
    cudaGetSymbolAddress((void**)&xc, g_xc);
    cudaGetSymbolAddress((void**)&h1, g_h1);
    cudaGetSymbolAddress((void**)&b1, g_b1);
    cudaGetSymbolAddress((void**)&b2, g_b2);
    cudaGetSymbolAddress((void**)&ah, g_ah);
    cudaGetSymbolAddress((void**)&al, g_al);
    cudaGetSymbolAddress((void**)&wh, g_wh);
    cudaGetSymbolAddress((void**)&wl, g_wl);

    cudaFuncSetAttribute(hmma_gemm<0,false>, cudaFuncAttributeMaxDynamicSharedMemorySize, GEMM_SMEM);
    cudaFuncSetAttribute(hmma_gemm<1,false>, cudaFuncAttributeMaxDynamicSharedMemorySize, GEMM_SMEM);
    cudaFuncSetAttribute(hmma_gemm<0,true>,  cudaFuncAttributeMaxDynamicSharedMemorySize, GEMM_SMEM);

    const dim3 tsb(32, 8);
    const size_t nMD = (size_t)MM * DD, nMH = (size_t)MM * HH;
    const int EW = 256;
    const int gMD = (int)((nMD + EW - 1) / EW);
    const int gMH = (int)((nMH + EW - 1) / EW);
    const int sMD = (int)(nMD / 4 / 256);
    const int sMH = (int)(nMH / 4 / 256);

    const dim3 gemD(DD / 128, MM / 128);    // C: M x 1024
    const dim3 gemH(HH / 128, MM / 128);    // C: M x 4096

    // --- weight prep: transpose + bf16 split (W [K,N] -> [N,K]) ---
    tsplit_kernel<<<dim3(DD/32, DD/32), tsb>>>(Wx, wh + WOFF_X, wl + WOFF_X, DD, DD);
    tsplit_kernel<<<dim3(DD/32, DD/32), tsb>>>(Wy, wh + WOFF_Y, wl + WOFF_Y, DD, DD);
    tsplit_kernel<<<dim3(DD/32, DD/32), tsb>>>(Wa, wh + WOFF_A, wl + WOFF_A, DD, DD);
    tsplit_kernel<<<dim3(DD/32, DD/32), tsb>>>(Wi, wh + WOFF_I, wl + WOFF_I, DD, DD);
    tsplit_kernel<<<dim3(DD/32, DD/32), tsb>>>(Wo, wh + WOFF_O, wl + WOFF_O, DD, DD);
    tsplit_kernel<<<dim3(HH/32, DD/32), tsb>>>(Wg, wh + WOFF_G, wl + WOFF_G, DD, HH);
    tsplit_kernel<<<dim3(HH/32, DD/32), tsb>>>(Wu, wh + WOFF_U, wl + WOFF_U, DD, HH);
    tsplit_kernel<<<dim3(DD/32, HH/32), tsb>>>(Wd, wh + WOFF_D, wl + WOFF_D, HH, DD);

    // 1) t = rmsnorm(x)
    rmsnorm_kernel<<<MM, 256>>>(x, norm1_w, t, DD);
    split_kernel<<<sMD, 256>>>(t, ah, al, nMD / 4);
    // 2) xb = t @ Wx ; 3) yb = gelu(t @ Wy)
    hmma_gemm<0,false><<<gemD, 256, GEMM_SMEM>>>(ah, al, wh + WOFF_X, wl + WOFF_X, nullptr, xb, DD, DD);
    hmma_gemm<1,false><<<gemD, 256, GEMM_SMEM>>>(ah, al, wh + WOFF_Y, wl + WOFF_Y, nullptr, yb, DD, DD);
    // 4) conv
    conv_kernel<<<gMD, EW>>>(xb, conv_w, conv_b, xc);
    split_kernel<<<sMD, 256>>>(xc, ah, al, nMD / 4);
    // 5) rlin = xc @ Wa -> t ; 6) ilin = xc @ Wi -> xb
    hmma_gemm<0,false><<<gemD, 256, GEMM_SMEM>>>(ah, al, wh + WOFF_A, wl + WOFF_A, nullptr, t,  DD, DD);
    hmma_gemm<0,false><<<gemD, 256, GEMM_SMEM>>>(ah, al, wh + WOFF_I, wl + WOFF_I, nullptr, xb, DD, DD);
    // 7) gates ; 8) scan ; 9) z = h*yb
    gates_kernel<<<gMD, EW>>>(t, xb, xc, lam);
    scan_kernel<<<(BB * DD + 255) / 256, 256>>>(t, xb);
    mul_kernel<<<gMD, EW>>>(xb, yb);
    // 10) h1 = x + z @ Wo
    split_kernel<<<sMD, 256>>>(yb, ah, al, nMD / 4);
    hmma_gemm<0,true><<<gemD, 256, GEMM_SMEM>>>(ah, al, wh + WOFF_O, wl + WOFF_O, x, h1, DD, DD);
    // 11) u = rmsnorm(h1) -> t
    rmsnorm_kernel<<<MM, 256>>>(h1, norm2_w, t, DD);
    split_kernel<<<sMD, 256>>>(t, ah, al, nMD / 4);
    // 12) g = u @ Wg -> b1 ; 13) v = u @ Wu -> b2
    hmma_gemm<0,false><<<gemH, 256, GEMM_SMEM>>>(ah, al, wh + WOFF_G, wl + WOFF_G, nullptr, b1, HH, DD);
    hmma_gemm<0,false><<<gemH, 256, GEMM_SMEM>>>(ah, al, wh + WOFF_U, wl + WOFF_U, nullptr, b2, HH, DD);
    // 14) ff = gelu(g) * v -> b1
    ffnact_kernel<<<gMH, EW>>>(b1, b2);
    // 15) out = h1 + ff @ Wd
    split_kernel<<<sMH, 256>>>(b1, ah, al, nMH / 4);
    hmma_gemm<0,true><<<gemD, 256, GEMM_SMEM>>>(ah, al, wh + WOFF_D, wl + WOFF_D, h1, out, DD, HH);
}

// round 5
// speedup vs baseline: 2.9031x; 1.3507x over previous
#include <cuda_runtime.h>
#include <cuda_bf16.h>
#include <math.h>
#include <stdint.h>

// Problem dims (fixed by the dataset)
#define BB 4
#define SS 2048
#define DD 1024
#define HH 4096
#define MM (BB*SS)          // 8192 rows
#define NC 32               // scan chunks
#define CL (SS/NC)          // 64 steps per chunk

// ---------------------------------------------------------------------------
// Scratch (static device globals; no allocation in kernel_launch)
// ---------------------------------------------------------------------------
__device__ __align__(16) float g_t  [(size_t)MM*DD];   // rlin -> a
__device__ __align__(16) float g_xb [(size_t)MM*DD];   // xb / ilin -> local h
__device__ __align__(16) float g_yb [(size_t)MM*DD];   // gelu gate
__device__ __align__(16) float g_xc [(size_t)MM*DD];   // conv output
__device__ __align__(16) float g_h1 [(size_t)MM*DD];   // h1
__device__ __align__(16) float g_b1 [(size_t)MM*HH];   // g
__device__ __align__(16) float g_b2 [(size_t)MM*HH];   // v
__device__ __align__(16) float g_sa [(size_t)BB*NC*DD]; // chunk a-products
__device__ __align__(16) float g_sh [(size_t)BB*NC*DD]; // chunk h-carries

// bf16 split buffers for GEMM A operands (sized for the largest, 8192x4096)
__device__ __align__(16) __nv_bfloat16 g_ah[(size_t)MM*HH];
__device__ __align__(16) __nv_bfloat16 g_al[(size_t)MM*HH];
// bf16 split+transposed weights, packed arena (pairs contiguous for dual GEMMs)
#define WOFF_X  ((size_t)0)
#define WOFF_Y  ((size_t)1*1024*1024)   // must follow X (dual Wx|Wy)
#define WOFF_A  ((size_t)2*1024*1024)
#define WOFF_I  ((size_t)3*1024*1024)   // must follow A (dual Wa|Wi)
#define WOFF_O  ((size_t)4*1024*1024)
#define WOFF_G  ((size_t)5*1024*1024)
#define WOFF_U  ((size_t)9*1024*1024)   // must follow G (dual Wg|Wu)
#define WOFF_D  ((size_t)13*1024*1024)
__device__ __align__(16) __nv_bfloat16 g_wh[(size_t)17*1024*1024];
__device__ __align__(16) __nv_bfloat16 g_wl[(size_t)17*1024*1024];

// ---------------------------------------------------------------------------
// Math helpers
// ---------------------------------------------------------------------------
__device__ __forceinline__ float geluf(float x) {
    const float c = 0.7978845608028654f; // sqrt(2/pi)
    float x3 = x * x * x;
    float t  = tanhf(c * (x + 0.044715f * x3));
    return 0.5f * x * (1.0f + t);
}
__device__ __forceinline__ float sigmoidf(float x) {
    return 1.0f / (1.0f + expf(-x));
}
__device__ __forceinline__ float softplusf(float x) {
    return fmaxf(x, 0.0f) + log1pf(expf(-fabsf(x)));
}
__device__ __forceinline__ void split_bf16(float v, __nv_bfloat16& h, __nv_bfloat16& l) {
    h = __float2bfloat16(v);
    l = __float2bfloat16(v - __bfloat162float(h));
}

// ---------------------------------------------------------------------------
// PTX helpers (baseline compute_103 features only)
// ---------------------------------------------------------------------------
__device__ __forceinline__ uint32_t smem_u32(const void* p) {
    uint32_t a;
    asm("{ .reg .u64 t; cvta.to.shared.u64 t, %1; cvt.u32.u64 %0, t; }" : "=r"(a) : "l"(p));
    return a;
}
__device__ __forceinline__ void cp_async16(uint32_t dst, const void* src) {
    asm volatile("cp.async.cg.shared.global [%0], [%1], 16;" :: "r"(dst), "l"(src) : "memory");
}
__device__ __forceinline__ void ldm_x4(uint32_t& r0, uint32_t& r1, uint32_t& r2, uint32_t& r3,
                                       uint32_t addr) {
    asm volatile("ldmatrix.sync.aligned.m8n8.x4.shared.b16 {%0,%1,%2,%3}, [%4];"
                 : "=r"(r0), "=r"(r1), "=r"(r2), "=r"(r3) : "r"(addr));
}
__device__ __forceinline__ void ldm_x2(uint32_t& r0, uint32_t& r1, uint32_t addr) {
    asm volatile("ldmatrix.sync.aligned.m8n8.x2.shared.b16 {%0,%1}, [%2];"
                 : "=r"(r0), "=r"(r1) : "r"(addr));
}
__device__ __forceinline__ void mma16816(float* c, const uint32_t* a, const uint32_t* b) {
    asm volatile(
        "mma.sync.aligned.m16n8k16.row.col.f32.bf16.bf16.f32 "
        "{%0,%1,%2,%3}, {%4,%5,%6,%7}, {%8,%9}, {%0,%1,%2,%3};"
        : "+f"(c[0]), "+f"(c[1]), "+f"(c[2]), "+f"(c[3])
        : "r"(a[0]), "r"(a[1]), "r"(a[2]), "r"(a[3]), "r"(b[0]), "r"(b[1]));
}

// ---------------------------------------------------------------------------
// Split-bf16 HMMA GEMM, dual-output variant.
//   A as Ah/Al bf16 [M,K] row-major; B as Bh/Bl bf16 [Ntot,K] row-major.
//   C = Ah*Bh + Al*Bh + Ah*Bl (fp32 accum).
//   Columns [0,NH) -> C1 with ACT1; [NH,2NH) -> C2 with ACT2 (each row stride NH).
//   Single-output mode: pass NH = Ntot and C2 = C1 (all CTAs take branch 1).
// CTA 128x128, BK=32, 8 warps (2Mx4N), 2-stage cp.async, 2 CTAs/SM.
// ---------------------------------------------------------------------------
#define GSTRIDE 80u
#define TILE_B  10240u
#define STG_B   40960u
#define GEMM_SMEM (2*STG_B)

template<int ACT1, int ACT2, bool RES>
__global__ void __launch_bounds__(256, 2)
hmma_gemm(const __nv_bfloat16* __restrict__ Ah, const __nv_bfloat16* __restrict__ Al,
          const __nv_bfloat16* __restrict__ Bh, const __nv_bfloat16* __restrict__ Bl,
          const float* __restrict__ R, float* __restrict__ C1, float* __restrict__ C2,
          int NH, int K)
{
    extern __shared__ char smem[];
    const uint32_t sb = smem_u32(smem);
    const int tid  = threadIdx.x;
    const int wid  = tid >> 5;
    const int lane = tid & 31;
    const int bm = blockIdx.y * 128;
    const int bn = blockIdx.x * 128;
    const int wr = wid >> 2;          // warp row (64 rows)
    const int wc = wid & 3;           // warp col (32 cols)

    const int nch = K >> 5;           // BK = 32

    auto fill = [&](int ch) {
        const int k0 = ch << 5;
        const uint32_t st = sb + (uint32_t)(ch & 1) * STG_B;
        #pragma unroll
        for (int r = 0; r < 2; r++) {
            const int c = tid + (r << 8);
            const int row = c >> 2, kc = c & 3;
            const uint32_t dst = st + (uint32_t)row * GSTRIDE + (uint32_t)(kc << 4);
            const size_t  src = (size_t)(bm + row) * K + k0 + (kc << 3);
            cp_async16(dst,          Ah + src);
            cp_async16(dst + TILE_B, Al + src);
        }
        #pragma unroll
        for (int r = 0; r < 2; r++) {
            const int c = tid + (r << 8);
            const int row = c >> 2, kc = c & 3;
            const uint32_t dst = st + 2*TILE_B + (uint32_t)row * GSTRIDE + (uint32_t)(kc << 4);
            const size_t  src = (size_t)(bn + row) * K + k0 + (kc << 3);
            cp_async16(dst,          Bh + src);
            cp_async16(dst + TILE_B, Bl + src);
        }
        asm volatile("cp.async.commit_group;" ::: "memory");
    };

    float acc[4][4][4];
    #pragma unroll
    for (int i = 0; i < 4; i++)
        #pragma unroll
        for (int j = 0; j < 4; j++)
            #pragma unroll
            for (int q = 0; q < 4; q++) acc[i][j][q] = 0.0f;

    fill(0);
    if (nch > 1) fill(1);

    const int l16  = lane & 15;
    const int ahi  = (lane >> 4) << 4;
    const int bl8  = lane & 7;
    const int bhi  = ((lane >> 3) & 1) << 4;

    for (int i = 0; i < nch; i++) {
        if (i + 1 < nch) asm volatile("cp.async.wait_group 1;" ::: "memory");
        else             asm volatile("cp.async.wait_group 0;" ::: "memory");
        __syncthreads();

        const uint32_t st  = sb + (uint32_t)(i & 1) * STG_B;
        const uint32_t sAh = st;
        const uint32_t sAl = st + TILE_B;
        const uint32_t sBh = st + 2*TILE_B;
        const uint32_t sBl = st + 3*TILE_B;

        #pragma unroll
        for (int ks = 0; ks < 2; ks++) {
            uint32_t ah[4][4], al[4][4];
            #pragma unroll
            for (int mt = 0; mt < 4; mt++) {
                const uint32_t ra = (uint32_t)(wr*64 + mt*16 + l16) * GSTRIDE
                                  + (uint32_t)(ks*32 + ahi);
                ldm_x4(ah[mt][0], ah[mt][1], ah[mt][2], ah[mt][3], sAh + ra);
                ldm_x4(al[mt][0], al[mt][1], al[mt][2], al[mt][3], sAl + ra);
            }
            #pragma unroll
            for (int nt = 0; nt < 4; nt++) {
                uint32_t bh[2], bl[2];
                const uint32_t rb = (uint32_t)(wc*32 + nt*8 + bl8) * GSTRIDE
                                  + (uint32_t)(ks*32 + bhi);
                ldm_x2(bh[0], bh[1], sBh + rb);
                ldm_x2(bl[0], bl[1], sBl + rb);
                #pragma unroll
                for (int mt = 0; mt < 4; mt++) {
                    mma16816(acc[mt][nt], ah[mt], bh);
                    mma16816(acc[mt][nt], al[mt], bh);
                    mma16816(acc[mt][nt], ah[mt], bl);
                }
            }
        }
        __syncthreads();
        if (i + 2 < nch) fill(i + 2);
    }

    // Epilogue: whole CTA lies in one output half (NH is a multiple of 128).
    float* Cout;
    int act, cb;
    if (bn < NH) { Cout = C1; act = ACT1; cb = bn; }
    else         { Cout = C2; act = ACT2; cb = bn - NH; }

    const int erow = lane >> 2;
    const int ecol = (lane & 3) << 1;
    #pragma unroll
    for (int mt = 0; mt < 4; mt++) {
        #pragma unroll
        for (int nt = 0; nt < 4; nt++) {
            const int r0 = bm + wr*64 + mt*16 + erow;
            const int cc = cb + wc*32 + nt*8 + ecol;
            float v0 = acc[mt][nt][0], v1 = acc[mt][nt][1];
            float v2 = acc[mt][nt][2], v3 = acc[mt][nt][3];
            if (act == 1) { v0 = geluf(v0); v1 = geluf(v1); v2 = geluf(v2); v3 = geluf(v3); }
            if (RES) {
                const float2 ra = *(const float2*)(R + (size_t)r0 * NH + cc);
                const float2 rb = *(const float2*)(R + (size_t)(r0+8) * NH + cc);
                v0 += ra.x; v1 += ra.y; v2 += rb.x; v3 += rb.y;
            }
            *(float2*)(Cout + (size_t)r0     * NH + cc) = make_float2(v0, v1);
            *(float2*)(Cout + (size_t)(r0+8) * NH + cc) = make_float2(v2, v3);
        }
    }
}

// ---------------------------------------------------------------------------
// Weight transpose + split: W [Kd, Nd] fp32 -> Th/Tl [Nd, Kd] bf16
// ---------------------------------------------------------------------------
__global__ void tsplit_kernel(const float* __restrict__ W,
                              __nv_bfloat16* __restrict__ Th,
                              __nv_bfloat16* __restrict__ Tl,
                              int Kd, int Nd)
{
    __shared__ float tile[32][33];
    const int n0 = blockIdx.x * 32, k0 = blockIdx.y * 32;
    const int tx = threadIdx.x, ty = threadIdx.y;   // (32, 8)
    #pragma unroll
    for (int i = 0; i < 32; i += 8)
        tile[ty + i][tx] = W[(size_t)(k0 + ty + i) * Nd + n0 + tx];
    __syncthreads();
    #pragma unroll
    for (int i = 0; i < 32; i += 8) {
        const float v = tile[tx][ty + i];
        __nv_bfloat16 h, l; split_bf16(v, h, l);
        const size_t o = (size_t)(n0 + ty + i) * Kd + k0 + tx;
        Th[o] = h; Tl[o] = l;
    }
}

// ---------------------------------------------------------------------------
// RMSNorm with fused bf16 hi/lo split output
// ---------------------------------------------------------------------------
__global__ void rmsnorm_split_kernel(const float* __restrict__ x,
                                     const float* __restrict__ w,
                                     __nv_bfloat16* __restrict__ oh,
                                     __nv_bfloat16* __restrict__ ol, int D)
{
    const int row = blockIdx.x;
    const float* xr = x + (size_t)row * D;
    float ss = 0.0f;
    for (int i = threadIdx.x; i < D; i += blockDim.x) {
        float v = xr[i];
        ss = fmaf(v, v, ss);
    }
    #pragma unroll
    for (int off = 16; off > 0; off >>= 1)
        ss += __shfl_xor_sync(0xffffffff, ss, off);
    __shared__ float red[32];
    const int lane = threadIdx.x & 31, wid = threadIdx.x >> 5;
    if (lane == 0) red[wid] = ss;
    __syncthreads();
    const int nw = blockDim.x >> 5;
    if (wid == 0) {
        float s = (lane < nw) ? red[lane] : 0.0f;
        #pragma unroll
        for (int off = 16; off > 0; off >>= 1)
            s += __shfl_xor_sync(0xffffffff, s, off);
        if (lane == 0) red[0] = s;
    }
    __syncthreads();
    const float inv = rsqrtf(red[0] / (float)D + 1e-6f);
    for (int i = threadIdx.x; i < D; i += blockDim.x) {
        const float v = xr[i] * inv * w[i];
        __nv_bfloat16 h, l; split_bf16(v, h, l);
        oh[(size_t)row * D + i] = h;
        ol[(size_t)row * D + i] = l;
    }
}

// ---------------------------------------------------------------------------
// Causal depthwise conv (K=4) with fused fp32 + bf16 split outputs
// ---------------------------------------------------------------------------
__global__ void conv_split_kernel(const float* __restrict__ in,
                                  const float* __restrict__ cw,
                                  const float* __restrict__ cb,
                                  float* __restrict__ xc,
                                  __nv_bfloat16* __restrict__ oh,
                                  __nv_bfloat16* __restrict__ ol)
{
    const size_t idx = (size_t)blockIdx.x * blockDim.x + threadIdx.x;
    if (idx >= (size_t)MM * DD) return;
    const int d = (int)(idx % DD);
    const int s = (int)((idx / DD) % SS);
    float acc = cb[d];
    #pragma unroll
    for (int k = 0; k < 4; k++) {
        if (s + k - 3 >= 0)
            acc = fmaf(cw[k * DD + d], in[idx - (size_t)(3 - k) * DD], acc);
    }
    xc[idx] = acc;
    __nv_bfloat16 h, l; split_bf16(acc, h, l);
    oh[idx] = h; ol[idx] = l;
}

// ---------------------------------------------------------------------------
// Scan pass 1: fused gates + chunk-local scan.
//   rlin (in) -> a (out, in place); ilin (in) -> local h (out, in place).
//   Writes per-chunk a-product and local end-h.
// One thread per (batch, chunk, d).
// ---------------------------------------------------------------------------
__global__ void scan1_kernel(float* __restrict__ rlin_a,
                             float* __restrict__ ilin_h,
                             const float* __restrict__ xc,
                             const float* __restrict__ lam,
                             float* __restrict__ sa,
                             float* __restrict__ sh)
{
    const int idx = blockIdx.x * blockDim.x + threadIdx.x;
    if (idx >= BB * NC * DD) return;
    const int d     = idx % DD;
    const int chunk = (idx / DD) % NC;
    const int batch = idx / (DD * NC);
    const float cfac = -8.0f * softplusf(lam[d]);
    const size_t base = ((size_t)batch * SS + (size_t)chunk * CL) * DD + d;

    float p = 1.0f, h = 0.0f;
    for (int t = 0; t < CL; t++) {
        const size_t off = base + (size_t)t * DD;
        const float r  = sigmoidf(rlin_a[off]);
        const float ii = sigmoidf(ilin_h[off]);
        const float a  = expf(cfac * r);
        const float b  = sqrtf(fmaxf(1.0f - a * a, 1e-12f)) * ii * xc[off];
        h = fmaf(a, h, b);
        p *= a;
        rlin_a[off] = a;
        ilin_h[off] = h;
    }
    sa[idx] = p;
    sh[idx] = h;
}

// ---------------------------------------------------------------------------
// Scan pass 2: combine chunk carries. One thread per (batch, d).
//   sh[c] <- true h at end of chunk c.
// ---------------------------------------------------------------------------
__global__ void scan2_kernel(const float* __restrict__ sa, float* __restrict__ sh)
{
    const int idx = blockIdx.x * blockDim.x + threadIdx.x;
    if (idx >= BB * DD) return;
    const int d = idx % DD, batch = idx / DD;
    float H = 0.0f;
    for (int c = 0; c < NC; c++) {
        const size_t o = ((size_t)batch * NC + c) * DD + d;
        H = fmaf(sa[o], H, sh[o]);
        sh[o] = H;
    }
}

// ---------------------------------------------------------------------------
// Scan pass 3: apply carries, fuse z = h * yb and bf16 split.
// ---------------------------------------------------------------------------
__global__ void scan3_kernel(const float* __restrict__ aArr,
                             const float* __restrict__ lhArr,
                             const float* __restrict__ sh,
                             const float* __restrict__ yb,
                             __nv_bfloat16* __restrict__ zh,
                             __nv_bfloat16* __restrict__ zl)
{
    const int idx = blockIdx.x * blockDim.x + threadIdx.x;
    if (idx >= BB * NC * DD) return;
    const int d     = idx % DD;
    const int chunk = (idx / DD) % NC;
    const int batch = idx / (DD * NC);
    const float carry = (chunk == 0)
        ? 0.0f : sh[((size_t)batch * NC + chunk - 1) * DD + d];
    const size_t base = ((size_t)batch * SS + (size_t)chunk * CL) * DD + d;

    float p = 1.0f;
    for (int t = 0; t < CL; t++) {
        const size_t off = base + (size_t)t * DD;
        p *= aArr[off];
        const float h = fmaf(p, carry, lhArr[off]);
        const float z = h * yb[off];
        __nv_bfloat16 hh, ll; split_bf16(z, hh, ll);
        zh[off] = hh; zl[off] = ll;
    }
}

// ---------------------------------------------------------------------------
// ffn activation with fused bf16 split: out = gelu(g) * v
// ---------------------------------------------------------------------------
__global__ void ffnact_split_kernel(const float* __restrict__ g,
                                    const float* __restrict__ v,
                                    __nv_bfloat16* __restrict__ oh,
                                    __nv_bfloat16* __restrict__ ol, size_t n4)
{
    const size_t i = (size_t)blockIdx.x * blockDim.x + threadIdx.x;
    if (i >= n4) return;
    const float4 gv = *(const float4*)(g + i * 4);
    const float4 vv = *(const float4*)(v + i * 4);
    float z0 = geluf(gv.x) * vv.x, z1 = geluf(gv.y) * vv.y;
    float z2 = geluf(gv.z) * vv.z, z3 = geluf(gv.w) * vv.w;
    __nv_bfloat16 h0, l0, h1, l1, h2, l2, h3, l3;
    split_bf16(z0, h0, l0); split_bf16(z1, h1, l1);
    split_bf16(z2, h2, l2); split_bf16(z3, h3, l3);
    __nv_bfloat162* hp = (__nv_bfloat162*)(oh + i * 4);
    __nv_bfloat162* lp = (__nv_bfloat162*)(ol + i * 4);
    hp[0] = __nv_bfloat162{h0, h1}; hp[1] = __nv_bfloat162{h2, h3};
    lp[0] = __nv_bfloat162{l0, l1}; lp[1] = __nv_bfloat162{l2, l3};
}

// ---------------------------------------------------------------------------
// Launch
// ---------------------------------------------------------------------------
extern "C" void kernel_launch(void* const* d_in, const int* in_sizes, int n_in,
                              void* d_out, int out_size)
{
    const float* x       = (const float*)d_in[0];
    const float* norm1_w = (const float*)d_in[1];
    const float* Wx      = (const float*)d_in[2];
    const float* Wy      = (const float*)d_in[3];
    const float* conv_w  = (const float*)d_in[4];
    const float* conv_b  = (const float*)d_in[5];
    const float* Wi      = (const float*)d_in[6];
    const float* Wa      = (const float*)d_in[7];
    const float* lam     = (const float*)d_in[8];
    const float* Wo      = (const float*)d_in[9];
    const float* norm2_w = (const float*)d_in[10];
    const float* Wg      = (const float*)d_in[11];
    const float* Wu      = (const float*)d_in[12];
    const float* Wd      = (const float*)d_in[13];
    float* out = (float*)d_out;

    float *t, *xb, *yb, *xc, *h1, *b1, *b2, *sa, *sh;
    __nv_bfloat16 *ah, *al, *wh, *wl;
    cudaGetSymbolAddress((void**)&t,  g_t);
    cudaGetSymbolAddress((void**)&xb, g_xb);
    cudaGetSymbolAddress((void**)&yb, g_yb);
    cudaGetSymbolAddress((void**)&xc, g_xc);
    cudaGetSymbolAddress((void**)&h1, g_h1);
    cudaGetSymbolAddress((void**)&b1, g_b1);
    cudaGetSymbolAddress((void**)&b2, g_b2);
    cudaGetSymbolAddress((void**)&sa, g_sa);
    cudaGetSymbolAddress((void**)&sh, g_sh);
    cudaGetSymbolAddress((void**)&ah, g_ah);
    cudaGetSymbolAddress((void**)&al, g_al);
    cudaGetSymbolAddress((void**)&wh, g_wh);
    cudaGetSymbolAddress((void**)&wl, g_wl);

    cudaFuncSetAttribute(hmma_gemm<0,1,false>, cudaFuncAttributeMaxDynamicSharedMemorySize, GEMM_SMEM);
    cudaFuncSetAttribute(hmma_gemm<0,0,false>, cudaFuncAttributeMaxDynamicSharedMemorySize, GEMM_SMEM);
    cudaFuncSetAttribute(hmma_gemm<0,0,true>,  cudaFuncAttributeMaxDynamicSharedMemorySize, GEMM_SMEM);

    const dim3 tsb(32, 8);
    const size_t nMD = (size_t)MM * DD, nMH = (size_t)MM * HH;
    const int gMD = (int)((nMD + 255) / 256);
    const int gSC = (BB * NC * DD + 255) / 256;     // 512 blocks
    const int fMH = (int)(nMH / 4 / 256);

    const dim3 gemXY(2048 / 128, MM / 128);   // dual Wx|Wy
    const dim3 gemAI(2048 / 128, MM / 128);   // dual Wa|Wi
    const dim3 gemGU(8192 / 128, MM / 128);   // dual Wg|Wu
    const dim3 gemO (1024 / 128, MM / 128);   // Wo (K=1024)
    const dim3 gemDn(1024 / 128, MM / 128);   // Wd (K=4096)

    // --- weight prep: transpose + bf16 split (W [K,N] -> [N,K]) ---
    tsplit_kernel<<<dim3(DD/32, DD/32), tsb>>>(Wx, wh + WOFF_X, wl + WOFF_X, DD, DD);
    tsplit_kernel<<<dim3(DD/32, DD/32), tsb>>>(Wy, wh + WOFF_Y, wl + WOFF_Y, DD, DD);
    tsplit_kernel<<<dim3(DD/32, DD/32), tsb>>>(Wa, wh + WOFF_A, wl + WOFF_A, DD, DD);
    tsplit_kernel<<<dim3(DD/32, DD/32), tsb>>>(Wi, wh + WOFF_I, wl + WOFF_I, DD, DD);
    tsplit_kernel<<<dim3(DD/32, DD/32), tsb>>>(Wo, wh + WOFF_O, wl + WOFF_O, DD, DD);
    tsplit_kernel<<<dim3(HH/32, DD/32), tsb>>>(Wg, wh + WOFF_G, wl + WOFF_G, DD, HH);
    tsplit_kernel<<<dim3(HH/32, DD/32), tsb>>>(Wu, wh + WOFF_U, wl + WOFF_U, DD, HH);
    tsplit_kernel<<<dim3(DD/32, HH/32), tsb>>>(Wd, wh + WOFF_D, wl + WOFF_D, HH, DD);

    // 1) t = rmsnorm(x) -> ah/al directly
    rmsnorm_split_kernel<<<MM, 256>>>(x, norm1_w, ah, al, DD);
    // 2+3) xb = t @ Wx ; yb = gelu(t @ Wy)  [dual]
    hmma_gemm<0,1,false><<<gemXY, 256, GEMM_SMEM>>>(ah, al, wh + WOFF_X, wl + WOFF_X,
                                                    nullptr, xb, yb, DD, DD);
    // 4) conv -> xc (fp32) + ah/al
    conv_split_kernel<<<gMD, 256>>>(xb, conv_w, conv_b, xc, ah, al);
    // 5+6) rlin = xc @ Wa -> t ; ilin = xc @ Wi -> xb  [dual]
    hmma_gemm<0,0,false><<<gemAI, 256, GEMM_SMEM>>>(ah, al, wh + WOFF_A, wl + WOFF_A,
                                                    nullptr, t, xb, DD, DD);
    // 7+8) gates + chunked scan; 9) z = h*yb fused into pass 3 -> ah/al
    scan1_kernel<<<gSC, 256>>>(t, xb, xc, lam, sa, sh);
    scan2_kernel<<<(BB * DD + 255) / 256, 256>>>(sa, sh);
    scan3_kernel<<<gSC, 256>>>(t, xb, sh, yb, ah, al);
    // 10) h1 = x + z @ Wo
    hmma_gemm<0,0,true><<<gemO, 256, GEMM_SMEM>>>(ah, al, wh + WOFF_O, wl + WOFF_O,
                                                  x, h1, h1, DD, DD);
    // 11) u = rmsnorm(h1) -> ah/al
    rmsnorm_split_kernel<<<MM, 256>>>(h1, norm2_w, ah, al, DD);
    // 12+13) g = u @ Wg -> b1 ; v = u @ Wu -> b2  [dual]
    hmma_gemm<0,0,false><<<gemGU, 256, GEMM_SMEM>>>(ah, al, wh + WOFF_G, wl + WOFF_G,
                                                    nullptr, b1, b2, HH, DD);
    // 14) ff = gelu(g) * v -> ah/al
    ffnact_split_kernel<<<fMH, 256>>>(b1, b2, ah, al, nMH / 4);
    // 15) out = h1 + ff @ Wd
    hmma_gemm<0,0,true><<<gemDn, 256, GEMM_SMEM>>>(ah, al, wh + WOFF_D, wl + WOFF_D,
                                                   h1, out, out, DD, HH);
}

// round 6
// speedup vs baseline: 4.1570x; 1.4319x over previous
#include <cuda_runtime.h>
#include <cuda_fp16.h>
#include <math.h>
#include <stdint.h>

// Problem dims (fixed by the dataset)
#define BB 4
#define SS 2048
#define DD 1024
#define HH 4096
#define MM (BB*SS)          // 8192 rows
#define NC 32               // scan chunks
#define CL (SS/NC)          // 64 steps per chunk

// ---------------------------------------------------------------------------
// Scratch (static device globals; no allocation in kernel_launch)
// ---------------------------------------------------------------------------
__device__ __align__(16) float g_t  [(size_t)MM*DD];   // rlin -> a
__device__ __align__(16) float g_xb [(size_t)MM*DD];   // xb / ilin -> local h
__device__ __align__(16) float g_yb [(size_t)MM*DD];   // gelu gate
__device__ __align__(16) float g_xc [(size_t)MM*DD];   // conv output
__device__ __align__(16) float g_h1 [(size_t)MM*DD];   // h1
__device__ __align__(16) float g_sa [(size_t)BB*NC*DD]; // chunk a-products
__device__ __align__(16) float g_sh [(size_t)BB*NC*DD]; // chunk h-carries

// fp16 hi/lo splits of D-dim activations
__device__ __align__(16) __half g_ah[(size_t)MM*DD];
__device__ __align__(16) __half g_al[(size_t)MM*DD];
// fp16 hi/lo splits of the gated-MLP intermediate (H-dim)
__device__ __align__(16) __half g_zh[(size_t)MM*HH];
__device__ __align__(16) __half g_zl[(size_t)MM*HH];
// fp16 transposed weights, packed arena (17M halfs)
#define WOFF_X  ((size_t)0)
#define WOFF_Y  ((size_t)1*1024*1024)   // follows X (dual Wx|Wy)
#define WOFF_A  ((size_t)2*1024*1024)
#define WOFF_I  ((size_t)3*1024*1024)   // follows A (dual Wa|Wi)
#define WOFF_O  ((size_t)4*1024*1024)
#define WOFF_GU ((size_t)5*1024*1024)   // Wg/Wu column-interleaved (8192 rows)
#define WOFF_D  ((size_t)13*1024*1024)
__device__ __align__(16) __half g_wh[(size_t)17*1024*1024];

// ---------------------------------------------------------------------------
// Math helpers
// ---------------------------------------------------------------------------
__device__ __forceinline__ float geluf(float x) {
    const float c = 0.7978845608028654f; // sqrt(2/pi)
    float x3 = x * x * x;
    float t  = tanhf(c * (x + 0.044715f * x3));
    return 0.5f * x * (1.0f + t);
}
__device__ __forceinline__ float sigmoidf(float x) {
    return 1.0f / (1.0f + expf(-x));
}
__device__ __forceinline__ float softplusf(float x) {
    return fmaxf(x, 0.0f) + log1pf(expf(-fabsf(x)));
}
__device__ __forceinline__ void split_f16(float v, __half& h, __half& l) {
    h = __float2half_rn(v);
    l = __float2half_rn(v - __half2float(h));
}

// ---------------------------------------------------------------------------
// PTX helpers (baseline compute_103 features only)
// ---------------------------------------------------------------------------
__device__ __forceinline__ uint32_t smem_u32(const void* p) {
    uint32_t a;
    asm("{ .reg .u64 t; cvta.to.shared.u64 t, %1; cvt.u32.u64 %0, t; }" : "=r"(a) : "l"(p));
    return a;
}
__device__ __forceinline__ void cp_async16(uint32_t dst, const void* src) {
    asm volatile("cp.async.cg.shared.global [%0], [%1], 16;" :: "r"(dst), "l"(src) : "memory");
}
__device__ __forceinline__ void ldm_x4(uint32_t& r0, uint32_t& r1, uint32_t& r2, uint32_t& r3,
                                       uint32_t addr) {
    asm volatile("ldmatrix.sync.aligned.m8n8.x4.shared.b16 {%0,%1,%2,%3}, [%4];"
                 : "=r"(r0), "=r"(r1), "=r"(r2), "=r"(r3) : "r"(addr));
}
__device__ __forceinline__ void ldm_x2(uint32_t& r0, uint32_t& r1, uint32_t addr) {
    asm volatile("ldmatrix.sync.aligned.m8n8.x2.shared.b16 {%0,%1}, [%2];"
                 : "=r"(r0), "=r"(r1) : "r"(addr));
}
__device__ __forceinline__ void mma16816(float* c, const uint32_t* a, const uint32_t* b) {
    asm volatile(
        "mma.sync.aligned.m16n8k16.row.col.f32.f16.f16.f32 "
        "{%0,%1,%2,%3}, {%4,%5,%6,%7}, {%8,%9}, {%0,%1,%2,%3};"
        : "+f"(c[0]), "+f"(c[1]), "+f"(c[2]), "+f"(c[3])
        : "r"(a[0]), "r"(a[1]), "r"(a[2]), "r"(a[3]), "r"(b[0]), "r"(b[1]));
}

// ---------------------------------------------------------------------------
// 2-product fp16 HMMA GEMM: C = act(A @ W^T) (+R), A = Ah + Al (fp16 split),
// W = Bh (fp16). C = Ah*Bh + Al*Bh (fp32 accum) = A*Bh to 2^-22.
// CTA 128x128, BK=64, 8 warps (2Mx4N), 2-stage cp.async, 2 CTAs/SM.
// SMEM: rows of 64 fp16 = 128B + 16B pad (stride 144B -> conflict-free ldmatrix).
// GATED mode: B rows interleave Wg/Wu columns; epilogue computes
//   ff_j = gelu(C[.,2j]) * C[.,2j+1], written as fp16 hi/lo split.
// ---------------------------------------------------------------------------
#define GSTRIDE 144u
#define TILE_B  18432u
#define STG_B   55296u
#define GEMM_SMEM (2*STG_B)

template<int ACT1, int ACT2, bool RES, bool GATED>
__global__ void __launch_bounds__(256, 2)
hmma_gemm(const __half* __restrict__ Ah, const __half* __restrict__ Al,
          const __half* __restrict__ Bh,
          const float* __restrict__ R, float* __restrict__ C1, float* __restrict__ C2,
          __half* __restrict__ ZH, __half* __restrict__ ZL,
          int NH, int K)
{
    extern __shared__ char smem[];
    const uint32_t sb = smem_u32(smem);
    const int tid  = threadIdx.x;
    const int wid  = tid >> 5;
    const int lane = tid & 31;
    const int bm = blockIdx.y * 128;
    const int bn = blockIdx.x * 128;
    const int wr = wid >> 2;          // warp row (64 rows)
    const int wc = wid & 3;           // warp col (32 cols)

    const int nch = K >> 6;           // BK = 64

    auto fill = [&](int ch) {
        const int k0 = ch << 6;
        const uint32_t st = sb + (uint32_t)(ch & 1) * STG_B;
        #pragma unroll
        for (int r = 0; r < 4; r++) {
            const int c = tid + (r << 8);          // 0..1023
            const int row = c >> 3, kc = c & 7;
            const uint32_t dst = (uint32_t)row * GSTRIDE + (uint32_t)(kc << 4);
            const size_t  srcA = (size_t)(bm + row) * K + k0 + (kc << 3);
            const size_t  srcB = (size_t)(bn + row) * K + k0 + (kc << 3);
            cp_async16(st + dst,            Ah + srcA);
            cp_async16(st + TILE_B + dst,   Al + srcA);
            cp_async16(st + 2*TILE_B + dst, Bh + srcB);
        }
        asm volatile("cp.async.commit_group;" ::: "memory");
    };

    float acc[4][4][4];
    #pragma unroll
    for (int i = 0; i < 4; i++)
        #pragma unroll
        for (int j = 0; j < 4; j++)
            #pragma unroll
            for (int q = 0; q < 4; q++) acc[i][j][q] = 0.0f;

    fill(0);
    if (nch > 1) fill(1);

    const int l16  = lane & 15;
    const int ahi  = (lane >> 4) << 4;
    const int bl8  = lane & 7;
    const int bhi  = ((lane >> 3) & 1) << 4;

    for (int i = 0; i < nch; i++) {
        if (i + 1 < nch) asm volatile("cp.async.wait_group 1;" ::: "memory");
        else             asm volatile("cp.async.wait_group 0;" ::: "memory");
        __syncthreads();

        const uint32_t st  = sb + (uint32_t)(i & 1) * STG_B;
        const uint32_t sAh = st;
        const uint32_t sAl = st + TILE_B;
        const uint32_t sBh = st + 2*TILE_B;

        #pragma unroll
        for (int ks = 0; ks < 4; ks++) {
            uint32_t ah[4][4], al[4][4];
            #pragma unroll
            for (int mt = 0; mt < 4; mt++) {
                const uint32_t ra = (uint32_t)(wr*64 + mt*16 + l16) * GSTRIDE
                                  + (uint32_t)(ks*32 + ahi);
                ldm_x4(ah[mt][0], ah[mt][1], ah[mt][2], ah[mt][3], sAh + ra);
                ldm_x4(al[mt][0], al[mt][1], al[mt][2], al[mt][3], sAl + ra);
            }
            #pragma unroll
            for (int nt = 0; nt < 4; nt++) {
                uint32_t bh[2];
                const uint32_t rb = (uint32_t)(wc*32 + nt*8 + bl8) * GSTRIDE
                                  + (uint32_t)(ks*32 + bhi);
                ldm_x2(bh[0], bh[1], sBh + rb);
                #pragma unroll
                for (int mt = 0; mt < 4; mt++) {
                    mma16816(acc[mt][nt], ah[mt], bh);
                    mma16816(acc[mt][nt], al[mt], bh);
                }
            }
        }
        __syncthreads();
        if (i + 2 < nch) fill(i + 2);
    }

    const int erow = lane >> 2;
    const int ecol = (lane & 3) << 1;

    if constexpr (GATED) {
        // (c0,c1) = (g_j, v_j); ff_j = gelu(g)*v; fp16 split out, width NH.
        #pragma unroll
        for (int mt = 0; mt < 4; mt++) {
            #pragma unroll
            for (int nt = 0; nt < 4; nt++) {
                const int r0 = bm + wr*64 + mt*16 + erow;
                const int j  = ((bn + wc*32 + nt*8 + ecol) >> 1);
                const float f0 = geluf(acc[mt][nt][0]) * acc[mt][nt][1];
                const float f1 = geluf(acc[mt][nt][2]) * acc[mt][nt][3];
                __half h0, l0, h1, l1;
                split_f16(f0, h0, l0); split_f16(f1, h1, l1);
                ZH[(size_t)r0     * NH + j] = h0; ZL[(size_t)r0     * NH + j] = l0;
                ZH[(size_t)(r0+8) * NH + j] = h1; ZL[(size_t)(r0+8) * NH + j] = l1;
            }
        }
        return;
    }

    // Normal epilogue: halves split at NH (NH multiple of 128).
    float* Cout;
    int act, cb;
    if (bn < NH) { Cout = C1; act = ACT1; cb = bn; }
    else         { Cout = C2; act = ACT2; cb = bn - NH; }

    #pragma unroll
    for (int mt = 0; mt < 4; mt++) {
        #pragma unroll
        for (int nt = 0; nt < 4; nt++) {
            const int r0 = bm + wr*64 + mt*16 + erow;
            const int cc = cb + wc*32 + nt*8 + ecol;
            float v0 = acc[mt][nt][0], v1 = acc[mt][nt][1];
            float v2 = acc[mt][nt][2], v3 = acc[mt][nt][3];
            if (act == 1) { v0 = geluf(v0); v1 = geluf(v1); v2 = geluf(v2); v3 = geluf(v3); }
            if (RES) {
                const float2 ra = *(const float2*)(R + (size_t)r0 * NH + cc);
                const float2 rb = *(const float2*)(R + (size_t)(r0+8) * NH + cc);
                v0 += ra.x; v1 += ra.y; v2 += rb.x; v3 += rb.y;
            }
            *(float2*)(Cout + (size_t)r0     * NH + cc) = make_float2(v0, v1);
            *(float2*)(Cout + (size_t)(r0+8) * NH + cc) = make_float2(v2, v3);
        }
    }
}

// ---------------------------------------------------------------------------
// Weight transpose to fp16: W [Kd, Nd] fp32 -> Th [(n*rstride+roff), Kd] fp16
// ---------------------------------------------------------------------------
__global__ void tsplit_kernel(const float* __restrict__ W,
                              __half* __restrict__ Th,
                              int Kd, int Nd, int rstride, int roff)
{
    __shared__ float tile[32][33];
    const int n0 = blockIdx.x * 32, k0 = blockIdx.y * 32;
    const int tx = threadIdx.x, ty = threadIdx.y;   // (32, 8)
    #pragma unroll
    for (int i = 0; i < 32; i += 8)
        tile[ty + i][tx] = W[(size_t)(k0 + ty + i) * Nd + n0 + tx];
    __syncthreads();
    #pragma unroll
    for (int i = 0; i < 32; i += 8) {
        const float v = tile[tx][ty + i];
        const size_t o = ((size_t)(n0 + ty + i) * rstride + roff) * Kd + k0 + tx;
        Th[o] = __float2half_rn(v);
    }
}

// ---------------------------------------------------------------------------
// RMSNorm with fused fp16 hi/lo split output
// ---------------------------------------------------------------------------
__global__ void rmsnorm_split_kernel(const float* __restrict__ x,
                                     const float* __restrict__ w,
                                     __half* __restrict__ oh,
                                     __half* __restrict__ ol, int D)
{
    const int row = blockIdx.x;
    const float* xr = x + (size_t)row * D;
    float ss = 0.0f;
    for (int i = threadIdx.x; i < D; i += blockDim.x) {
        float v = xr[i];
        ss = fmaf(v, v, ss);
    }
    #pragma unroll
    for (int off = 16; off > 0; off >>= 1)
        ss += __shfl_xor_sync(0xffffffff, ss, off);
    __shared__ float red[32];
    const int lane = threadIdx.x & 31, wid = threadIdx.x >> 5;
    if (lane == 0) red[wid] = ss;
    __syncthreads();
    const int nw = blockDim.x >> 5;
    if (wid == 0) {
        float s = (lane < nw) ? red[lane] : 0.0f;
        #pragma unroll
        for (int off = 16; off > 0; off >>= 1)
            s += __shfl_xor_sync(0xffffffff, s, off);
        if (lane == 0) red[0] = s;
    }
    __syncthreads();
    const float inv = rsqrtf(red[0] / (float)D + 1e-6f);
    for (int i = threadIdx.x; i < D; i += blockDim.x) {
        const float v = xr[i] * inv * w[i];
        __half h, l; split_f16(v, h, l);
        oh[(size_t)row * D + i] = h;
        ol[(size_t)row * D + i] = l;
    }
}

// ---------------------------------------------------------------------------
// Causal depthwise conv (K=4) with fused fp32 + fp16 split outputs
// ---------------------------------------------------------------------------
__global__ void conv_split_kernel(const float* __restrict__ in,
                                  const float* __restrict__ cw,
                                  const float* __restrict__ cb,
                                  float* __restrict__ xc,
                                  __half* __restrict__ oh,
                                  __half* __restrict__ ol)
{
    const size_t idx = (size_t)blockIdx.x * blockDim.x + threadIdx.x;
    if (idx >= (size_t)MM * DD) return;
    const int d = (int)(idx % DD);
    const int s = (int)((idx / DD) % SS);
    float acc = cb[d];
    #pragma unroll
    for (int k = 0; k < 4; k++) {
        if (s + k - 3 >= 0)
            acc = fmaf(cw[k * DD + d], in[idx - (size_t)(3 - k) * DD], acc);
    }
    xc[idx] = acc;
    __half h, l; split_f16(acc, h, l);
    oh[idx] = h; ol[idx] = l;
}

// ---------------------------------------------------------------------------
// Scan pass 1: fused gates + chunk-local scan.
// ---------------------------------------------------------------------------
__global__ void scan1_kernel(float* __restrict__ rlin_a,
                             float* __restrict__ ilin_h,
                             const float* __restrict__ xc,
                             const float* __restrict__ lam,
                             float* __restrict__ sa,
                             float* __restrict__ sh)
{
    const int idx = blockIdx.x * blockDim.x + threadIdx.x;
    if (idx >= BB * NC * DD) return;
    const int d     = idx % DD;
    const int chunk = (idx / DD) % NC;
    const int batch = idx / (DD * NC);
    const float cfac = -8.0f * softplusf(lam[d]);
    const size_t base = ((size_t)batch * SS + (size_t)chunk * CL) * DD + d;

    float p = 1.0f, h = 0.0f;
    for (int t = 0; t < CL; t++) {
        const size_t off = base + (size_t)t * DD;
        const float r  = sigmoidf(rlin_a[off]);
        const float ii = sigmoidf(ilin_h[off]);
        const float a  = expf(cfac * r);
        const float b  = sqrtf(fmaxf(1.0f - a * a, 1e-12f)) * ii * xc[off];
        h = fmaf(a, h, b);
        p *= a;
        rlin_a[off] = a;
        ilin_h[off] = h;
    }
    sa[idx] = p;
    sh[idx] = h;
}

// ---------------------------------------------------------------------------
// Scan pass 2: combine chunk carries.
// ---------------------------------------------------------------------------
__global__ void scan2_kernel(const float* __restrict__ sa, float* __restrict__ sh)
{
    const int idx = blockIdx.x * blockDim.x + threadIdx.x;
    if (idx >= BB * DD) return;
    const int d = idx % DD, batch = idx / DD;
    float H = 0.0f;
    for (int c = 0; c < NC; c++) {
        const size_t o = ((size_t)batch * NC + c) * DD + d;
        H = fmaf(sa[o], H, sh[o]);
        sh[o] = H;
    }
}

// ---------------------------------------------------------------------------
// Scan pass 3: apply carries, fuse z = h * yb and fp16 split.
// ---------------------------------------------------------------------------
__global__ void scan3_kernel(const float* __restrict__ aArr,
                             const float* __restrict__ lhArr,
                             const float* __restrict__ sh,
                             const float* __restrict__ yb,
                             __half* __restrict__ zh,
                             __half* __restrict__ zl)
{
    const int idx = blockIdx.x * blockDim.x + threadIdx.x;
    if (idx >= BB * NC * DD) return;
    const int d     = idx % DD;
    const int chunk = (idx / DD) % NC;
    const int batch = idx / (DD * NC);
    const float carry = (chunk == 0)
        ? 0.0f : sh[((size_t)batch * NC + chunk - 1) * DD + d];
    const size_t base = ((size_t)batch * SS + (size_t)chunk * CL) * DD + d;

    float p = 1.0f;
    for (int t = 0; t < CL; t++) {
        const size_t off = base + (size_t)t * DD;
        p *= aArr[off];
        const float h = fmaf(p, carry, lhArr[off]);
        const float z = h * yb[off];
        __half hh, ll; split_f16(z, hh, ll);
        zh[off] = hh; zl[off] = ll;
    }
}

// ---------------------------------------------------------------------------
// Launch
// ---------------------------------------------------------------------------
extern "C" void kernel_launch(void* const* d_in, const int* in_sizes, int n_in,
                              void* d_out, int out_size)
{
    const float* x       = (const float*)d_in[0];
    const float* norm1_w = (const float*)d_in[1];
    const float* Wx      = (const float*)d_in[2];
    const float* Wy      = (const float*)d_in[3];
    const float* conv_w  = (const float*)d_in[4];
    const float* conv_b  = (const float*)d_in[5];
    const float* Wi      = (const float*)d_in[6];
    const float* Wa      = (const float*)d_in[7];
    const float* lam     = (const float*)d_in[8];
    const float* Wo      = (const float*)d_in[9];
    const float* norm2_w = (const float*)d_in[10];
    const float* Wg      = (const float*)d_in[11];
    const float* Wu      = (const float*)d_in[12];
    const float* Wd      = (const float*)d_in[13];
    float* out = (float*)d_out;

    float *t, *xb, *yb, *xc, *h1, *sa, *sh;
    __half *ah, *al, *zh, *zl, *wh;
    cudaGetSymbolAddress((void**)&t,  g_t);
    cudaGetSymbolAddress((void**)&xb, g_xb);
    cudaGetSymbolAddress((void**)&yb, g_yb);
    cudaGetSymbolAddress((void**)&xc, g_xc);
    cudaGetSymbolAddress((void**)&h1, g_h1);
    cudaGetSymbolAddress((void**)&sa, g_sa);
    cudaGetSymbolAddress((void**)&sh, g_sh);
    cudaGetSymbolAddress((void**)&ah, g_ah);
    cudaGetSymbolAddress((void**)&al, g_al);
    cudaGetSymbolAddress((void**)&zh, g_zh);
    cudaGetSymbolAddress((void**)&zl, g_zl);
    cudaGetSymbolAddress((void**)&wh, g_wh);

    cudaFuncSetAttribute(hmma_gemm<0,1,false,false>, cudaFuncAttributeMaxDynamicSharedMemorySize, GEMM_SMEM);
    cudaFuncSetAttribute(hmma_gemm<0,0,false,false>, cudaFuncAttributeMaxDynamicSharedMemorySize, GEMM_SMEM);
    cudaFuncSetAttribute(hmma_gemm<0,0,true,false>,  cudaFuncAttributeMaxDynamicSharedMemorySize, GEMM_SMEM);
    cudaFuncSetAttribute(hmma_gemm<0,0,false,true>,  cudaFuncAttributeMaxDynamicSharedMemorySize, GEMM_SMEM);

    const dim3 tsb(32, 8);
    const size_t nMD = (size_t)MM * DD;
    const int gMD = (int)((nMD + 255) / 256);
    const int gSC = (BB * NC * DD + 255) / 256;

    const dim3 gemXY(2048 / 128, MM / 128);   // dual Wx|Wy
    const dim3 gemAI(2048 / 128, MM / 128);   // dual Wa|Wi
    const dim3 gemGU(8192 / 128, MM / 128);   // interleaved Wg|Wu (gated)
    const dim3 gemO (1024 / 128, MM / 128);   // Wo (K=1024)
    const dim3 gemDn(1024 / 128, MM / 128);   // Wd (K=4096)

    // --- weight prep: transpose to fp16 [N,K] ---
    tsplit_kernel<<<dim3(DD/32, DD/32), tsb>>>(Wx, wh + WOFF_X, DD, DD, 1, 0);
    tsplit_kernel<<<dim3(DD/32, DD/32), tsb>>>(Wy, wh + WOFF_Y, DD, DD, 1, 0);
    tsplit_kernel<<<dim3(DD/32, DD/32), tsb>>>(Wa, wh + WOFF_A, DD, DD, 1, 0);
    tsplit_kernel<<<dim3(DD/32, DD/32), tsb>>>(Wi, wh + WOFF_I, DD, DD, 1, 0);
    tsplit_kernel<<<dim3(DD/32, DD/32), tsb>>>(Wo, wh + WOFF_O, DD, DD, 1, 0);
    tsplit_kernel<<<dim3(HH/32, DD/32), tsb>>>(Wg, wh + WOFF_GU, DD, HH, 2, 0);  // even rows
    tsplit_kernel<<<dim3(HH/32, DD/32), tsb>>>(Wu, wh + WOFF_GU, DD, HH, 2, 1);  // odd rows
    tsplit_kernel<<<dim3(DD/32, HH/32), tsb>>>(Wd, wh + WOFF_D, HH, DD, 1, 0);

    // 1) t = rmsnorm(x) -> ah/al (fp16 split)
    rmsnorm_split_kernel<<<MM, 256>>>(x, norm1_w, ah, al, DD);
    // 2+3) xb = t @ Wx ; yb = gelu(t @ Wy)  [dual]
    hmma_gemm<0,1,false,false><<<gemXY, 256, GEMM_SMEM>>>(ah, al, wh + WOFF_X,
        nullptr, xb, yb, nullptr, nullptr, DD, DD);
    // 4) conv -> xc (fp32) + ah/al
    conv_split_kernel<<<gMD, 256>>>(xb, conv_w, conv_b, xc, ah, al);
    // 5+6) rlin = xc @ Wa -> t ; ilin = xc @ Wi -> xb  [dual]
    hmma_gemm<0,0,false,false><<<gemAI, 256, GEMM_SMEM>>>(ah, al, wh + WOFF_A,
        nullptr, t, xb, nullptr, nullptr, DD, DD);
    // 7+8+9) gates + chunked scan + z = h*yb -> ah/al
    scan1_kernel<<<gSC, 256>>>(t, xb, xc, lam, sa, sh);
    scan2_kernel<<<(BB * DD + 255) / 256, 256>>>(sa, sh);
    scan3_kernel<<<gSC, 256>>>(t, xb, sh, yb, ah, al);
    // 10) h1 = x + z @ Wo
    hmma_gemm<0,0,true,false><<<gemO, 256, GEMM_SMEM>>>(ah, al, wh + WOFF_O,
        x, h1, h1, nullptr, nullptr, DD, DD);
    // 11) u = rmsnorm(h1) -> ah/al
    rmsnorm_split_kernel<<<MM, 256>>>(h1, norm2_w, ah, al, DD);
    // 12+13+14) ff = gelu(u @ Wg) * (u @ Wu) -> zh/zl  [gated, interleaved]
    hmma_gemm<0,0,false,true><<<gemGU, 256, GEMM_SMEM>>>(ah, al, wh + WOFF_GU,
        nullptr, nullptr, nullptr, zh, zl, HH, DD);
    // 15) out = h1 + ff @ Wd
    hmma_gemm<0,0,true,false><<<gemDn, 256, GEMM_SMEM>>>(zh, zl, wh + WOFF_D,
        h1, out, out, nullptr, nullptr, DD, HH);
}

// round 7
// speedup vs baseline: 6.5412x; 1.5735x over previous
#include <cuda_runtime.h>
#include <cuda_fp16.h>
#include <math.h>
#include <stdint.h>

// Problem dims (fixed by the dataset)
#define BB 4
#define SS 2048
#define DD 1024
#define HH 4096
#define MM (BB*SS)          // 8192 rows
#define NC 32               // scan chunks
#define CL (SS/NC)          // 64 steps per chunk

// ---------------------------------------------------------------------------
// Scratch (static device globals; no allocation in kernel_launch)
// ---------------------------------------------------------------------------
__device__ __align__(16) float g_t  [(size_t)MM*DD];   // rlin -> a
__device__ __align__(16) float g_xb [(size_t)MM*DD];   // xb / ilin -> local h
__device__ __align__(16) float g_yb [(size_t)MM*DD];   // gelu gate
__device__ __align__(16) float g_xc [(size_t)MM*DD];   // conv output
__device__ __align__(16) float g_h1 [(size_t)MM*DD];   // h1
__device__ __align__(16) float g_sa [(size_t)BB*NC*DD]; // chunk a-products
__device__ __align__(16) float g_sh [(size_t)BB*NC*DD]; // chunk h-carries

// fp16 activations (D-dim) and gated-MLP intermediate (H-dim)
__device__ __align__(16) __half g_ah[(size_t)MM*DD];
__device__ __align__(16) __half g_zh[(size_t)MM*HH];
// fp16 transposed weights, packed arena (17M halfs)
#define WOFF_X  ((size_t)0)
#define WOFF_Y  ((size_t)1*1024*1024)   // follows X (dual Wx|Wy)
#define WOFF_A  ((size_t)2*1024*1024)
#define WOFF_I  ((size_t)3*1024*1024)   // follows A (dual Wa|Wi)
#define WOFF_O  ((size_t)4*1024*1024)
#define WOFF_GU ((size_t)5*1024*1024)   // Wg/Wu column-interleaved (8192 rows)
#define WOFF_D  ((size_t)13*1024*1024)
__device__ __align__(16) __half g_wh[(size_t)17*1024*1024];

// ---------------------------------------------------------------------------
// Math helpers
// ---------------------------------------------------------------------------
__device__ __forceinline__ float geluf(float x) {
    const float c = 0.7978845608028654f; // sqrt(2/pi)
    float x3 = x * x * x;
    float t  = tanhf(c * (x + 0.044715f * x3));
    return 0.5f * x * (1.0f + t);
}
__device__ __forceinline__ float sigmoidf(float x) {
    return 1.0f / (1.0f + expf(-x));
}
__device__ __forceinline__ float softplusf(float x) {
    return fmaxf(x, 0.0f) + log1pf(expf(-fabsf(x)));
}

// ---------------------------------------------------------------------------
// PTX helpers (baseline compute_103 features only)
// ---------------------------------------------------------------------------
__device__ __forceinline__ uint32_t smem_u32(const void* p) {
    uint32_t a;
    asm("{ .reg .u64 t; cvta.to.shared.u64 t, %1; cvt.u32.u64 %0, t; }" : "=r"(a) : "l"(p));
    return a;
}
__device__ __forceinline__ void cp_async16(uint32_t dst, const void* src) {
    asm volatile("cp.async.cg.shared.global [%0], [%1], 16;" :: "r"(dst), "l"(src) : "memory");
}
__device__ __forceinline__ void ldm_x4(uint32_t& r0, uint32_t& r1, uint32_t& r2, uint32_t& r3,
                                       uint32_t addr) {
    asm volatile("ldmatrix.sync.aligned.m8n8.x4.shared.b16 {%0,%1,%2,%3}, [%4];"
                 : "=r"(r0), "=r"(r1), "=r"(r2), "=r"(r3) : "r"(addr));
}
__device__ __forceinline__ void ldm_x2(uint32_t& r0, uint32_t& r1, uint32_t addr) {
    asm volatile("ldmatrix.sync.aligned.m8n8.x2.shared.b16 {%0,%1}, [%2];"
                 : "=r"(r0), "=r"(r1) : "r"(addr));
}
__device__ __forceinline__ void mma16816(float* c, const uint32_t* a, const uint32_t* b) {
    asm volatile(
        "mma.sync.aligned.m16n8k16.row.col.f32.f16.f16.f32 "
        "{%0,%1,%2,%3}, {%4,%5,%6,%7}, {%8,%9}, {%0,%1,%2,%3};"
        : "+f"(c[0]), "+f"(c[1]), "+f"(c[2]), "+f"(c[3])
        : "r"(a[0]), "r"(a[1]), "r"(a[2]), "r"(a[3]), "r"(b[0]), "r"(b[1]));
}

// ---------------------------------------------------------------------------
// Single-product fp16 HMMA GEMM: C = act(A @ W^T) (+R), A/W fp16, fp32 accum.
// CTA 128x128, BK=64, 8 warps (2Mx4N), 3-stage cp.async, 2 CTAs/SM.
// SMEM: rows of 64 fp16 = 128B + 16B pad (stride 144B -> conflict-free ldmatrix).
// GATED mode: B rows interleave Wg/Wu columns; epilogue computes
//   ff_j = gelu(C[.,2j]) * C[.,2j+1], written as fp16.
// ---------------------------------------------------------------------------
#define GSTRIDE 144u
#define TILE_B  18432u
#define STG_B   36864u
#define GEMM_SMEM (3*STG_B)

template<int ACT1, int ACT2, bool RES, bool GATED>
__global__ void __launch_bounds__(256, 2)
hmma_gemm(const __half* __restrict__ Ah, const __half* __restrict__ Bh,
          const float* __restrict__ R, float* __restrict__ C1, float* __restrict__ C2,
          __half* __restrict__ ZH,
          int NH, int K)
{
    extern __shared__ char smem[];
    const uint32_t sb = smem_u32(smem);
    const int tid  = threadIdx.x;
    const int wid  = tid >> 5;
    const int lane = tid & 31;
    const int bm = blockIdx.y * 128;
    const int bn = blockIdx.x * 128;
    const int wr = wid >> 2;          // warp row (64 rows)
    const int wc = wid & 3;           // warp col (32 cols)

    const int nch = K >> 6;           // BK = 64

    auto fill = [&](int ch) {
        const int k0 = ch << 6;
        const uint32_t st = sb + (uint32_t)(ch % 3) * STG_B;
        #pragma unroll
        for (int r = 0; r < 4; r++) {
            const int c = tid + (r << 8);          // 0..1023
            const int row = c >> 3, kc = c & 7;
            const uint32_t dst = (uint32_t)row * GSTRIDE + (uint32_t)(kc << 4);
            cp_async16(st + dst,          Ah + (size_t)(bm + row) * K + k0 + (kc << 3));
            cp_async16(st + TILE_B + dst, Bh + (size_t)(bn + row) * K + k0 + (kc << 3));
        }
        asm volatile("cp.async.commit_group;" ::: "memory");
    };

    float acc[4][4][4];
    #pragma unroll
    for (int i = 0; i < 4; i++)
        #pragma unroll
        for (int j = 0; j < 4; j++)
            #pragma unroll
            for (int q = 0; q < 4; q++) acc[i][j][q] = 0.0f;

    fill(0);
    if (nch > 1) fill(1);
    if (nch > 2) fill(2);

    const int l16  = lane & 15;
    const int ahi  = (lane >> 4) << 4;
    const int bl8  = lane & 7;
    const int bhi  = ((lane >> 3) & 1) << 4;

    for (int i = 0; i < nch; i++) {
        if      (i + 2 < nch) asm volatile("cp.async.wait_group 2;" ::: "memory");
        else if (i + 1 < nch) asm volatile("cp.async.wait_group 1;" ::: "memory");
        else                  asm volatile("cp.async.wait_group 0;" ::: "memory");
        __syncthreads();

        const uint32_t st  = sb + (uint32_t)(i % 3) * STG_B;
        const uint32_t sAh = st;
        const uint32_t sBh = st + TILE_B;

        #pragma unroll
        for (int ks = 0; ks < 4; ks++) {
            uint32_t ah[4][4];
            #pragma unroll
            for (int mt = 0; mt < 4; mt++) {
                const uint32_t ra = (uint32_t)(wr*64 + mt*16 + l16) * GSTRIDE
                                  + (uint32_t)(ks*32 + ahi);
                ldm_x4(ah[mt][0], ah[mt][1], ah[mt][2], ah[mt][3], sAh + ra);
            }
            #pragma unroll
            for (int nt = 0; nt < 4; nt++) {
                uint32_t bh[2];
                const uint32_t rb = (uint32_t)(wc*32 + nt*8 + bl8) * GSTRIDE
                                  + (uint32_t)(ks*32 + bhi);
                ldm_x2(bh[0], bh[1], sBh + rb);
                #pragma unroll
                for (int mt = 0; mt < 4; mt++)
                    mma16816(acc[mt][nt], ah[mt], bh);
            }
        }
        __syncthreads();
        if (i + 3 < nch) fill(i + 3);
    }

    const int erow = lane >> 2;
    const int ecol = (lane & 3) << 1;

    if constexpr (GATED) {
        // (c0,c1) = (g_j, v_j); ff_j = gelu(g)*v; fp16 out, width NH.
        #pragma unroll
        for (int mt = 0; mt < 4; mt++) {
            #pragma unroll
            for (int nt = 0; nt < 4; nt++) {
                const int r0 = bm + wr*64 + mt*16 + erow;
                const int j  = ((bn + wc*32 + nt*8 + ecol) >> 1);
                const float f0 = geluf(acc[mt][nt][0]) * acc[mt][nt][1];
                const float f1 = geluf(acc[mt][nt][2]) * acc[mt][nt][3];
                ZH[(size_t)r0     * NH + j] = __float2half_rn(f0);
                ZH[(size_t)(r0+8) * NH + j] = __float2half_rn(f1);
            }
        }
        return;
    }

    // Normal epilogue: halves split at NH (NH multiple of 128).
    float* Cout;
    int act, cb;
    if (bn < NH) { Cout = C1; act = ACT1; cb = bn; }
    else         { Cout = C2; act = ACT2; cb = bn - NH; }

    #pragma unroll
    for (int mt = 0; mt < 4; mt++) {
        #pragma unroll
        for (int nt = 0; nt < 4; nt++) {
            const int r0 = bm + wr*64 + mt*16 + erow;
            const int cc = cb + wc*32 + nt*8 + ecol;
            float v0 = acc[mt][nt][0], v1 = acc[mt][nt][1];
            float v2 = acc[mt][nt][2], v3 = acc[mt][nt][3];
            if (act == 1) { v0 = geluf(v0); v1 = geluf(v1); v2 = geluf(v2); v3 = geluf(v3); }
            if (RES) {
                const float2 ra = *(const float2*)(R + (size_t)r0 * NH + cc);
                const float2 rb = *(const float2*)(R + (size_t)(r0+8) * NH + cc);
                v0 += ra.x; v1 += ra.y; v2 += rb.x; v3 += rb.y;
            }
            *(float2*)(Cout + (size_t)r0     * NH + cc) = make_float2(v0, v1);
            *(float2*)(Cout + (size_t)(r0+8) * NH + cc) = make_float2(v2, v3);
        }
    }
}

// ---------------------------------------------------------------------------
// Weight transpose to fp16: W [Kd, Nd] fp32 -> Th [(n*rstride+roff), Kd] fp16
// ---------------------------------------------------------------------------
__global__ void tsplit_kernel(const float* __restrict__ W,
                              __half* __restrict__ Th,
                              int Kd, int Nd, int rstride, int roff)
{
    __shared__ float tile[32][33];
    const int n0 = blockIdx.x * 32, k0 = blockIdx.y * 32;
    const int tx = threadIdx.x, ty = threadIdx.y;   // (32, 8)
    #pragma unroll
    for (int i = 0; i < 32; i += 8)
        tile[ty + i][tx] = W[(size_t)(k0 + ty + i) * Nd + n0 + tx];
    __syncthreads();
    #pragma unroll
    for (int i = 0; i < 32; i += 8) {
        const float v = tile[tx][ty + i];
        const size_t o = ((size_t)(n0 + ty + i) * rstride + roff) * Kd + k0 + tx;
        Th[o] = __float2half_rn(v);
    }
}

// ---------------------------------------------------------------------------
// RMSNorm with fp16 output
// ---------------------------------------------------------------------------
__global__ void rmsnorm_f16_kernel(const float* __restrict__ x,
                                   const float* __restrict__ w,
                                   __half* __restrict__ oh, int D)
{
    const int row = blockIdx.x;
    const float* xr = x + (size_t)row * D;
    float ss = 0.0f;
    for (int i = threadIdx.x; i < D; i += blockDim.x) {
        float v = xr[i];
        ss = fmaf(v, v, ss);
    }
    #pragma unroll
    for (int off = 16; off > 0; off >>= 1)
        ss += __shfl_xor_sync(0xffffffff, ss, off);
    __shared__ float red[32];
    const int lane = threadIdx.x & 31, wid = threadIdx.x >> 5;
    if (lane == 0) red[wid] = ss;
    __syncthreads();
    const int nw = blockDim.x >> 5;
    if (wid == 0) {
        float s = (lane < nw) ? red[lane] : 0.0f;
        #pragma unroll
        for (int off = 16; off > 0; off >>= 1)
            s += __shfl_xor_sync(0xffffffff, s, off);
        if (lane == 0) red[0] = s;
    }
    __syncthreads();
    const float inv = rsqrtf(red[0] / (float)D + 1e-6f);
    for (int i = threadIdx.x; i < D; i += blockDim.x)
        oh[(size_t)row * D + i] = __float2half_rn(xr[i] * inv * w[i]);
}

// ---------------------------------------------------------------------------
// Causal depthwise conv (K=4) with fused fp32 + fp16 outputs
// ---------------------------------------------------------------------------
__global__ void conv_f16_kernel(const float* __restrict__ in,
                                const float* __restrict__ cw,
                                const float* __restrict__ cb,
                                float* __restrict__ xc,
                                __half* __restrict__ oh)
{
    const size_t idx = (size_t)blockIdx.x * blockDim.x + threadIdx.x;
    if (idx >= (size_t)MM * DD) return;
    const int d = (int)(idx % DD);
    const int s = (int)((idx / DD) % SS);
    float acc = cb[d];
    #pragma unroll
    for (int k = 0; k < 4; k++) {
        if (s + k - 3 >= 0)
            acc = fmaf(cw[k * DD + d], in[idx - (size_t)(3 - k) * DD], acc);
    }
    xc[idx] = acc;
    oh[idx] = __float2half_rn(acc);
}

// ---------------------------------------------------------------------------
// Scan pass 1: fused gates + chunk-local scan.
// ---------------------------------------------------------------------------
__global__ void scan1_kernel(float* __restrict__ rlin_a,
                             float* __restrict__ ilin_h,
                             const float* __restrict__ xc,
                             const float* __restrict__ lam,
                             float* __restrict__ sa,
                             float* __restrict__ sh)
{
    const int idx = blockIdx.x * blockDim.x + threadIdx.x;
    if (idx >= BB * NC * DD) return;
    const int d     = idx % DD;
    const int chunk = (idx / DD) % NC;
    const int batch = idx / (DD * NC);
    const float cfac = -8.0f * softplusf(lam[d]);
    const size_t base = ((size_t)batch * SS + (size_t)chunk * CL) * DD + d;

    float p = 1.0f, h = 0.0f;
    for (int t = 0; t < CL; t++) {
        const size_t off = base + (size_t)t * DD;
        const float r  = sigmoidf(rlin_a[off]);
        const float ii = sigmoidf(ilin_h[off]);
        const float a  = expf(cfac * r);
        const float b  = sqrtf(fmaxf(1.0f - a * a, 1e-12f)) * ii * xc[off];
        h = fmaf(a, h, b);
        p *= a;
        rlin_a[off] = a;
        ilin_h[off] = h;
    }
    sa[idx] = p;
    sh[idx] = h;
}

// ---------------------------------------------------------------------------
// Scan pass 2: combine chunk carries.
// ---------------------------------------------------------------------------
__global__ void scan2_kernel(const float* __restrict__ sa, float* __restrict__ sh)
{
    const int idx = blockIdx.x * blockDim.x + threadIdx.x;
    if (idx >= BB * DD) return;
    const int d = idx % DD, batch = idx / DD;
    float H = 0.0f;
    for (int c = 0; c < NC; c++) {
        const size_t o = ((size_t)batch * NC + c) * DD + d;
        H = fmaf(sa[o], H, sh[o]);
        sh[o] = H;
    }
}

// ---------------------------------------------------------------------------
// Scan pass 3: apply carries, fuse z = h * yb, fp16 out.
// ---------------------------------------------------------------------------
__global__ void scan3_kernel(const float* __restrict__ aArr,
                             const float* __restrict__ lhArr,
                             const float* __restrict__ sh,
                             const float* __restrict__ yb,
                             __half* __restrict__ zh)
{
    const int idx = blockIdx.x * blockDim.x + threadIdx.x;
    if (idx >= BB * NC * DD) return;
    const int d     = idx % DD;
    const int chunk = (idx / DD) % NC;
    const int batch = idx / (DD * NC);
    const float carry = (chunk == 0)
        ? 0.0f : sh[((size_t)batch * NC + chunk - 1) * DD + d];
    const size_t base = ((size_t)batch * SS + (size_t)chunk * CL) * DD + d;

    float p = 1.0f;
    for (int t = 0; t < CL; t++) {
        const size_t off = base + (size_t)t * DD;
        p *= aArr[off];
        const float h = fmaf(p, carry, lhArr[off]);
        zh[off] = __float2half_rn(h * yb[off]);
    }
}

// ---------------------------------------------------------------------------
// Launch
// ---------------------------------------------------------------------------
extern "C" void kernel_launch(void* const* d_in, const int* in_sizes, int n_in,
                              void* d_out, int out_size)
{
    const float* x       = (const float*)d_in[0];
    const float* norm1_w = (const float*)d_in[1];
    const float* Wx      = (const float*)d_in[2];
    const float* Wy      = (const float*)d_in[3];
    const float* conv_w  = (const float*)d_in[4];
    const float* conv_b  = (const float*)d_in[5];
    const float* Wi      = (const float*)d_in[6];
    const float* Wa      = (const float*)d_in[7];
    const float* lam     = (const float*)d_in[8];
    const float* Wo      = (const float*)d_in[9];
    const float* norm2_w = (const float*)d_in[10];
    const float* Wg      = (const float*)d_in[11];
    const float* Wu      = (const float*)d_in[12];
    const float* Wd      = (const float*)d_in[13];
    float* out = (float*)d_out;

    float *t, *xb, *yb, *xc, *h1, *sa, *sh;
    __half *ah, *zh, *wh;
    cudaGetSymbolAddress((void**)&t,  g_t);
    cudaGetSymbolAddress((void**)&xb, g_xb);
    cudaGetSymbolAddress((void**)&yb, g_yb);
    cudaGetSymbolAddress((void**)&xc, g_xc);
    cudaGetSymbolAddress((void**)&h1, g_h1);
    cudaGetSymbolAddress((void**)&sa, g_sa);
    cudaGetSymbolAddress((void**)&sh, g_sh);
    cudaGetSymbolAddress((void**)&ah, g_ah);
    cudaGetSymbolAddress((void**)&zh, g_zh);
    cudaGetSymbolAddress((void**)&wh, g_wh);

    cudaFuncSetAttribute(hmma_gemm<0,1,false,false>, cudaFuncAttributeMaxDynamicSharedMemorySize, GEMM_SMEM);
    cudaFuncSetAttribute(hmma_gemm<0,0,false,false>, cudaFuncAttributeMaxDynamicSharedMemorySize, GEMM_SMEM);
    cudaFuncSetAttribute(hmma_gemm<0,0,true,false>,  cudaFuncAttributeMaxDynamicSharedMemorySize, GEMM_SMEM);
    cudaFuncSetAttribute(hmma_gemm<0,0,false,true>,  cudaFuncAttributeMaxDynamicSharedMemorySize, GEMM_SMEM);

    const dim3 tsb(32, 8);
    const size_t nMD = (size_t)MM * DD;
    const int gMD = (int)((nMD + 255) / 256);
    const int gSC = (BB * NC * DD + 255) / 256;

    const dim3 gemXY(2048 / 128, MM / 128);   // dual Wx|Wy
    const dim3 gemAI(2048 / 128, MM / 128);   // dual Wa|Wi
    const dim3 gemGU(8192 / 128, MM / 128);   // interleaved Wg|Wu (gated)
    const dim3 gemO (1024 / 128, MM / 128);   // Wo (K=1024)
    const dim3 gemDn(1024 / 128, MM / 128);   // Wd (K=4096)

    // --- weight prep: transpose to fp16 [N,K] ---
    tsplit_kernel<<<dim3(DD/32, DD/32), tsb>>>(Wx, wh + WOFF_X, DD, DD, 1, 0);
    tsplit_kernel<<<dim3(DD/32, DD/32), tsb>>>(Wy, wh + WOFF_Y, DD, DD, 1, 0);
    tsplit_kernel<<<dim3(DD/32, DD/32), tsb>>>(Wa, wh + WOFF_A, DD, DD, 1, 0);
    tsplit_kernel<<<dim3(DD/32, DD/32), tsb>>>(Wi, wh + WOFF_I, DD, DD, 1, 0);
    tsplit_kernel<<<dim3(DD/32, DD/32), tsb>>>(Wo, wh + WOFF_O, DD, DD, 1, 0);
    tsplit_kernel<<<dim3(HH/32, DD/32), tsb>>>(Wg, wh + WOFF_GU, DD, HH, 2, 0);  // even rows
    tsplit_kernel<<<dim3(HH/32, DD/32), tsb>>>(Wu, wh + WOFF_GU, DD, HH, 2, 1);  // odd rows
    tsplit_kernel<<<dim3(DD/32, HH/32), tsb>>>(Wd, wh + WOFF_D, HH, DD, 1, 0);

    // 1) t = rmsnorm(x) -> ah (fp16)
    rmsnorm_f16_kernel<<<MM, 256>>>(x, norm1_w, ah, DD);
    // 2+3) xb = t @ Wx ; yb = gelu(t @ Wy)  [dual]
    hmma_gemm<0,1,false,false><<<gemXY, 256, GEMM_SMEM>>>(ah, wh + WOFF_X,
        nullptr, xb, yb, nullptr, DD, DD);
    // 4) conv -> xc (fp32) + ah (fp16)
    conv_f16_kernel<<<gMD, 256>>>(xb, conv_w, conv_b, xc, ah);
    // 5+6) rlin = xc @ Wa -> t ; ilin = xc @ Wi -> xb  [dual]
    hmma_gemm<0,0,false,false><<<gemAI, 256, GEMM_SMEM>>>(ah, wh + WOFF_A,
        nullptr, t, xb, nullptr, DD, DD);
    // 7+8+9) gates + chunked scan + z = h*yb -> ah (fp16)
    scan1_kernel<<<gSC, 256>>>(t, xb, xc, lam, sa, sh);
    scan2_kernel<<<(BB * DD + 255) / 256, 256>>>(sa, sh);
    scan3_kernel<<<gSC, 256>>>(t, xb, sh, yb, ah);
    // 10) h1 = x + z @ Wo
    hmma_gemm<0,0,true,false><<<gemO, 256, GEMM_SMEM>>>(ah, wh + WOFF_O,
        x, h1, h1, nullptr, DD, DD);
    // 11) u = rmsnorm(h1) -> ah
    rmsnorm_f16_kernel<<<MM, 256>>>(h1, norm2_w, ah, DD);
    // 12+13+14) ff = gelu(u @ Wg) * (u @ Wu) -> zh  [gated, interleaved]
    hmma_gemm<0,0,false,true><<<gemGU, 256, GEMM_SMEM>>>(ah, wh + WOFF_GU,
        nullptr, nullptr, nullptr, zh, HH, DD);
    // 15) out = h1 + ff @ Wd
    hmma_gemm<0,0,true,false><<<gemDn, 256, GEMM_SMEM>>>(zh, wh + WOFF_D,
        h1, out, out, nullptr, DD, HH);
}

// round 8
// speedup vs baseline: 6.5855x; 1.0068x over previous
#include <cuda_runtime.h>
#include <cuda_fp16.h>
#include <math.h>
#include <stdint.h>

// Problem dims (fixed by the dataset)
#define BB 4
#define SS 2048
#define DD 1024
#define HH 4096
#define MM (BB*SS)          // 8192 rows
#define NC 32               // scan chunks
#define CL (SS/NC)          // 64 steps per chunk

// ---------------------------------------------------------------------------
// Scratch (static device globals; no allocation in kernel_launch)
// ---------------------------------------------------------------------------
__device__ __align__(16) float g_t  [(size_t)MM*DD];   // rlin -> a
__device__ __align__(16) float g_xb [(size_t)MM*DD];   // xb / ilin -> local h
__device__ __align__(16) float g_yb [(size_t)MM*DD];   // gelu gate
__device__ __align__(16) float g_xc [(size_t)MM*DD];   // conv output
__device__ __align__(16) float g_h1 [(size_t)MM*DD];   // h1
__device__ __align__(16) float g_sa [(size_t)BB*NC*DD]; // chunk a-products
__device__ __align__(16) float g_sh [(size_t)BB*NC*DD]; // chunk h-carries

// fp16 activations (D-dim) and gated-MLP intermediate (H-dim)
__device__ __align__(16) __half g_ah[(size_t)MM*DD];
__device__ __align__(16) __half g_zh[(size_t)MM*HH];
// fp16 transposed weights, packed arena (17M halfs)
#define WOFF_X  ((size_t)0)
#define WOFF_Y  ((size_t)1*1024*1024)   // follows X (dual Wx|Wy)
#define WOFF_A  ((size_t)2*1024*1024)
#define WOFF_I  ((size_t)3*1024*1024)   // follows A (dual Wa|Wi)
#define WOFF_O  ((size_t)4*1024*1024)
#define WOFF_GU ((size_t)5*1024*1024)   // Wg/Wu column-interleaved (8192 rows)
#define WOFF_D  ((size_t)13*1024*1024)
__device__ __align__(16) __half g_wh[(size_t)17*1024*1024];

// ---------------------------------------------------------------------------
// Math helpers
// ---------------------------------------------------------------------------
__device__ __forceinline__ float geluf(float x) {
    const float c = 0.7978845608028654f; // sqrt(2/pi)
    float x3 = x * x * x;
    float t  = tanhf(c * (x + 0.044715f * x3));
    return 0.5f * x * (1.0f + t);
}
__device__ __forceinline__ float sigmoidf(float x) {
    return 1.0f / (1.0f + expf(-x));
}
__device__ __forceinline__ float softplusf(float x) {
    return fmaxf(x, 0.0f) + log1pf(expf(-fabsf(x)));
}

// ---------------------------------------------------------------------------
// PTX helpers (baseline compute_103 features only)
// ---------------------------------------------------------------------------
__device__ __forceinline__ uint32_t smem_u32(const void* p) {
    uint32_t a;
    asm("{ .reg .u64 t; cvta.to.shared.u64 t, %1; cvt.u32.u64 %0, t; }" : "=r"(a) : "l"(p));
    return a;
}
__device__ __forceinline__ void cp_async16(uint32_t dst, const void* src) {
    asm volatile("cp.async.cg.shared.global [%0], [%1], 16;" :: "r"(dst), "l"(src) : "memory");
}
__device__ __forceinline__ void ldm_x4(uint32_t& r0, uint32_t& r1, uint32_t& r2, uint32_t& r3,
                                       uint32_t addr) {
    asm volatile("ldmatrix.sync.aligned.m8n8.x4.shared.b16 {%0,%1,%2,%3}, [%4];"
                 : "=r"(r0), "=r"(r1), "=r"(r2), "=r"(r3) : "r"(addr));
}
__device__ __forceinline__ void mma16816(float* c, const uint32_t* a, const uint32_t* b) {
    asm volatile(
        "mma.sync.aligned.m16n8k16.row.col.f32.f16.f16.f32 "
        "{%0,%1,%2,%3}, {%4,%5,%6,%7}, {%8,%9}, {%0,%1,%2,%3};"
        : "+f"(c[0]), "+f"(c[1]), "+f"(c[2]), "+f"(c[3])
        : "r"(a[0]), "r"(a[1]), "r"(a[2]), "r"(a[3]), "r"(b[0]), "r"(b[1]));
}

// ---------------------------------------------------------------------------
// Single-product fp16 HMMA GEMM: C = act(A @ W^T) (+R), A/W fp16, fp32 accum.
// CTA 128x128, BK=64, 8 warps (2Mx4N), 3-stage cp.async, 2 CTAs/SM.
// B fragments loaded pairwise via ldmatrix.x4 (2 n-tiles per instruction).
// ---------------------------------------------------------------------------
#define GSTRIDE 144u
#define TILE_B  18432u
#define STG_B   36864u
#define GEMM_SMEM (3*STG_B)

template<int ACT1, int ACT2, bool RES, bool GATED>
__global__ void __launch_bounds__(256, 2)
hmma_gemm(const __half* __restrict__ Ah, const __half* __restrict__ Bh,
          const float* __restrict__ R, float* __restrict__ C1, float* __restrict__ C2,
          __half* __restrict__ ZH,
          int NH, int K)
{
    extern __shared__ char smem[];
    const uint32_t sb = smem_u32(smem);
    const int tid  = threadIdx.x;
    const int wid  = tid >> 5;
    const int lane = tid & 31;
    const int bm = blockIdx.y * 128;
    const int bn = blockIdx.x * 128;
    const int wr = wid >> 2;          // warp row (64 rows)
    const int wc = wid & 3;           // warp col (32 cols)

    const int nch = K >> 6;           // BK = 64

    auto fill = [&](int ch) {
        const int k0 = ch << 6;
        const uint32_t st = sb + (uint32_t)(ch % 3) * STG_B;
        #pragma unroll
        for (int r = 0; r < 4; r++) {
            const int c = tid + (r << 8);          // 0..1023
            const int row = c >> 3, kc = c & 7;
            const uint32_t dst = (uint32_t)row * GSTRIDE + (uint32_t)(kc << 4);
            cp_async16(st + dst,          Ah + (size_t)(bm + row) * K + k0 + (kc << 3));
            cp_async16(st + TILE_B + dst, Bh + (size_t)(bn + row) * K + k0 + (kc << 3));
        }
        asm volatile("cp.async.commit_group;" ::: "memory");
    };

    float acc[4][4][4];
    #pragma unroll
    for (int i = 0; i < 4; i++)
        #pragma unroll
        for (int j = 0; j < 4; j++)
            #pragma unroll
            for (int q = 0; q < 4; q++) acc[i][j][q] = 0.0f;

    fill(0);
    if (nch > 1) fill(1);
    if (nch > 2) fill(2);

    // A ldmatrix.x4 addressing (row-major A): rows mt*16 + lane%16, +16B for hi lanes
    const int l16  = lane & 15;
    const int ahi  = (lane >> 4) << 4;
    // B ldmatrix.x4 addressing (pairs of n-tiles): rows ntp*16 + (lane/16)*8 + lane%8,
    //   col offset +16B for lanes with bit3 set
    const int brow = ((lane >> 4) << 3) + (lane & 7);
    const int bhi  = ((lane >> 3) & 1) << 4;

    for (int i = 0; i < nch; i++) {
        if      (i + 2 < nch) asm volatile("cp.async.wait_group 2;" ::: "memory");
        else if (i + 1 < nch) asm volatile("cp.async.wait_group 1;" ::: "memory");
        else                  asm volatile("cp.async.wait_group 0;" ::: "memory");
        __syncthreads();

        const uint32_t st  = sb + (uint32_t)(i % 3) * STG_B;
        const uint32_t sAh = st;
        const uint32_t sBh = st + TILE_B;

        #pragma unroll
        for (int ks = 0; ks < 4; ks++) {
            uint32_t ah[4][4];
            #pragma unroll
            for (int mt = 0; mt < 4; mt++) {
                const uint32_t ra = (uint32_t)(wr*64 + mt*16 + l16) * GSTRIDE
                                  + (uint32_t)(ks*32 + ahi);
                ldm_x4(ah[mt][0], ah[mt][1], ah[mt][2], ah[mt][3], sAh + ra);
            }
            #pragma unroll
            for (int ntp = 0; ntp < 2; ntp++) {
                uint32_t bq[4];
                const uint32_t rb = (uint32_t)(wc*32 + ntp*16 + brow) * GSTRIDE
                                  + (uint32_t)(ks*32 + bhi);
                ldm_x4(bq[0], bq[1], bq[2], bq[3], sBh + rb);
                #pragma unroll
                for (int mt = 0; mt < 4; mt++) {
                    mma16816(acc[mt][2*ntp],   ah[mt], bq);
                    mma16816(acc[mt][2*ntp+1], ah[mt], bq + 2);
                }
            }
        }
        __syncthreads();
        if (i + 3 < nch) fill(i + 3);
    }

    const int erow = lane >> 2;
    const int ecol = (lane & 3) << 1;

    if constexpr (GATED) {
        // (c0,c1) = (g_j, v_j); ff_j = gelu(g)*v; fp16 out, width NH.
        #pragma unroll
        for (int mt = 0; mt < 4; mt++) {
            #pragma unroll
            for (int nt = 0; nt < 4; nt++) {
                const int r0 = bm + wr*64 + mt*16 + erow;
                const int j  = ((bn + wc*32 + nt*8 + ecol) >> 1);
                const float f0 = geluf(acc[mt][nt][0]) * acc[mt][nt][1];
                const float f1 = geluf(acc[mt][nt][2]) * acc[mt][nt][3];
                ZH[(size_t)r0     * NH + j] = __float2half_rn(f0);
                ZH[(size_t)(r0+8) * NH + j] = __float2half_rn(f1);
            }
        }
        return;
    }

    // Normal epilogue: halves split at NH (NH multiple of 128).
    float* Cout;
    int act, cb;
    if (bn < NH) { Cout = C1; act = ACT1; cb = bn; }
    else         { Cout = C2; act = ACT2; cb = bn - NH; }

    #pragma unroll
    for (int mt = 0; mt < 4; mt++) {
        #pragma unroll
        for (int nt = 0; nt < 4; nt++) {
            const int r0 = bm + wr*64 + mt*16 + erow;
            const int cc = cb + wc*32 + nt*8 + ecol;
            float v0 = acc[mt][nt][0], v1 = acc[mt][nt][1];
            float v2 = acc[mt][nt][2], v3 = acc[mt][nt][3];
            if (act == 1) { v0 = geluf(v0); v1 = geluf(v1); v2 = geluf(v2); v3 = geluf(v3); }
            if (RES) {
                const float2 ra = *(const float2*)(R + (size_t)r0 * NH + cc);
                const float2 rb = *(const float2*)(R + (size_t)(r0+8) * NH + cc);
                v0 += ra.x; v1 += ra.y; v2 += rb.x; v3 += rb.y;
            }
            *(float2*)(Cout + (size_t)r0     * NH + cc) = make_float2(v0, v1);
            *(float2*)(Cout + (size_t)(r0+8) * NH + cc) = make_float2(v2, v3);
        }
    }
}

// ---------------------------------------------------------------------------
// Weight transpose to fp16: W [Kd, Nd] fp32 -> Th [(n*rstride+roff), Kd] fp16
// ---------------------------------------------------------------------------
__global__ void tsplit_kernel(const float* __restrict__ W,
                              __half* __restrict__ Th,
                              int Kd, int Nd, int rstride, int roff)
{
    __shared__ float tile[32][33];
    const int n0 = blockIdx.x * 32, k0 = blockIdx.y * 32;
    const int tx = threadIdx.x, ty = threadIdx.y;   // (32, 8)
    #pragma unroll
    for (int i = 0; i < 32; i += 8)
        tile[ty + i][tx] = W[(size_t)(k0 + ty + i) * Nd + n0 + tx];
    __syncthreads();
    #pragma unroll
    for (int i = 0; i < 32; i += 8) {
        const float v = tile[tx][ty + i];
        const size_t o = ((size_t)(n0 + ty + i) * rstride + roff) * Kd + k0 + tx;
        Th[o] = __float2half_rn(v);
    }
}

// ---------------------------------------------------------------------------
// RMSNorm with fp16 output
// ---------------------------------------------------------------------------
__global__ void rmsnorm_f16_kernel(const float* __restrict__ x,
                                   const float* __restrict__ w,
                                   __half* __restrict__ oh, int D)
{
    const int row = blockIdx.x;
    const float* xr = x + (size_t)row * D;
    float ss = 0.0f;
    for (int i = threadIdx.x; i < D; i += blockDim.x) {
        float v = xr[i];
        ss = fmaf(v, v, ss);
    }
    #pragma unroll
    for (int off = 16; off > 0; off >>= 1)
        ss += __shfl_xor_sync(0xffffffff, ss, off);
    __shared__ float red[32];
    const int lane = threadIdx.x & 31, wid = threadIdx.x >> 5;
    if (lane == 0) red[wid] = ss;
    __syncthreads();
    const int nw = blockDim.x >> 5;
    if (wid == 0) {
        float s = (lane < nw) ? red[lane] : 0.0f;
        #pragma unroll
        for (int off = 16; off > 0; off >>= 1)
            s += __shfl_xor_sync(0xffffffff, s, off);
        if (lane == 0) red[0] = s;
    }
    __syncthreads();
    const float inv = rsqrtf(red[0] / (float)D + 1e-6f);
    for (int i = threadIdx.x; i < D; i += blockDim.x)
        oh[(size_t)row * D + i] = __float2half_rn(xr[i] * inv * w[i]);
}

// ---------------------------------------------------------------------------
// Causal depthwise conv (K=4) with fused fp32 + fp16 outputs
// ---------------------------------------------------------------------------
__global__ void conv_f16_kernel(const float* __restrict__ in,
                                const float* __restrict__ cw,
                                const float* __restrict__ cb,
                                float* __restrict__ xc,
                                __half* __restrict__ oh)
{
    const size_t idx = (size_t)blockIdx.x * blockDim.x + threadIdx.x;
    if (idx >= (size_t)MM * DD) return;
    const int d = (int)(idx % DD);
    const int s = (int)((idx / DD) % SS);
    float acc = cb[d];
    #pragma unroll
    for (int k = 0; k < 4; k++) {
        if (s + k - 3 >= 0)
            acc = fmaf(cw[k * DD + d], in[idx - (size_t)(3 - k) * DD], acc);
    }
    xc[idx] = acc;
    oh[idx] = __float2half_rn(acc);
}

// ---------------------------------------------------------------------------
// Scan pass 1: fused gates + chunk-local scan.
// ---------------------------------------------------------------------------
__global__ void scan1_kernel(float* __restrict__ rlin_a,
                             float* __restrict__ ilin_h,
                             const float* __restrict__ xc,
                             const float* __restrict__ lam,
                             float* __restrict__ sa,
                             float* __restrict__ sh)
{
    const int idx = blockIdx.x * blockDim.x + threadIdx.x;
    if (idx >= BB * NC * DD) return;
    const int d     = idx % DD;
    const int chunk = (idx / DD) % NC;
    const int batch = idx / (DD * NC);
    const float cfac = -8.0f * softplusf(lam[d]);
    const size_t base = ((size_t)batch * SS + (size_t)chunk * CL) * DD + d;

    float p = 1.0f, h = 0.0f;
    for (int t = 0; t < CL; t++) {
        const size_t off = base + (size_t)t * DD;
        const float r  = sigmoidf(rlin_a[off]);
        const float ii = sigmoidf(ilin_h[off]);
        const float a  = expf(cfac * r);
        const float b  = sqrtf(fmaxf(1.0f - a * a, 1e-12f)) * ii * xc[off];
        h = fmaf(a, h, b);
        p *= a;
        rlin_a[off] = a;
        ilin_h[off] = h;
    }
    sa[idx] = p;
    sh[idx] = h;
}

// ---------------------------------------------------------------------------
// Scan pass 2: combine chunk carries.
// ---------------------------------------------------------------------------
__global__ void scan2_kernel(const float* __restrict__ sa, float* __restrict__ sh)
{
    const int idx = blockIdx.x * blockDim.x + threadIdx.x;
    if (idx >= BB * DD) return;
    const int d = idx % DD, batch = idx / DD;
    float H = 0.0f;
    for (int c = 0; c < NC; c++) {
        const size_t o = ((size_t)batch * NC + c) * DD + d;
        H = fmaf(sa[o], H, sh[o]);
        sh[o] = H;
    }
}

// ---------------------------------------------------------------------------
// Scan pass 3: apply carries, fuse z = h * yb, fp16 out.
// ---------------------------------------------------------------------------
__global__ void scan3_kernel(const float* __restrict__ aArr,
                             const float* __restrict__ lhArr,
                             const float* __restrict__ sh,
                             const float* __restrict__ yb,
                             __half* __restrict__ zh)
{
    const int idx = blockIdx.x * blockDim.x + threadIdx.x;
    if (idx >= BB * NC * DD) return;
    const int d     = idx % DD;
    const int chunk = (idx / DD) % NC;
    const int batch = idx / (DD * NC);
    const float carry = (chunk == 0)
        ? 0.0f : sh[((size_t)batch * NC + chunk - 1) * DD + d];
    const size_t base = ((size_t)batch * SS + (size_t)chunk * CL) * DD + d;

    float p = 1.0f;
    for (int t = 0; t < CL; t++) {
        const size_t off = base + (size_t)t * DD;
        p *= aArr[off];
        const float h = fmaf(p, carry, lhArr[off]);
        zh[off] = __float2half_rn(h * yb[off]);
    }
}

// ---------------------------------------------------------------------------
// Launch (ordered so launch #6 is the dual Wx|Wy GEMM -> ncu -s 5 -c 1 hits it)
// ---------------------------------------------------------------------------
extern "C" void kernel_launch(void* const* d_in, const int* in_sizes, int n_in,
                              void* d_out, int out_size)
{
    const float* x       = (const float*)d_in[0];
    const float* norm1_w = (const float*)d_in[1];
    const float* Wx      = (const float*)d_in[2];
    const float* Wy      = (const float*)d_in[3];
    const float* conv_w  = (const float*)d_in[4];
    const float* conv_b  = (const float*)d_in[5];
    const float* Wi      = (const float*)d_in[6];
    const float* Wa      = (const float*)d_in[7];
    const float* lam     = (const float*)d_in[8];
    const float* Wo      = (const float*)d_in[9];
    const float* norm2_w = (const float*)d_in[10];
    const float* Wg      = (const float*)d_in[11];
    const float* Wu      = (const float*)d_in[12];
    const float* Wd      = (const float*)d_in[13];
    float* out = (float*)d_out;

    float *t, *xb, *yb, *xc, *h1, *sa, *sh;
    __half *ah, *zh, *wh;
    cudaGetSymbolAddress((void**)&t,  g_t);
    cudaGetSymbolAddress((void**)&xb, g_xb);
    cudaGetSymbolAddress((void**)&yb, g_yb);
    cudaGetSymbolAddress((void**)&xc, g_xc);
    cudaGetSymbolAddress((void**)&h1, g_h1);
    cudaGetSymbolAddress((void**)&sa, g_sa);
    cudaGetSymbolAddress((void**)&sh, g_sh);
    cudaGetSymbolAddress((void**)&ah, g_ah);
    cudaGetSymbolAddress((void**)&zh, g_zh);
    cudaGetSymbolAddress((void**)&wh, g_wh);

    cudaFuncSetAttribute(hmma_gemm<0,1,false,false>, cudaFuncAttributeMaxDynamicSharedMemorySize, GEMM_SMEM);
    cudaFuncSetAttribute(hmma_gemm<0,0,false,false>, cudaFuncAttributeMaxDynamicSharedMemorySize, GEMM_SMEM);
    cudaFuncSetAttribute(hmma_gemm<0,0,true,false>,  cudaFuncAttributeMaxDynamicSharedMemorySize, GEMM_SMEM);
    cudaFuncSetAttribute(hmma_gemm<0,0,false,true>,  cudaFuncAttributeMaxDynamicSharedMemorySize, GEMM_SMEM);

    const dim3 tsb(32, 8);
    const size_t nMD = (size_t)MM * DD;
    const int gMD = (int)((nMD + 255) / 256);
    const int gSC = (BB * NC * DD + 255) / 256;

    const dim3 gemXY(2048 / 128, MM / 128);   // dual Wx|Wy
    const dim3 gemAI(2048 / 128, MM / 128);   // dual Wa|Wi
    const dim3 gemGU(8192 / 128, MM / 128);   // interleaved Wg|Wu (gated)
    const dim3 gemO (1024 / 128, MM / 128);   // Wo (K=1024)
    const dim3 gemDn(1024 / 128, MM / 128);   // Wd (K=4096)

    // #1..#5: weight prep (X, Y) + rmsnorm1 + weight prep (A, I)
    tsplit_kernel<<<dim3(DD/32, DD/32), tsb>>>(Wx, wh + WOFF_X, DD, DD, 1, 0);
    tsplit_kernel<<<dim3(DD/32, DD/32), tsb>>>(Wy, wh + WOFF_Y, DD, DD, 1, 0);
    rmsnorm_f16_kernel<<<MM, 256>>>(x, norm1_w, ah, DD);
    tsplit_kernel<<<dim3(DD/32, DD/32), tsb>>>(Wa, wh + WOFF_A, DD, DD, 1, 0);
    tsplit_kernel<<<dim3(DD/32, DD/32), tsb>>>(Wi, wh + WOFF_I, DD, DD, 1, 0);
    // #6: xb = t @ Wx ; yb = gelu(t @ Wy)  [dual]  <-- ncu profiles this one
    hmma_gemm<0,1,false,false><<<gemXY, 256, GEMM_SMEM>>>(ah, wh + WOFF_X,
        nullptr, xb, yb, nullptr, DD, DD);
    // conv -> xc (fp32) + ah (fp16)
    conv_f16_kernel<<<gMD, 256>>>(xb, conv_w, conv_b, xc, ah);
    tsplit_kernel<<<dim3(DD/32, DD/32), tsb>>>(Wo, wh + WOFF_O, DD, DD, 1, 0);
    // rlin = xc @ Wa -> t ; ilin = xc @ Wi -> xb  [dual]
    hmma_gemm<0,0,false,false><<<gemAI, 256, GEMM_SMEM>>>(ah, wh + WOFF_A,
        nullptr, t, xb, nullptr, DD, DD);
    // gates + chunked scan + z = h*yb -> ah (fp16)
    scan1_kernel<<<gSC, 256>>>(t, xb, xc, lam, sa, sh);
    scan2_kernel<<<(BB * DD + 255) / 256, 256>>>(sa, sh);
    scan3_kernel<<<gSC, 256>>>(t, xb, sh, yb, ah);
    // h1 = x + z @ Wo
    hmma_gemm<0,0,true,false><<<gemO, 256, GEMM_SMEM>>>(ah, wh + WOFF_O,
        x, h1, h1, nullptr, DD, DD);
    // u = rmsnorm(h1) -> ah
    rmsnorm_f16_kernel<<<MM, 256>>>(h1, norm2_w, ah, DD);
    tsplit_kernel<<<dim3(HH/32, DD/32), tsb>>>(Wg, wh + WOFF_GU, DD, HH, 2, 0);  // even rows
    tsplit_kernel<<<dim3(HH/32, DD/32), tsb>>>(Wu, wh + WOFF_GU, DD, HH, 2, 1);  // odd rows
    // ff = gelu(u @ Wg) * (u @ Wu) -> zh  [gated, interleaved]
    hmma_gemm<0,0,false,true><<<gemGU, 256, GEMM_SMEM>>>(ah, wh + WOFF_GU,
        nullptr, nullptr, nullptr, zh, HH, DD);
    tsplit_kernel<<<dim3(DD/32, HH/32), tsb>>>(Wd, wh + WOFF_D, HH, DD, 1, 0);
    // out = h1 + ff @ Wd
    hmma_gemm<0,0,true,false><<<gemDn, 256, GEMM_SMEM>>>(zh, wh + WOFF_D,
        h1, out, out, nullptr, DD, HH);
}

// round 9
// speedup vs baseline: 6.8227x; 1.0360x over previous
#include <cuda_runtime.h>
#include <cuda_fp16.h>
#include <math.h>
#include <stdint.h>

// Problem dims (fixed by the dataset)
#define BB 4
#define SS 2048
#define DD 1024
#define HH 4096
#define MM (BB*SS)          // 8192 rows
#define NC 32               // scan chunks
#define CL (SS/NC)          // 64 steps per chunk

// ---------------------------------------------------------------------------
// Scratch (static device globals; no allocation in kernel_launch)
// ---------------------------------------------------------------------------
__device__ __align__(16) float g_lh [(size_t)MM*DD];   // scan local h (fp32)
__device__ __align__(16) float g_h1 [(size_t)MM*DD];   // h1 trunk (fp32)
__device__ __align__(16) float g_sa [(size_t)BB*NC*DD]; // chunk a-products
__device__ __align__(16) float g_sh [(size_t)BB*NC*DD]; // chunk h-carries

// fp16 streams
__device__ __align__(16) __half g_ah [(size_t)MM*DD];  // rmsnorm out / conv out / z
__device__ __align__(16) __half g_xbh[(size_t)MM*DD];  // xb (gemXY C1)
__device__ __align__(16) __half g_ybh[(size_t)MM*DD];  // yb (gemXY C2, gelu)
__device__ __align__(16) __half g_rl [(size_t)MM*DD];  // rlin -> a (in place)
__device__ __align__(16) __half g_il [(size_t)MM*DD];  // ilin
__device__ __align__(16) __half g_zh [(size_t)MM*HH];  // gated-MLP intermediate
// fp16 transposed weights, packed arena (17M halfs)
#define WOFF_X  ((size_t)0)
#define WOFF_Y  ((size_t)1*1024*1024)   // follows X (dual Wx|Wy)
#define WOFF_A  ((size_t)2*1024*1024)
#define WOFF_I  ((size_t)3*1024*1024)   // follows A (dual Wa|Wi)
#define WOFF_O  ((size_t)4*1024*1024)
#define WOFF_GU ((size_t)5*1024*1024)   // Wg/Wu column-interleaved (8192 rows)
#define WOFF_D  ((size_t)13*1024*1024)
__device__ __align__(16) __half g_wh[(size_t)17*1024*1024];

// ---------------------------------------------------------------------------
// Math helpers
// ---------------------------------------------------------------------------
__device__ __forceinline__ float geluf(float x) {
    const float c = 0.7978845608028654f; // sqrt(2/pi)
    float x3 = x * x * x;
    float t  = tanhf(c * (x + 0.044715f * x3));
    return 0.5f * x * (1.0f + t);
}
__device__ __forceinline__ float sigmoidf(float x) {
    return 1.0f / (1.0f + expf(-x));
}
__device__ __forceinline__ float softplusf(float x) {
    return fmaxf(x, 0.0f) + log1pf(expf(-fabsf(x)));
}

// ---------------------------------------------------------------------------
// PTX helpers (baseline compute_103 features only)
// ---------------------------------------------------------------------------
__device__ __forceinline__ uint32_t smem_u32(const void* p) {
    uint32_t a;
    asm("{ .reg .u64 t; cvta.to.shared.u64 t, %1; cvt.u32.u64 %0, t; }" : "=r"(a) : "l"(p));
    return a;
}
__device__ __forceinline__ void cp_async16(uint32_t dst, const void* src) {
    asm volatile("cp.async.cg.shared.global [%0], [%1], 16;" :: "r"(dst), "l"(src) : "memory");
}
__device__ __forceinline__ void ldm_x4(uint32_t& r0, uint32_t& r1, uint32_t& r2, uint32_t& r3,
                                       uint32_t addr) {
    asm volatile("ldmatrix.sync.aligned.m8n8.x4.shared.b16 {%0,%1,%2,%3}, [%4];"
                 : "=r"(r0), "=r"(r1), "=r"(r2), "=r"(r3) : "r"(addr));
}
__device__ __forceinline__ void mma16816(float* c, const uint32_t* a, const uint32_t* b) {
    asm volatile(
        "mma.sync.aligned.m16n8k16.row.col.f32.f16.f16.f32 "
        "{%0,%1,%2,%3}, {%4,%5,%6,%7}, {%8,%9}, {%0,%1,%2,%3};"
        : "+f"(c[0]), "+f"(c[1]), "+f"(c[2]), "+f"(c[3])
        : "r"(a[0]), "r"(a[1]), "r"(a[2]), "r"(a[3]), "r"(b[0]), "r"(b[1]));
}

// ---------------------------------------------------------------------------
// Single-product fp16 HMMA GEMM: C = act(A @ W^T) (+R).
// CTA 128x128, BK=64, 8 warps (2Mx4N), 3-stage cp.async, 2 CTAs/SM.
// OUT16: outputs written as fp16 (H1o/H2o). GATED: gelu(g)*v -> ZH fp16.
// ---------------------------------------------------------------------------
#define GSTRIDE 144u
#define TILE_B  18432u
#define STG_B   36864u
#define GEMM_SMEM (3*STG_B)

template<int ACT1, int ACT2, bool RES, bool GATED, bool OUT16>
__global__ void __launch_bounds__(256, 2)
hmma_gemm(const __half* __restrict__ Ah, const __half* __restrict__ Bh,
          const float* __restrict__ R, float* __restrict__ C1, float* __restrict__ C2,
          __half* __restrict__ H1o, __half* __restrict__ H2o,
          __half* __restrict__ ZH,
          int NH, int K)
{
    extern __shared__ char smem[];
    const uint32_t sb = smem_u32(smem);
    const int tid  = threadIdx.x;
    const int wid  = tid >> 5;
    const int lane = tid & 31;
    const int bm = blockIdx.y * 128;
    const int bn = blockIdx.x * 128;
    const int wr = wid >> 2;          // warp row (64 rows)
    const int wc = wid & 3;           // warp col (32 cols)

    const int nch = K >> 6;           // BK = 64

    auto fill = [&](int ch) {
        const int k0 = ch << 6;
        const uint32_t st = sb + (uint32_t)(ch % 3) * STG_B;
        #pragma unroll
        for (int r = 0; r < 4; r++) {
            const int c = tid + (r << 8);          // 0..1023
            const int row = c >> 3, kc = c & 7;
            const uint32_t dst = (uint32_t)row * GSTRIDE + (uint32_t)(kc << 4);
            cp_async16(st + dst,          Ah + (size_t)(bm + row) * K + k0 + (kc << 3));
            cp_async16(st + TILE_B + dst, Bh + (size_t)(bn + row) * K + k0 + (kc << 3));
        }
        asm volatile("cp.async.commit_group;" ::: "memory");
    };

    float acc[4][4][4];
    #pragma unroll
    for (int i = 0; i < 4; i++)
        #pragma unroll
        for (int j = 0; j < 4; j++)
            #pragma unroll
            for (int q = 0; q < 4; q++) acc[i][j][q] = 0.0f;

    fill(0);
    if (nch > 1) fill(1);
    if (nch > 2) fill(2);

    const int l16  = lane & 15;
    const int ahi  = (lane >> 4) << 4;
    const int brow = ((lane >> 4) << 3) + (lane & 7);
    const int bhi  = ((lane >> 3) & 1) << 4;

    for (int i = 0; i < nch; i++) {
        if      (i + 2 < nch) asm volatile("cp.async.wait_group 2;" ::: "memory");
        else if (i + 1 < nch) asm volatile("cp.async.wait_group 1;" ::: "memory");
        else                  asm volatile("cp.async.wait_group 0;" ::: "memory");
        __syncthreads();

        const uint32_t st  = sb + (uint32_t)(i % 3) * STG_B;
        const uint32_t sAh = st;
        const uint32_t sBh = st + TILE_B;

        #pragma unroll
        for (int ks = 0; ks < 4; ks++) {
            uint32_t ah[4][4];
            #pragma unroll
            for (int mt = 0; mt < 4; mt++) {
                const uint32_t ra = (uint32_t)(wr*64 + mt*16 + l16) * GSTRIDE
                                  + (uint32_t)(ks*32 + ahi);
                ldm_x4(ah[mt][0], ah[mt][1], ah[mt][2], ah[mt][3], sAh + ra);
            }
            #pragma unroll
            for (int ntp = 0; ntp < 2; ntp++) {
                uint32_t bq[4];
                const uint32_t rb = (uint32_t)(wc*32 + ntp*16 + brow) * GSTRIDE
                                  + (uint32_t)(ks*32 + bhi);
                ldm_x4(bq[0], bq[1], bq[2], bq[3], sBh + rb);
                #pragma unroll
                for (int mt = 0; mt < 4; mt++) {
                    mma16816(acc[mt][2*ntp],   ah[mt], bq);
                    mma16816(acc[mt][2*ntp+1], ah[mt], bq + 2);
                }
            }
        }
        __syncthreads();
        if (i + 3 < nch) fill(i + 3);
    }

    const int erow = lane >> 2;
    const int ecol = (lane & 3) << 1;

    if constexpr (GATED) {
        #pragma unroll
        for (int mt = 0; mt < 4; mt++) {
            #pragma unroll
            for (int nt = 0; nt < 4; nt++) {
                const int r0 = bm + wr*64 + mt*16 + erow;
                const int j  = ((bn + wc*32 + nt*8 + ecol) >> 1);
                const float f0 = geluf(acc[mt][nt][0]) * acc[mt][nt][1];
                const float f1 = geluf(acc[mt][nt][2]) * acc[mt][nt][3];
                ZH[(size_t)r0     * NH + j] = __float2half_rn(f0);
                ZH[(size_t)(r0+8) * NH + j] = __float2half_rn(f1);
            }
        }
        return;
    }

    if constexpr (OUT16) {
        __half* Hout;
        int act, cb;
        if (bn < NH) { Hout = H1o; act = ACT1; cb = bn; }
        else         { Hout = H2o; act = ACT2; cb = bn - NH; }
        #pragma unroll
        for (int mt = 0; mt < 4; mt++) {
            #pragma unroll
            for (int nt = 0; nt < 4; nt++) {
                const int r0 = bm + wr*64 + mt*16 + erow;
                const int cc = cb + wc*32 + nt*8 + ecol;
                float v0 = acc[mt][nt][0], v1 = acc[mt][nt][1];
                float v2 = acc[mt][nt][2], v3 = acc[mt][nt][3];
                if (act == 1) { v0 = geluf(v0); v1 = geluf(v1); v2 = geluf(v2); v3 = geluf(v3); }
                *(__half2*)(Hout + (size_t)r0     * NH + cc) =
                    __floats2half2_rn(v0, v1);
                *(__half2*)(Hout + (size_t)(r0+8) * NH + cc) =
                    __floats2half2_rn(v2, v3);
            }
        }
        return;
    }

    // fp32 epilogue (with residual)
    float* Cout;
    int act, cb;
    if (bn < NH) { Cout = C1; act = ACT1; cb = bn; }
    else         { Cout = C2; act = ACT2; cb = bn - NH; }

    #pragma unroll
    for (int mt = 0; mt < 4; mt++) {
        #pragma unroll
        for (int nt = 0; nt < 4; nt++) {
            const int r0 = bm + wr*64 + mt*16 + erow;
            const int cc = cb + wc*32 + nt*8 + ecol;
            float v0 = acc[mt][nt][0], v1 = acc[mt][nt][1];
            float v2 = acc[mt][nt][2], v3 = acc[mt][nt][3];
            if (act == 1) { v0 = geluf(v0); v1 = geluf(v1); v2 = geluf(v2); v3 = geluf(v3); }
            if (RES) {
                const float2 ra = *(const float2*)(R + (size_t)r0 * NH + cc);
                const float2 rb = *(const float2*)(R + (size_t)(r0+8) * NH + cc);
                v0 += ra.x; v1 += ra.y; v2 += rb.x; v3 += rb.y;
            }
            *(float2*)(Cout + (size_t)r0     * NH + cc) = make_float2(v0, v1);
            *(float2*)(Cout + (size_t)(r0+8) * NH + cc) = make_float2(v2, v3);
        }
    }
}

// ---------------------------------------------------------------------------
// Weight transpose to fp16: W [Kd, Nd] fp32 -> Th [(n*rstride+roff), Kd] fp16
// ---------------------------------------------------------------------------
__global__ void tsplit_kernel(const float* __restrict__ W,
                              __half* __restrict__ Th,
                              int Kd, int Nd, int rstride, int roff)
{
    __shared__ float tile[32][33];
    const int n0 = blockIdx.x * 32, k0 = blockIdx.y * 32;
    const int tx = threadIdx.x, ty = threadIdx.y;   // (32, 8)
    #pragma unroll
    for (int i = 0; i < 32; i += 8)
        tile[ty + i][tx] = W[(size_t)(k0 + ty + i) * Nd + n0 + tx];
    __syncthreads();
    #pragma unroll
    for (int i = 0; i < 32; i += 8) {
        const float v = tile[tx][ty + i];
        const size_t o = ((size_t)(n0 + ty + i) * rstride + roff) * Kd + k0 + tx;
        Th[o] = __float2half_rn(v);
    }
}

// ---------------------------------------------------------------------------
// RMSNorm with fp16 output
// ---------------------------------------------------------------------------
__global__ void rmsnorm_f16_kernel(const float* __restrict__ x,
                                   const float* __restrict__ w,
                                   __half* __restrict__ oh, int D)
{
    const int row = blockIdx.x;
    const float* xr = x + (size_t)row * D;
    float ss = 0.0f;
    for (int i = threadIdx.x; i < D; i += blockDim.x) {
        float v = xr[i];
        ss = fmaf(v, v, ss);
    }
    #pragma unroll
    for (int off = 16; off > 0; off >>= 1)
        ss += __shfl_xor_sync(0xffffffff, ss, off);
    __shared__ float red[32];
    const int lane = threadIdx.x & 31, wid = threadIdx.x >> 5;
    if (lane == 0) red[wid] = ss;
    __syncthreads();
    const int nw = blockDim.x >> 5;
    if (wid == 0) {
        float s = (lane < nw) ? red[lane] : 0.0f;
        #pragma unroll
        for (int off = 16; off > 0; off >>= 1)
            s += __shfl_xor_sync(0xffffffff, s, off);
        if (lane == 0) red[0] = s;
    }
    __syncthreads();
    const float inv = rsqrtf(red[0] / (float)D + 1e-6f);
    for (int i = threadIdx.x; i < D; i += blockDim.x)
        oh[(size_t)row * D + i] = __float2half_rn(xr[i] * inv * w[i]);
}

// ---------------------------------------------------------------------------
// Causal depthwise conv (K=4): fp16 in, fp32 compute, fp16 out
// ---------------------------------------------------------------------------
__global__ void conv_f16_kernel(const __half* __restrict__ in,
                                const float* __restrict__ cw,
                                const float* __restrict__ cb,
                                __half* __restrict__ oh)
{
    const size_t idx = (size_t)blockIdx.x * blockDim.x + threadIdx.x;
    if (idx >= (size_t)MM * DD) return;
    const int d = (int)(idx % DD);
    const int s = (int)((idx / DD) % SS);
    float acc = cb[d];
    #pragma unroll
    for (int k = 0; k < 4; k++) {
        if (s + k - 3 >= 0)
            acc = fmaf(cw[k * DD + d],
                       __half2float(in[idx - (size_t)(3 - k) * DD]), acc);
    }
    oh[idx] = __float2half_rn(acc);
}

// ---------------------------------------------------------------------------
// Scan pass 1: fused gates + chunk-local scan (fp16 in, a->fp16 in-place,
// local h -> fp32).
// ---------------------------------------------------------------------------
__global__ void scan1_kernel(__half* __restrict__ rlin_a,
                             const __half* __restrict__ ilin,
                             const __half* __restrict__ xc,
                             const float* __restrict__ lam,
                             float* __restrict__ lh,
                             float* __restrict__ sa,
                             float* __restrict__ sh)
{
    const int idx = blockIdx.x * blockDim.x + threadIdx.x;
    if (idx >= BB * NC * DD) return;
    const int d     = idx % DD;
    const int chunk = (idx / DD) % NC;
    const int batch = idx / (DD * NC);
    const float cfac = -8.0f * softplusf(lam[d]);
    const size_t base = ((size_t)batch * SS + (size_t)chunk * CL) * DD + d;

    float p = 1.0f, h = 0.0f;
    for (int t = 0; t < CL; t++) {
        const size_t off = base + (size_t)t * DD;
        const float r  = sigmoidf(__half2float(rlin_a[off]));
        const float ii = sigmoidf(__half2float(ilin[off]));
        const float a  = expf(cfac * r);
        const float b  = sqrtf(fmaxf(1.0f - a * a, 1e-12f)) * ii * __half2float(xc[off]);
        h = fmaf(a, h, b);
        p *= a;
        rlin_a[off] = __float2half_rn(a);
        lh[off] = h;
    }
    sa[idx] = p;
    sh[idx] = h;
}

// ---------------------------------------------------------------------------
// Scan pass 2: combine chunk carries.
// ---------------------------------------------------------------------------
__global__ void scan2_kernel(const float* __restrict__ sa, float* __restrict__ sh)
{
    const int idx = blockIdx.x * blockDim.x + threadIdx.x;
    if (idx >= BB * DD) return;
    const int d = idx % DD, batch = idx / DD;
    float H = 0.0f;
    for (int c = 0; c < NC; c++) {
        const size_t o = ((size_t)batch * NC + c) * DD + d;
        H = fmaf(sa[o], H, sh[o]);
        sh[o] = H;
    }
}

// ---------------------------------------------------------------------------
// Scan pass 3: apply carries, fuse z = h * yb, fp16 out.
// ---------------------------------------------------------------------------
__global__ void scan3_kernel(const __half* __restrict__ aArr,
                             const float* __restrict__ lhArr,
                             const float* __restrict__ sh,
                             const __half* __restrict__ yb,
                             __half* __restrict__ zh)
{
    const int idx = blockIdx.x * blockDim.x + threadIdx.x;
    if (idx >= BB * NC * DD) return;
    const int d     = idx % DD;
    const int chunk = (idx / DD) % NC;
    const int batch = idx / (DD * NC);
    const float carry = (chunk == 0)
        ? 0.0f : sh[((size_t)batch * NC + chunk - 1) * DD + d];
    const size_t base = ((size_t)batch * SS + (size_t)chunk * CL) * DD + d;

    float p = 1.0f;
    for (int t = 0; t < CL; t++) {
        const size_t off = base + (size_t)t * DD;
        p *= __half2float(aArr[off]);
        const float h = fmaf(p, carry, lhArr[off]);
        zh[off] = __float2half_rn(h * __half2float(yb[off]));
    }
}

// ---------------------------------------------------------------------------
// Launch (gemXY is the 5th kernel launch: with the harness's d_out poison
// memset counted as launch 0, ncu -s 5 -c 1 should capture it)
// ---------------------------------------------------------------------------
extern "C" void kernel_launch(void* const* d_in, const int* in_sizes, int n_in,
                              void* d_out, int out_size)
{
    const float* x       = (const float*)d_in[0];
    const float* norm1_w = (const float*)d_in[1];
    const float* Wx      = (const float*)d_in[2];
    const float* Wy      = (const float*)d_in[3];
    const float* conv_w  = (const float*)d_in[4];
    const float* conv_b  = (const float*)d_in[5];
    const float* Wi      = (const float*)d_in[6];
    const float* Wa      = (const float*)d_in[7];
    const float* lam     = (const float*)d_in[8];
    const float* Wo      = (const float*)d_in[9];
    const float* norm2_w = (const float*)d_in[10];
    const float* Wg      = (const float*)d_in[11];
    const float* Wu      = (const float*)d_in[12];
    const float* Wd      = (const float*)d_in[13];
    float* out = (float*)d_out;

    float *lh, *h1, *sa, *sh;
    __half *ah, *xbh, *ybh, *rl, *il, *zh, *wh;
    cudaGetSymbolAddress((void**)&lh,  g_lh);
    cudaGetSymbolAddress((void**)&h1,  g_h1);
    cudaGetSymbolAddress((void**)&sa,  g_sa);
    cudaGetSymbolAddress((void**)&sh,  g_sh);
    cudaGetSymbolAddress((void**)&ah,  g_ah);
    cudaGetSymbolAddress((void**)&xbh, g_xbh);
    cudaGetSymbolAddress((void**)&ybh, g_ybh);
    cudaGetSymbolAddress((void**)&rl,  g_rl);
    cudaGetSymbolAddress((void**)&il,  g_il);
    cudaGetSymbolAddress((void**)&zh,  g_zh);
    cudaGetSymbolAddress((void**)&wh,  g_wh);

    cudaFuncSetAttribute(hmma_gemm<0,1,false,false,true>,  cudaFuncAttributeMaxDynamicSharedMemorySize, GEMM_SMEM);
    cudaFuncSetAttribute(hmma_gemm<0,0,false,false,true>,  cudaFuncAttributeMaxDynamicSharedMemorySize, GEMM_SMEM);
    cudaFuncSetAttribute(hmma_gemm<0,0,true,false,false>,  cudaFuncAttributeMaxDynamicSharedMemorySize, GEMM_SMEM);
    cudaFuncSetAttribute(hmma_gemm<0,0,false,true,false>,  cudaFuncAttributeMaxDynamicSharedMemorySize, GEMM_SMEM);

    const dim3 tsb(32, 8);
    const size_t nMD = (size_t)MM * DD;
    const int gMD = (int)((nMD + 255) / 256);
    const int gSC = (BB * NC * DD + 255) / 256;

    const dim3 gemXY(2048 / 128, MM / 128);   // dual Wx|Wy (fp16 out)
    const dim3 gemAI(2048 / 128, MM / 128);   // dual Wa|Wi (fp16 out)
    const dim3 gemGU(8192 / 128, MM / 128);   // interleaved Wg|Wu (gated)
    const dim3 gemO (1024 / 128, MM / 128);   // Wo (K=1024, fp32+res)
    const dim3 gemDn(1024 / 128, MM / 128);   // Wd (K=4096, fp32+res)

    // #1..#4: tsplit X, tsplit Y, rmsnorm1, tsplit A
    tsplit_kernel<<<dim3(DD/32, DD/32), tsb>>>(Wx, wh + WOFF_X, DD, DD, 1, 0);
    tsplit_kernel<<<dim3(DD/32, DD/32), tsb>>>(Wy, wh + WOFF_Y, DD, DD, 1, 0);
    rmsnorm_f16_kernel<<<MM, 256>>>(x, norm1_w, ah, DD);
    tsplit_kernel<<<dim3(DD/32, DD/32), tsb>>>(Wa, wh + WOFF_A, DD, DD, 1, 0);
    // #5: xb = t @ Wx ; yb = gelu(t @ Wy)  [dual, fp16 out]  <-- ncu target
    hmma_gemm<0,1,false,false,true><<<gemXY, 256, GEMM_SMEM>>>(ah, wh + WOFF_X,
        nullptr, nullptr, nullptr, xbh, ybh, nullptr, DD, DD);
    tsplit_kernel<<<dim3(DD/32, DD/32), tsb>>>(Wi, wh + WOFF_I, DD, DD, 1, 0);
    // conv -> ah (fp16)
    conv_f16_kernel<<<gMD, 256>>>(xbh, conv_w, conv_b, ah);
    tsplit_kernel<<<dim3(DD/32, DD/32), tsb>>>(Wo, wh + WOFF_O, DD, DD, 1, 0);
    // rlin -> rl ; ilin -> il  [dual, fp16 out]
    hmma_gemm<0,0,false,false,true><<<gemAI, 256, GEMM_SMEM>>>(ah, wh + WOFF_A,
        nullptr, nullptr, nullptr, rl, il, nullptr, DD, DD);
    // gates + chunked scan + z = h*yb -> ah (fp16)
    scan1_kernel<<<gSC, 256>>>(rl, il, ah, lam, lh, sa, sh);
    scan2_kernel<<<(BB * DD + 255) / 256, 256>>>(sa, sh);
    scan3_kernel<<<gSC, 256>>>(rl, lh, sh, ybh, ah);
    // h1 = x + z @ Wo
    hmma_gemm<0,0,true,false,false><<<gemO, 256, GEMM_SMEM>>>(ah, wh + WOFF_O,
        x, h1, h1, nullptr, nullptr, nullptr, DD, DD);
    // u = rmsnorm(h1) -> ah
    rmsnorm_f16_kernel<<<MM, 256>>>(h1, norm2_w, ah, DD);
    tsplit_kernel<<<dim3(HH/32, DD/32), tsb>>>(Wg, wh + WOFF_GU, DD, HH, 2, 0);
    tsplit_kernel<<<dim3(HH/32, DD/32), tsb>>>(Wu, wh + WOFF_GU, DD, HH, 2, 1);
    // ff = gelu(u @ Wg) * (u @ Wu) -> zh  [gated]
    hmma_gemm<0,0,false,true,false><<<gemGU, 256, GEMM_SMEM>>>(ah, wh + WOFF_GU,
        nullptr, nullptr, nullptr, nullptr, nullptr, zh, HH, DD);
    tsplit_kernel<<<dim3(DD/32, HH/32), tsb>>>(Wd, wh + WOFF_D, HH, DD, 1, 0);
    // out = h1 + ff @ Wd
    hmma_gemm<0,0,true,false,false><<<gemDn, 256, GEMM_SMEM>>>(zh, wh + WOFF_D,
        h1, out, out, nullptr, nullptr, nullptr, DD, HH);
}

// round 10
// speedup vs baseline: 7.2077x; 1.0564x over previous
#include <cuda_runtime.h>
#include <cuda_fp16.h>
#include <math.h>
#include <stdint.h>

// Problem dims (fixed by the dataset)
#define BB 4
#define SS 2048
#define DD 1024
#define HH 4096
#define MM (BB*SS)          // 8192 rows
#define NC 32               // scan chunks
#define CL (SS/NC)          // 64 steps per chunk
#define DD2 (DD/2)

// ---------------------------------------------------------------------------
// Scratch (static device globals; no allocation in kernel_launch)
// ---------------------------------------------------------------------------
__device__ __align__(16) float g_h1 [(size_t)MM*DD];    // h1 trunk (fp32)
__device__ __align__(16) float g_sa [(size_t)BB*NC*DD]; // chunk a-products
__device__ __align__(16) float g_sh [(size_t)BB*NC*DD]; // chunk h-carries

// fp16 streams
__device__ __align__(16) __half g_ah [(size_t)MM*DD];  // rmsnorm out / conv out / z
__device__ __align__(16) __half g_xbh[(size_t)MM*DD];  // xb (gemXY C1)
__device__ __align__(16) __half g_ybh[(size_t)MM*DD];  // yb (gemXY C2, gelu)
__device__ __align__(16) __half g_rl [(size_t)MM*DD];  // rlin -> a (in place)
__device__ __align__(16) __half g_il [(size_t)MM*DD];  // ilin
__device__ __align__(16) __half g_lh [(size_t)MM*DD];  // scan local h (fp16)
__device__ __align__(16) __half g_zh [(size_t)MM*HH];  // gated-MLP intermediate
// fp16 transposed weights, packed arena (17M halfs)
#define WOFF_X  ((size_t)0)
#define WOFF_Y  ((size_t)1*1024*1024)   // follows X (dual Wx|Wy)
#define WOFF_A  ((size_t)2*1024*1024)
#define WOFF_I  ((size_t)3*1024*1024)   // follows A (dual Wa|Wi)
#define WOFF_O  ((size_t)4*1024*1024)
#define WOFF_GU ((size_t)5*1024*1024)   // Wg/Wu column-interleaved (8192 rows)
#define WOFF_D  ((size_t)13*1024*1024)
__device__ __align__(16) __half g_wh[(size_t)17*1024*1024];

// ---------------------------------------------------------------------------
// Math helpers
// ---------------------------------------------------------------------------
__device__ __forceinline__ float geluf(float x) {
    const float c = 0.7978845608028654f; // sqrt(2/pi)
    float x3 = x * x * x;
    float t  = tanhf(c * (x + 0.044715f * x3));
    return 0.5f * x * (1.0f + t);
}
__device__ __forceinline__ float sigmoidf(float x) {
    return 1.0f / (1.0f + expf(-x));
}
__device__ __forceinline__ float softplusf(float x) {
    return fmaxf(x, 0.0f) + log1pf(expf(-fabsf(x)));
}

// ---------------------------------------------------------------------------
// PTX helpers (baseline compute_103 features only)
// ---------------------------------------------------------------------------
__device__ __forceinline__ uint32_t smem_u32(const void* p) {
    uint32_t a;
    asm("{ .reg .u64 t; cvta.to.shared.u64 t, %1; cvt.u32.u64 %0, t; }" : "=r"(a) : "l"(p));
    return a;
}
__device__ __forceinline__ void cp_async16(uint32_t dst, const void* src) {
    asm volatile("cp.async.cg.shared.global [%0], [%1], 16;" :: "r"(dst), "l"(src) : "memory");
}
__device__ __forceinline__ void ldm_x4(uint32_t& r0, uint32_t& r1, uint32_t& r2, uint32_t& r3,
                                       uint32_t addr) {
    asm volatile("ldmatrix.sync.aligned.m8n8.x4.shared.b16 {%0,%1,%2,%3}, [%4];"
                 : "=r"(r0), "=r"(r1), "=r"(r2), "=r"(r3) : "r"(addr));
}
__device__ __forceinline__ void mma16816(float* c, const uint32_t* a, const uint32_t* b) {
    asm volatile(
        "mma.sync.aligned.m16n8k16.row.col.f32.f16.f16.f32 "
        "{%0,%1,%2,%3}, {%4,%5,%6,%7}, {%8,%9}, {%0,%1,%2,%3};"
        : "+f"(c[0]), "+f"(c[1]), "+f"(c[2]), "+f"(c[3])
        : "r"(a[0]), "r"(a[1]), "r"(a[2]), "r"(a[3]), "r"(b[0]), "r"(b[1]));
}

// ---------------------------------------------------------------------------
// Single-product fp16 HMMA GEMM: C = act(A @ W^T) (+R).
// CTA 128x128, BK=64, 8 warps (2Mx4N), 3-stage cp.async, 2 CTAs/SM.
// OUT16: outputs written as fp16 (H1o/H2o). GATED: gelu(g)*v -> ZH fp16.
// ---------------------------------------------------------------------------
#define GSTRIDE 144u
#define TILE_B  18432u
#define STG_B   36864u
#define GEMM_SMEM (3*STG_B)

template<int ACT1, int ACT2, bool RES, bool GATED, bool OUT16>
__global__ void __launch_bounds__(256, 2)
hmma_gemm(const __half* __restrict__ Ah, const __half* __restrict__ Bh,
          const float* __restrict__ R, float* __restrict__ C1, float* __restrict__ C2,
          __half* __restrict__ H1o, __half* __restrict__ H2o,
          __half* __restrict__ ZH,
          int NH, int K)
{
    extern __shared__ char smem[];
    const uint32_t sb = smem_u32(smem);
    const int tid  = threadIdx.x;
    const int wid  = tid >> 5;
    const int lane = tid & 31;
    const int bm = blockIdx.y * 128;
    const int bn = blockIdx.x * 128;
    const int wr = wid >> 2;          // warp row (64 rows)
    const int wc = wid & 3;           // warp col (32 cols)

    const int nch = K >> 6;           // BK = 64

    auto fill = [&](int ch) {
        const int k0 = ch << 6;
        const uint32_t st = sb + (uint32_t)(ch % 3) * STG_B;
        #pragma unroll
        for (int r = 0; r < 4; r++) {
            const int c = tid + (r << 8);          // 0..1023
            const int row = c >> 3, kc = c & 7;
            const uint32_t dst = (uint32_t)row * GSTRIDE + (uint32_t)(kc << 4);
            cp_async16(st + dst,          Ah + (size_t)(bm + row) * K + k0 + (kc << 3));
            cp_async16(st + TILE_B + dst, Bh + (size_t)(bn + row) * K + k0 + (kc << 3));
        }
        asm volatile("cp.async.commit_group;" ::: "memory");
    };

    float acc[4][4][4];
    #pragma unroll
    for (int i = 0; i < 4; i++)
        #pragma unroll
        for (int j = 0; j < 4; j++)
            #pragma unroll
            for (int q = 0; q < 4; q++) acc[i][j][q] = 0.0f;

    fill(0);
    if (nch > 1) fill(1);
    if (nch > 2) fill(2);

    const int l16  = lane & 15;
    const int ahi  = (lane >> 4) << 4;
    const int brow = ((lane >> 4) << 3) + (lane & 7);
    const int bhi  = ((lane >> 3) & 1) << 4;

    for (int i = 0; i < nch; i++) {
        if      (i + 2 < nch) asm volatile("cp.async.wait_group 2;" ::: "memory");
        else if (i + 1 < nch) asm volatile("cp.async.wait_group 1;" ::: "memory");
        else                  asm volatile("cp.async.wait_group 0;" ::: "memory");
        __syncthreads();

        const uint32_t st  = sb + (uint32_t)(i % 3) * STG_B;
        const uint32_t sAh = st;
        const uint32_t sBh = st + TILE_B;

        #pragma unroll
        for (int ks = 0; ks < 4; ks++) {
            uint32_t ah[4][4];
            #pragma unroll
            for (int mt = 0; mt < 4; mt++) {
                const uint32_t ra = (uint32_t)(wr*64 + mt*16 + l16) * GSTRIDE
                                  + (uint32_t)(ks*32 + ahi);
                ldm_x4(ah[mt][0], ah[mt][1], ah[mt][2], ah[mt][3], sAh + ra);
            }
            #pragma unroll
            for (int ntp = 0; ntp < 2; ntp++) {
                uint32_t bq[4];
                const uint32_t rb = (uint32_t)(wc*32 + ntp*16 + brow) * GSTRIDE
                                  + (uint32_t)(ks*32 + bhi);
                ldm_x4(bq[0], bq[1], bq[2], bq[3], sBh + rb);
                #pragma unroll
                for (int mt = 0; mt < 4; mt++) {
                    mma16816(acc[mt][2*ntp],   ah[mt], bq);
                    mma16816(acc[mt][2*ntp+1], ah[mt], bq + 2);
                }
            }
        }
        __syncthreads();
        if (i + 3 < nch) fill(i + 3);
    }

    const int erow = lane >> 2;
    const int ecol = (lane & 3) << 1;

    if constexpr (GATED) {
        #pragma unroll
        for (int mt = 0; mt < 4; mt++) {
            #pragma unroll
            for (int nt = 0; nt < 4; nt++) {
                const int r0 = bm + wr*64 + mt*16 + erow;
                const int j  = ((bn + wc*32 + nt*8 + ecol) >> 1);
                const float f0 = geluf(acc[mt][nt][0]) * acc[mt][nt][1];
                const float f1 = geluf(acc[mt][nt][2]) * acc[mt][nt][3];
                ZH[(size_t)r0     * NH + j] = __float2half_rn(f0);
                ZH[(size_t)(r0+8) * NH + j] = __float2half_rn(f1);
            }
        }
        return;
    }

    if constexpr (OUT16) {
        __half* Hout;
        int act, cb;
        if (bn < NH) { Hout = H1o; act = ACT1; cb = bn; }
        else         { Hout = H2o; act = ACT2; cb = bn - NH; }
        #pragma unroll
        for (int mt = 0; mt < 4; mt++) {
            #pragma unroll
            for (int nt = 0; nt < 4; nt++) {
                const int r0 = bm + wr*64 + mt*16 + erow;
                const int cc = cb + wc*32 + nt*8 + ecol;
                float v0 = acc[mt][nt][0], v1 = acc[mt][nt][1];
                float v2 = acc[mt][nt][2], v3 = acc[mt][nt][3];
                if (act == 1) { v0 = geluf(v0); v1 = geluf(v1); v2 = geluf(v2); v3 = geluf(v3); }
                *(__half2*)(Hout + (size_t)r0     * NH + cc) =
                    __floats2half2_rn(v0, v1);
                *(__half2*)(Hout + (size_t)(r0+8) * NH + cc) =
                    __floats2half2_rn(v2, v3);
            }
        }
        return;
    }

    // fp32 epilogue (with residual)
    float* Cout;
    int act, cb;
    if (bn < NH) { Cout = C1; act = ACT1; cb = bn; }
    else         { Cout = C2; act = ACT2; cb = bn - NH; }

    #pragma unroll
    for (int mt = 0; mt < 4; mt++) {
        #pragma unroll
        for (int nt = 0; nt < 4; nt++) {
            const int r0 = bm + wr*64 + mt*16 + erow;
            const int cc = cb + wc*32 + nt*8 + ecol;
            float v0 = acc[mt][nt][0], v1 = acc[mt][nt][1];
            float v2 = acc[mt][nt][2], v3 = acc[mt][nt][3];
            if (act == 1) { v0 = geluf(v0); v1 = geluf(v1); v2 = geluf(v2); v3 = geluf(v3); }
            if (RES) {
                const float2 ra = *(const float2*)(R + (size_t)r0 * NH + cc);
                const float2 rb = *(const float2*)(R + (size_t)(r0+8) * NH + cc);
                v0 += ra.x; v1 += ra.y; v2 += rb.x; v3 += rb.y;
            }
            *(float2*)(Cout + (size_t)r0     * NH + cc) = make_float2(v0, v1);
            *(float2*)(Cout + (size_t)(r0+8) * NH + cc) = make_float2(v2, v3);
        }
    }
}

// ---------------------------------------------------------------------------
// Weight transpose to fp16: W [Kd, Nd] fp32 -> Th [(n*rstride+roff), Kd] fp16
// ---------------------------------------------------------------------------
__device__ __forceinline__ void tsplit_body(const float* __restrict__ W,
                                            __half* __restrict__ Th,
                                            int Kd, int Nd, int rstride, int roff,
                                            int bx, int by)
{
    __shared__ float tile[32][33];
    const int n0 = bx * 32, k0 = by * 32;
    const int tx = threadIdx.x, ty = threadIdx.y;   // (32, 8)
    #pragma unroll
    for (int i = 0; i < 32; i += 8)
        tile[ty + i][tx] = W[(size_t)(k0 + ty + i) * Nd + n0 + tx];
    __syncthreads();
    #pragma unroll
    for (int i = 0; i < 32; i += 8) {
        const float v = tile[tx][ty + i];
        const size_t o = ((size_t)(n0 + ty + i) * rstride + roff) * Kd + k0 + tx;
        Th[o] = __float2half_rn(v);
    }
}

__global__ void tsplit_kernel(const float* __restrict__ W,
                              __half* __restrict__ Th,
                              int Kd, int Nd, int rstride, int roff)
{
    tsplit_body(W, Th, Kd, Nd, rstride, roff, blockIdx.x, blockIdx.y);
}

// Batched transpose of the five square DxD weights (z selects the weight).
__global__ void tsplit5_kernel(const float* __restrict__ W0, const float* __restrict__ W1,
                               const float* __restrict__ W2, const float* __restrict__ W3,
                               const float* __restrict__ W4, __half* __restrict__ ThBase)
{
    const float* W;
    __half* Th;
    switch (blockIdx.z) {
        case 0:  W = W0; Th = ThBase + WOFF_X; break;
        case 1:  W = W1; Th = ThBase + WOFF_Y; break;
        case 2:  W = W2; Th = ThBase + WOFF_A; break;
        case 3:  W = W3; Th = ThBase + WOFF_I; break;
        default: W = W4; Th = ThBase + WOFF_O; break;
    }
    tsplit_body(W, Th, DD, DD, 1, 0, blockIdx.x, blockIdx.y);
}

// ---------------------------------------------------------------------------
// RMSNorm with fp16 output (float2 / half2 vectorized; D=1024, 256 threads)
// ---------------------------------------------------------------------------
__global__ void rmsnorm_f16_kernel(const float* __restrict__ x,
                                   const float* __restrict__ w,
                                   __half* __restrict__ oh)
{
    const int row = blockIdx.x;
    const float2* xr = (const float2*)(x + (size_t)row * DD);
    const float2* w2 = (const float2*)w;
    float ss = 0.0f;
    float2 v[2];
    #pragma unroll
    for (int r = 0; r < 2; r++) {
        v[r] = xr[threadIdx.x + r * 256];
        ss = fmaf(v[r].x, v[r].x, fmaf(v[r].y, v[r].y, ss));
    }
    #pragma unroll
    for (int off = 16; off > 0; off >>= 1)
        ss += __shfl_xor_sync(0xffffffff, ss, off);
    __shared__ float red[8];
    const int lane = threadIdx.x & 31, wid = threadIdx.x >> 5;
    if (lane == 0) red[wid] = ss;
    __syncthreads();
    if (wid == 0) {
        float s = (lane < 8) ? red[lane] : 0.0f;
        #pragma unroll
        for (int off = 4; off > 0; off >>= 1)
            s += __shfl_xor_sync(0xffffffff, s, off);
        if (lane == 0) red[0] = s;
    }
    __syncthreads();
    const float inv = rsqrtf(red[0] / (float)DD + 1e-6f);
    __half2* o2 = (__half2*)(oh + (size_t)row * DD);
    #pragma unroll
    for (int r = 0; r < 2; r++) {
        const float2 ww = w2[threadIdx.x + r * 256];
        o2[threadIdx.x + r * 256] =
            __floats2half2_rn(v[r].x * inv * ww.x, v[r].y * inv * ww.y);
    }
}

// ---------------------------------------------------------------------------
// Causal depthwise conv (K=4), half2 vectorized (2 channels/thread)
// ---------------------------------------------------------------------------
__global__ void conv_f16_kernel(const __half2* __restrict__ in,
                                const float* __restrict__ cw,
                                const float* __restrict__ cb,
                                __half2* __restrict__ oh)
{
    const size_t idx = (size_t)blockIdx.x * blockDim.x + threadIdx.x;
    if (idx >= (size_t)MM * DD2) return;
    const int d2 = (int)(idx % DD2);
    const int s  = (int)((idx / DD2) % SS);
    float a0 = cb[2*d2], a1 = cb[2*d2 + 1];
    #pragma unroll
    for (int k = 0; k < 4; k++) {
        if (s + k - 3 >= 0) {
            const float2 v = __half22float2(in[idx - (size_t)(3 - k) * DD2]);
            a0 = fmaf(cw[k * DD + 2*d2],     v.x, a0);
            a1 = fmaf(cw[k * DD + 2*d2 + 1], v.y, a1);
        }
    }
    oh[idx] = __floats2half2_rn(a0, a1);
}

// ---------------------------------------------------------------------------
// Scan pass 1 (half2): gates + chunk-local scan; a->rl in place (fp16),
// local h -> lh (fp16), chunk products/carries -> sa/sh (float2).
// One thread per (batch, chunk, d-pair).
// ---------------------------------------------------------------------------
__global__ void scan1_kernel(__half2* __restrict__ rlin_a,
                             const __half2* __restrict__ ilin,
                             const __half2* __restrict__ xc,
                             const float* __restrict__ lam,
                             __half2* __restrict__ lh,
                             float2* __restrict__ sa,
                             float2* __restrict__ sh)
{
    const int idx = blockIdx.x * blockDim.x + threadIdx.x;
    if (idx >= BB * NC * DD2) return;
    const int d2    = idx % DD2;
    const int chunk = (idx / DD2) % NC;
    const int batch = idx / (DD2 * NC);
    const float cf0 = -8.0f * softplusf(lam[2*d2]);
    const float cf1 = -8.0f * softplusf(lam[2*d2 + 1]);
    const size_t base = ((size_t)batch * SS + (size_t)chunk * CL) * DD2 + d2;

    float p0 = 1.0f, p1 = 1.0f, h0 = 0.0f, h1 = 0.0f;
    for (int t = 0; t < CL; t++) {
        const size_t off = base + (size_t)t * DD2;
        const float2 rv = __half22float2(rlin_a[off]);
        const float2 iv = __half22float2(ilin[off]);
        const float2 xv = __half22float2(xc[off]);
        const float a0 = expf(cf0 * sigmoidf(rv.x));
        const float a1 = expf(cf1 * sigmoidf(rv.y));
        const float b0 = sqrtf(fmaxf(1.0f - a0*a0, 1e-12f)) * sigmoidf(iv.x) * xv.x;
        const float b1 = sqrtf(fmaxf(1.0f - a1*a1, 1e-12f)) * sigmoidf(iv.y) * xv.y;
        h0 = fmaf(a0, h0, b0);
        h1 = fmaf(a1, h1, b1);
        p0 *= a0; p1 *= a1;
        rlin_a[off] = __floats2half2_rn(a0, a1);
        lh[off]     = __floats2half2_rn(h0, h1);
    }
    sa[idx] = make_float2(p0, p1);
    sh[idx] = make_float2(h0, h1);
}

// ---------------------------------------------------------------------------
// Scan pass 2 (float2): combine chunk carries. One thread per (batch, d-pair).
// ---------------------------------------------------------------------------
__global__ void scan2_kernel(const float2* __restrict__ sa, float2* __restrict__ sh)
{
    const int idx = blockIdx.x * blockDim.x + threadIdx.x;
    if (idx >= BB * DD2) return;
    const int d2 = idx % DD2, batch = idx / DD2;
    float H0 = 0.0f, H1 = 0.0f;
    for (int c = 0; c < NC; c++) {
        const size_t o = ((size_t)batch * NC + c) * DD2 + d2;
        const float2 av = sa[o];
        const float2 hv = sh[o];
        H0 = fmaf(av.x, H0, hv.x);
        H1 = fmaf(av.y, H1, hv.y);
        sh[o] = make_float2(H0, H1);
    }
}

// ---------------------------------------------------------------------------
// Scan pass 3 (half2): apply carries, z = h * yb, fp16 out.
// ---------------------------------------------------------------------------
__global__ void scan3_kernel(const __half2* __restrict__ aArr,
                             const __half2* __restrict__ lhArr,
                             const float2* __restrict__ sh,
                             const __half2* __restrict__ yb,
                             __half2* __restrict__ zh)
{
    const int idx = blockIdx.x * blockDim.x + threadIdx.x;
    if (idx >= BB * NC * DD2) return;
    const int d2    = idx % DD2;
    const int chunk = (idx / DD2) % NC;
    const int batch = idx / (DD2 * NC);
    float c0 = 0.0f, c1 = 0.0f;
    if (chunk != 0) {
        const float2 cv = sh[((size_t)batch * NC + chunk - 1) * DD2 + d2];
        c0 = cv.x; c1 = cv.y;
    }
    const size_t base = ((size_t)batch * SS + (size_t)chunk * CL) * DD2 + d2;

    float p0 = 1.0f, p1 = 1.0f;
    for (int t = 0; t < CL; t++) {
        const size_t off = base + (size_t)t * DD2;
        const float2 av = __half22float2(aArr[off]);
        const float2 lv = __half22float2(lhArr[off]);
        const float2 yv = __half22float2(yb[off]);
        p0 *= av.x; p1 *= av.y;
        const float z0 = fmaf(p0, c0, lv.x) * yv.x;
        const float z1 = fmaf(p1, c1, lv.y) * yv.y;
        zh[off] = __floats2half2_rn(z0, z1);
    }
}

// ---------------------------------------------------------------------------
// Launch
// ---------------------------------------------------------------------------
extern "C" void kernel_launch(void* const* d_in, const int* in_sizes, int n_in,
                              void* d_out, int out_size)
{
    const float* x       = (const float*)d_in[0];
    const float* norm1_w = (const float*)d_in[1];
    const float* Wx      = (const float*)d_in[2];
    const float* Wy      = (const float*)d_in[3];
    const float* conv_w  = (const float*)d_in[4];
    const float* conv_b  = (const float*)d_in[5];
    const float* Wi      = (const float*)d_in[6];
    const float* Wa      = (const float*)d_in[7];
    const float* lam     = (const float*)d_in[8];
    const float* Wo      = (const float*)d_in[9];
    const float* norm2_w = (const float*)d_in[10];
    const float* Wg      = (const float*)d_in[11];
    const float* Wu      = (const float*)d_in[12];
    const float* Wd      = (const float*)d_in[13];
    float* out = (float*)d_out;

    float *h1, *sa, *sh;
    __half *ah, *xbh, *ybh, *rl, *il, *lh, *zh, *wh;
    cudaGetSymbolAddress((void**)&h1,  g_h1);
    cudaGetSymbolAddress((void**)&sa,  g_sa);
    cudaGetSymbolAddress((void**)&sh,  g_sh);
    cudaGetSymbolAddress((void**)&ah,  g_ah);
    cudaGetSymbolAddress((void**)&xbh, g_xbh);
    cudaGetSymbolAddress((void**)&ybh, g_ybh);
    cudaGetSymbolAddress((void**)&rl,  g_rl);
    cudaGetSymbolAddress((void**)&il,  g_il);
    cudaGetSymbolAddress((void**)&lh,  g_lh);
    cudaGetSymbolAddress((void**)&zh,  g_zh);
    cudaGetSymbolAddress((void**)&wh,  g_wh);

    cudaFuncSetAttribute(hmma_gemm<0,1,false,false,true>,  cudaFuncAttributeMaxDynamicSharedMemorySize, GEMM_SMEM);
    cudaFuncSetAttribute(hmma_gemm<0,0,false,false,true>,  cudaFuncAttributeMaxDynamicSharedMemorySize, GEMM_SMEM);
    cudaFuncSetAttribute(hmma_gemm<0,0,true,false,false>,  cudaFuncAttributeMaxDynamicSharedMemorySize, GEMM_SMEM);
    cudaFuncSetAttribute(hmma_gemm<0,0,false,true,false>,  cudaFuncAttributeMaxDynamicSharedMemorySize, GEMM_SMEM);

    const dim3 tsb(32, 8);
    const int gMD2 = (int)(((size_t)MM * DD2 + 255) / 256);
    const int gSC2 = (BB * NC * DD2 + 255) / 256;

    const dim3 gemXY(2048 / 128, MM / 128);   // dual Wx|Wy (fp16 out)
    const dim3 gemAI(2048 / 128, MM / 128);   // dual Wa|Wi (fp16 out)
    const dim3 gemGU(8192 / 128, MM / 128);   // interleaved Wg|Wu (gated)
    const dim3 gemO (1024 / 128, MM / 128);   // Wo (K=1024, fp32+res)
    const dim3 gemDn(1024 / 128, MM / 128);   // Wd (K=4096, fp32+res)

    // #1..#5: all weight prep + rmsnorm1 (front-loaded)
    tsplit5_kernel<<<dim3(32, 32, 5), tsb>>>(Wx, Wy, Wa, Wi, Wo, wh);
    tsplit_kernel<<<dim3(HH/32, DD/32), tsb>>>(Wg, wh + WOFF_GU, DD, HH, 2, 0);
    tsplit_kernel<<<dim3(HH/32, DD/32), tsb>>>(Wu, wh + WOFF_GU, DD, HH, 2, 1);
    tsplit_kernel<<<dim3(DD/32, HH/32), tsb>>>(Wd, wh + WOFF_D, HH, DD, 1, 0);
    rmsnorm_f16_kernel<<<MM, 256>>>(x, norm1_w, ah);
    // #6: xb = t @ Wx ; yb = gelu(t @ Wy)  [dual, fp16 out]
    hmma_gemm<0,1,false,false,true><<<gemXY, 256, GEMM_SMEM>>>(ah, wh + WOFF_X,
        nullptr, nullptr, nullptr, xbh, ybh, nullptr, DD, DD);
    // conv -> ah (fp16)
    conv_f16_kernel<<<gMD2, 256>>>((const __half2*)xbh, conv_w, conv_b, (__half2*)ah);
    // rlin -> rl ; ilin -> il  [dual, fp16 out]
    hmma_gemm<0,0,false,false,true><<<gemAI, 256, GEMM_SMEM>>>(ah, wh + WOFF_A,
        nullptr, nullptr, nullptr, rl, il, nullptr, DD, DD);
    // gates + chunked scan + z = h*yb -> ah (fp16)
    scan1_kernel<<<gSC2, 256>>>((__half2*)rl, (const __half2*)il, (const __half2*)ah,
                                lam, (__half2*)lh, (float2*)sa, (float2*)sh);
    scan2_kernel<<<(BB * DD2 + 255) / 256, 256>>>((const float2*)sa, (float2*)sh);
    scan3_kernel<<<gSC2, 256>>>((const __half2*)rl, (const __half2*)lh,
                                (const float2*)sh, (const __half2*)ybh, (__half2*)ah);
    // h1 = x + z @ Wo
    hmma_gemm<0,0,true,false,false><<<gemO, 256, GEMM_SMEM>>>(ah, wh + WOFF_O,
        x, h1, h1, nullptr, nullptr, nullptr, DD, DD);
    // u = rmsnorm(h1) -> ah
    rmsnorm_f16_kernel<<<MM, 256>>>(h1, norm2_w, ah);
    // ff = gelu(u @ Wg) * (u @ Wu) -> zh  [gated]
    hmma_gemm<0,0,false,true,false><<<gemGU, 256, GEMM_SMEM>>>(ah, wh + WOFF_GU,
        nullptr, nullptr, nullptr, nullptr, nullptr, zh, HH, DD);
    // out = h1 + ff @ Wd
    hmma_gemm<0,0,true,false,false><<<gemDn, 256, GEMM_SMEM>>>(zh, wh + WOFF_D,
        h1, out, out, nullptr, nullptr, nullptr, DD, HH);
}

// round 11
// speedup vs baseline: 7.3064x; 1.0137x over previous
#include <cuda_runtime.h>
#include <cuda_fp16.h>
#include <math.h>
#include <stdint.h>

// Problem dims (fixed by the dataset)
#define BB 4
#define SS 2048
#define DD 1024
#define HH 4096
#define MM (BB*SS)          // 8192 rows
#define NC 32               // scan chunks
#define CL (SS/NC)          // 64 steps per chunk
#define DD2 (DD/2)

// ---------------------------------------------------------------------------
// Scratch (static device globals; no allocation in kernel_launch)
// ---------------------------------------------------------------------------
__device__ __align__(16) float g_h1 [(size_t)MM*DD];    // h1 trunk (fp32)
__device__ __align__(16) float g_sa [(size_t)BB*NC*DD]; // chunk a-products
__device__ __align__(16) float g_sh [(size_t)BB*NC*DD]; // chunk h-carries

// fp16 streams
__device__ __align__(16) __half g_ah [(size_t)MM*DD];  // rmsnorm out / conv out / z
__device__ __align__(16) __half g_xbh[(size_t)MM*DD];  // xb (gemXY C1)
__device__ __align__(16) __half g_ybh[(size_t)MM*DD];  // yb (gemXY C2, gelu)
__device__ __align__(16) __half g_rl [(size_t)MM*DD];  // rlin -> a (in place)
__device__ __align__(16) __half g_il [(size_t)MM*DD];  // ilin
__device__ __align__(16) __half g_lh [(size_t)MM*DD];  // scan local h (fp16)
__device__ __align__(16) __half g_zh [(size_t)MM*HH];  // gated-MLP intermediate
// fp16 transposed weights, packed arena (17M halfs)
#define WOFF_X  ((size_t)0)
#define WOFF_Y  ((size_t)1*1024*1024)   // follows X (dual Wx|Wy)
#define WOFF_A  ((size_t)2*1024*1024)
#define WOFF_I  ((size_t)3*1024*1024)   // follows A (dual Wa|Wi)
#define WOFF_O  ((size_t)4*1024*1024)
#define WOFF_GU ((size_t)5*1024*1024)   // Wg/Wu column-interleaved (8192 rows)
#define WOFF_D  ((size_t)13*1024*1024)
__device__ __align__(16) __half g_wh[(size_t)17*1024*1024];

// ---------------------------------------------------------------------------
// Math helpers
// ---------------------------------------------------------------------------
__device__ __forceinline__ float geluf(float x) {
    const float c = 0.7978845608028654f; // sqrt(2/pi)
    float x3 = x * x * x;
    float t  = tanhf(c * (x + 0.044715f * x3));
    return 0.5f * x * (1.0f + t);
}
__device__ __forceinline__ float sigmoidf(float x) {
    return 1.0f / (1.0f + expf(-x));
}
__device__ __forceinline__ float softplusf(float x) {
    return fmaxf(x, 0.0f) + log1pf(expf(-fabsf(x)));
}

// ---------------------------------------------------------------------------
// PTX helpers (baseline compute_103 features only)
// ---------------------------------------------------------------------------
__device__ __forceinline__ uint32_t smem_u32(const void* p) {
    uint32_t a;
    asm("{ .reg .u64 t; cvta.to.shared.u64 t, %1; cvt.u32.u64 %0, t; }" : "=r"(a) : "l"(p));
    return a;
}
__device__ __forceinline__ void cp_async16(uint32_t dst, const void* src) {
    asm volatile("cp.async.cg.shared.global [%0], [%1], 16;" :: "r"(dst), "l"(src) : "memory");
}
__device__ __forceinline__ void ldm_x4(uint32_t& r0, uint32_t& r1, uint32_t& r2, uint32_t& r3,
                                       uint32_t addr) {
    asm volatile("ldmatrix.sync.aligned.m8n8.x4.shared.b16 {%0,%1,%2,%3}, [%4];"
                 : "=r"(r0), "=r"(r1), "=r"(r2), "=r"(r3) : "r"(addr));
}
__device__ __forceinline__ void mma16816(float* c, const uint32_t* a, const uint32_t* b) {
    asm volatile(
        "mma.sync.aligned.m16n8k16.row.col.f32.f16.f16.f32 "
        "{%0,%1,%2,%3}, {%4,%5,%6,%7}, {%8,%9}, {%0,%1,%2,%3};"
        : "+f"(c[0]), "+f"(c[1]), "+f"(c[2]), "+f"(c[3])
        : "r"(a[0]), "r"(a[1]), "r"(a[2]), "r"(a[3]), "r"(b[0]), "r"(b[1]));
}

// ---------------------------------------------------------------------------
// Single-product fp16 HMMA GEMM: C = act(A @ W^T) (+R).
// CTA 256x128, BK=64, 16 warps (4Mx4N, warp tile 64x32), 3-stage cp.async,
// fill-distance 2, single __syncthreads per chunk, 1 CTA/SM.
// OUT16: outputs written as fp16 (H1o/H2o). GATED: gelu(g)*v -> ZH fp16.
// ---------------------------------------------------------------------------
#define GSTRIDE 144u
#define TILE_A  36864u            // 256 rows * 144B
#define STG_B   55296u            // A(36864) + B(18432)
#define GEMM_SMEM (3*STG_B)       // 165888

template<int ACT1, int ACT2, bool RES, bool GATED, bool OUT16>
__global__ void __launch_bounds__(512, 1)
hmma_gemm(const __half* __restrict__ Ah, const __half* __restrict__ Bh,
          const float* __restrict__ R, float* __restrict__ C1, float* __restrict__ C2,
          __half* __restrict__ H1o, __half* __restrict__ H2o,
          __half* __restrict__ ZH,
          int NH, int K)
{
    extern __shared__ char smem[];
    const uint32_t sb = smem_u32(smem);
    const int tid  = threadIdx.x;
    const int wid  = tid >> 5;
    const int lane = tid & 31;
    const int bm = blockIdx.y * 256;
    const int bn = blockIdx.x * 128;
    const int wr = wid >> 2;          // warp row 0..3 (64 rows each)
    const int wc = wid & 3;           // warp col 0..3 (32 cols each)

    const int nch = K >> 6;           // BK = 64

    auto fill = [&](int ch) {
        const int k0 = ch << 6;
        const uint32_t st = sb + (uint32_t)(ch % 3) * STG_B;
        #pragma unroll
        for (int r = 0; r < 4; r++) {            // A: 2048 16B chunks
            const int c = tid + (r << 9);
            const int row = c >> 3, kc = c & 7;
            const uint32_t dst = (uint32_t)row * GSTRIDE + (uint32_t)(kc << 4);
            cp_async16(st + dst, Ah + (size_t)(bm + row) * K + k0 + (kc << 3));
        }
        #pragma unroll
        for (int r = 0; r < 2; r++) {            // B: 1024 16B chunks
            const int c = tid + (r << 9);
            const int row = c >> 3, kc = c & 7;
            const uint32_t dst = (uint32_t)row * GSTRIDE + (uint32_t)(kc << 4);
            cp_async16(st + TILE_A + dst, Bh + (size_t)(bn + row) * K + k0 + (kc << 3));
        }
        asm volatile("cp.async.commit_group;" ::: "memory");
    };

    float acc[4][4][4];
    #pragma unroll
    for (int i = 0; i < 4; i++)
        #pragma unroll
        for (int j = 0; j < 4; j++)
            #pragma unroll
            for (int q = 0; q < 4; q++) acc[i][j][q] = 0.0f;

    fill(0);
    if (nch > 1) fill(1);

    const int l16  = lane & 15;
    const int ahi  = (lane >> 4) << 4;
    const int brow = ((lane >> 4) << 3) + (lane & 7);
    const int bhi  = ((lane >> 3) & 1) << 4;

    for (int i = 0; i < nch; i++) {
        if (i + 1 < nch) asm volatile("cp.async.wait_group 1;" ::: "memory");
        else             asm volatile("cp.async.wait_group 0;" ::: "memory");
        __syncthreads();   // single barrier per chunk (fill-distance-2 safety)

        const uint32_t st  = sb + (uint32_t)(i % 3) * STG_B;
        const uint32_t sAh = st;
        const uint32_t sBh = st + TILE_A;

        #pragma unroll
        for (int ks = 0; ks < 4; ks++) {
            uint32_t ah[4][4];
            #pragma unroll
            for (int mt = 0; mt < 4; mt++) {
                const uint32_t ra = (uint32_t)(wr*64 + mt*16 + l16) * GSTRIDE
                                  + (uint32_t)(ks*32 + ahi);
                ldm_x4(ah[mt][0], ah[mt][1], ah[mt][2], ah[mt][3], sAh + ra);
            }
            #pragma unroll
            for (int ntp = 0; ntp < 2; ntp++) {
                uint32_t bq[4];
                const uint32_t rb = (uint32_t)(wc*32 + ntp*16 + brow) * GSTRIDE
                                  + (uint32_t)(ks*32 + bhi);
                ldm_x4(bq[0], bq[1], bq[2], bq[3], sBh + rb);
                #pragma unroll
                for (int mt = 0; mt < 4; mt++) {
                    mma16816(acc[mt][2*ntp],   ah[mt], bq);
                    mma16816(acc[mt][2*ntp+1], ah[mt], bq + 2);
                }
            }
        }
        if (i + 2 < nch) fill(i + 2);
    }

    const int erow = lane >> 2;
    const int ecol = (lane & 3) << 1;

    if constexpr (GATED) {
        #pragma unroll
        for (int mt = 0; mt < 4; mt++) {
            #pragma unroll
            for (int nt = 0; nt < 4; nt++) {
                const int r0 = bm + wr*64 + mt*16 + erow;
                const int j  = ((bn + wc*32 + nt*8 + ecol) >> 1);
                const float f0 = geluf(acc[mt][nt][0]) * acc[mt][nt][1];
                const float f1 = geluf(acc[mt][nt][2]) * acc[mt][nt][3];
                ZH[(size_t)r0     * NH + j] = __float2half_rn(f0);
                ZH[(size_t)(r0+8) * NH + j] = __float2half_rn(f1);
            }
        }
        return;
    }

    if constexpr (OUT16) {
        __half* Hout;
        int act, cb;
        if (bn < NH) { Hout = H1o; act = ACT1; cb = bn; }
        else         { Hout = H2o; act = ACT2; cb = bn - NH; }
        #pragma unroll
        for (int mt = 0; mt < 4; mt++) {
            #pragma unroll
            for (int nt = 0; nt < 4; nt++) {
                const int r0 = bm + wr*64 + mt*16 + erow;
                const int cc = cb + wc*32 + nt*8 + ecol;
                float v0 = acc[mt][nt][0], v1 = acc[mt][nt][1];
                float v2 = acc[mt][nt][2], v3 = acc[mt][nt][3];
                if (act == 1) { v0 = geluf(v0); v1 = geluf(v1); v2 = geluf(v2); v3 = geluf(v3); }
                *(__half2*)(Hout + (size_t)r0     * NH + cc) =
                    __floats2half2_rn(v0, v1);
                *(__half2*)(Hout + (size_t)(r0+8) * NH + cc) =
                    __floats2half2_rn(v2, v3);
            }
        }
        return;
    }

    // fp32 epilogue (with residual)
    float* Cout;
    int act, cb;
    if (bn < NH) { Cout = C1; act = ACT1; cb = bn; }
    else         { Cout = C2; act = ACT2; cb = bn - NH; }

    #pragma unroll
    for (int mt = 0; mt < 4; mt++) {
        #pragma unroll
        for (int nt = 0; nt < 4; nt++) {
            const int r0 = bm + wr*64 + mt*16 + erow;
            const int cc = cb + wc*32 + nt*8 + ecol;
            float v0 = acc[mt][nt][0], v1 = acc[mt][nt][1];
            float v2 = acc[mt][nt][2], v3 = acc[mt][nt][3];
            if (act == 1) { v0 = geluf(v0); v1 = geluf(v1); v2 = geluf(v2); v3 = geluf(v3); }
            if (RES) {
                const float2 ra = *(const float2*)(R + (size_t)r0 * NH + cc);
                const float2 rb = *(const float2*)(R + (size_t)(r0+8) * NH + cc);
                v0 += ra.x; v1 += ra.y; v2 += rb.x; v3 += rb.y;
            }
            *(float2*)(Cout + (size_t)r0     * NH + cc) = make_float2(v0, v1);
            *(float2*)(Cout + (size_t)(r0+8) * NH + cc) = make_float2(v2, v3);
        }
    }
}

// ---------------------------------------------------------------------------
// Weight transpose to fp16: W [Kd, Nd] fp32 -> Th [(n*rstride+roff), Kd] fp16
// ---------------------------------------------------------------------------
__device__ __forceinline__ void tsplit_body(const float* __restrict__ W,
                                            __half* __restrict__ Th,
                                            int Kd, int Nd, int rstride, int roff,
                                            int bx, int by)
{
    __shared__ float tile[32][33];
    const int n0 = bx * 32, k0 = by * 32;
    const int tx = threadIdx.x, ty = threadIdx.y;   // (32, 8)
    #pragma unroll
    for (int i = 0; i < 32; i += 8)
        tile[ty + i][tx] = W[(size_t)(k0 + ty + i) * Nd + n0 + tx];
    __syncthreads();
    #pragma unroll
    for (int i = 0; i < 32; i += 8) {
        const float v = tile[tx][ty + i];
        const size_t o = ((size_t)(n0 + ty + i) * rstride + roff) * Kd + k0 + tx;
        Th[o] = __float2half_rn(v);
    }
}

__global__ void tsplit_kernel(const float* __restrict__ W,
                              __half* __restrict__ Th,
                              int Kd, int Nd, int rstride, int roff)
{
    tsplit_body(W, Th, Kd, Nd, rstride, roff, blockIdx.x, blockIdx.y);
}

// Batched transpose of the five square DxD weights (z selects the weight).
__global__ void tsplit5_kernel(const float* __restrict__ W0, const float* __restrict__ W1,
                               const float* __restrict__ W2, const float* __restrict__ W3,
                               const float* __restrict__ W4, __half* __restrict__ ThBase)
{
    const float* W;
    __half* Th;
    switch (blockIdx.z) {
        case 0:  W = W0; Th = ThBase + WOFF_X; break;
        case 1:  W = W1; Th = ThBase + WOFF_Y; break;
        case 2:  W = W2; Th = ThBase + WOFF_A; break;
        case 3:  W = W3; Th = ThBase + WOFF_I; break;
        default: W = W4; Th = ThBase + WOFF_O; break;
    }
    tsplit_body(W, Th, DD, DD, 1, 0, blockIdx.x, blockIdx.y);
}

// ---------------------------------------------------------------------------
// RMSNorm with fp16 output (float2 / half2 vectorized; D=1024, 256 threads)
// ---------------------------------------------------------------------------
__global__ void rmsnorm_f16_kernel(const float* __restrict__ x,
                                   const float* __restrict__ w,
                                   __half* __restrict__ oh)
{
    const int row = blockIdx.x;
    const float2* xr = (const float2*)(x + (size_t)row * DD);
    const float2* w2 = (const float2*)w;
    float ss = 0.0f;
    float2 v[2];
    #pragma unroll
    for (int r = 0; r < 2; r++) {
        v[r] = xr[threadIdx.x + r * 256];
        ss = fmaf(v[r].x, v[r].x, fmaf(v[r].y, v[r].y, ss));
    }
    #pragma unroll
    for (int off = 16; off > 0; off >>= 1)
        ss += __shfl_xor_sync(0xffffffff, ss, off);
    __shared__ float red[8];
    const int lane = threadIdx.x & 31, wid = threadIdx.x >> 5;
    if (lane == 0) red[wid] = ss;
    __syncthreads();
    if (wid == 0) {
        float s = (lane < 8) ? red[lane] : 0.0f;
        #pragma unroll
        for (int off = 4; off > 0; off >>= 1)
            s += __shfl_xor_sync(0xffffffff, s, off);
        if (lane == 0) red[0] = s;
    }
    __syncthreads();
    const float inv = rsqrtf(red[0] / (float)DD + 1e-6f);
    __half2* o2 = (__half2*)(oh + (size_t)row * DD);
    #pragma unroll
    for (int r = 0; r < 2; r++) {
        const float2 ww = w2[threadIdx.x + r * 256];
        o2[threadIdx.x + r * 256] =
            __floats2half2_rn(v[r].x * inv * ww.x, v[r].y * inv * ww.y);
    }
}

// ---------------------------------------------------------------------------
// Causal depthwise conv (K=4), half2 vectorized (2 channels/thread)
// ---------------------------------------------------------------------------
__global__ void conv_f16_kernel(const __half2* __restrict__ in,
                                const float* __restrict__ cw,
                                const float* __restrict__ cb,
                                __half2* __restrict__ oh)
{
    const size_t idx = (size_t)blockIdx.x * blockDim.x + threadIdx.x;
    if (idx >= (size_t)MM * DD2) return;
    const int d2 = (int)(idx % DD2);
    const int s  = (int)((idx / DD2) % SS);
    float a0 = cb[2*d2], a1 = cb[2*d2 + 1];
    #pragma unroll
    for (int k = 0; k < 4; k++) {
        if (s + k - 3 >= 0) {
            const float2 v = __half22float2(in[idx - (size_t)(3 - k) * DD2]);
            a0 = fmaf(cw[k * DD + 2*d2],     v.x, a0);
            a1 = fmaf(cw[k * DD + 2*d2 + 1], v.y, a1);
        }
    }
    oh[idx] = __floats2half2_rn(a0, a1);
}

// ---------------------------------------------------------------------------
// Scan pass 1 (half2): gates + chunk-local scan; a->rl in place (fp16),
// local h -> lh (fp16), chunk products/carries -> sa/sh (float2).
// ---------------------------------------------------------------------------
__global__ void scan1_kernel(__half2* __restrict__ rlin_a,
                             const __half2* __restrict__ ilin,
                             const __half2* __restrict__ xc,
                             const float* __restrict__ lam,
                             __half2* __restrict__ lh,
                             float2* __restrict__ sa,
                             float2* __restrict__ sh)
{
    const int idx = blockIdx.x * blockDim.x + threadIdx.x;
    if (idx >= BB * NC * DD2) return;
    const int d2    = idx % DD2;
    const int chunk = (idx / DD2) % NC;
    const int batch = idx / (DD2 * NC);
    const float cf0 = -8.0f * softplusf(lam[2*d2]);
    const float cf1 = -8.0f * softplusf(lam[2*d2 + 1]);
    const size_t base = ((size_t)batch * SS + (size_t)chunk * CL) * DD2 + d2;

    float p0 = 1.0f, p1 = 1.0f, h0 = 0.0f, h1 = 0.0f;
    for (int t = 0; t < CL; t++) {
        const size_t off = base + (size_t)t * DD2;
        const float2 rv = __half22float2(rlin_a[off]);
        const float2 iv = __half22float2(ilin[off]);
        const float2 xv = __half22float2(xc[off]);
        const float a0 = expf(cf0 * sigmoidf(rv.x));
        const float a1 = expf(cf1 * sigmoidf(rv.y));
        const float b0 = sqrtf(fmaxf(1.0f - a0*a0, 1e-12f)) * sigmoidf(iv.x) * xv.x;
        const float b1 = sqrtf(fmaxf(1.0f - a1*a1, 1e-12f)) * sigmoidf(iv.y) * xv.y;
        h0 = fmaf(a0, h0, b0);
        h1 = fmaf(a1, h1, b1);
        p0 *= a0; p1 *= a1;
        rlin_a[off] = __floats2half2_rn(a0, a1);
        lh[off]     = __floats2half2_rn(h0, h1);
    }
    sa[idx] = make_float2(p0, p1);
    sh[idx] = make_float2(h0, h1);
}

// ---------------------------------------------------------------------------
// Scan pass 2 (float2): combine chunk carries.
// ---------------------------------------------------------------------------
__global__ void scan2_kernel(const float2* __restrict__ sa, float2* __restrict__ sh)
{
    const int idx = blockIdx.x * blockDim.x + threadIdx.x;
    if (idx >= BB * DD2) return;
    const int d2 = idx % DD2, batch = idx / DD2;
    float H0 = 0.0f, H1 = 0.0f;
    for (int c = 0; c < NC; c++) {
        const size_t o = ((size_t)batch * NC + c) * DD2 + d2;
        const float2 av = sa[o];
        const float2 hv = sh[o];
        H0 = fmaf(av.x, H0, hv.x);
        H1 = fmaf(av.y, H1, hv.y);
        sh[o] = make_float2(H0, H1);
    }
}

// ---------------------------------------------------------------------------
// Scan pass 3 (half2): apply carries, z = h * yb, fp16 out.
// ---------------------------------------------------------------------------
__global__ void scan3_kernel(const __half2* __restrict__ aArr,
                             const __half2* __restrict__ lhArr,
                             const float2* __restrict__ sh,
                             const __half2* __restrict__ yb,
                             __half2* __restrict__ zh)
{
    const int idx = blockIdx.x * blockDim.x + threadIdx.x;
    if (idx >= BB * NC * DD2) return;
    const int d2    = idx % DD2;
    const int chunk = (idx / DD2) % NC;
    const int batch = idx / (DD2 * NC);
    float c0 = 0.0f, c1 = 0.0f;
    if (chunk != 0) {
        const float2 cv = sh[((size_t)batch * NC + chunk - 1) * DD2 + d2];
        c0 = cv.x; c1 = cv.y;
    }
    const size_t base = ((size_t)batch * SS + (size_t)chunk * CL) * DD2 + d2;

    float p0 = 1.0f, p1 = 1.0f;
    for (int t = 0; t < CL; t++) {
        const size_t off = base + (size_t)t * DD2;
        const float2 av = __half22float2(aArr[off]);
        const float2 lv = __half22float2(lhArr[off]);
        const float2 yv = __half22float2(yb[off]);
        p0 *= av.x; p1 *= av.y;
        const float z0 = fmaf(p0, c0, lv.x) * yv.x;
        const float z1 = fmaf(p1, c1, lv.y) * yv.y;
        zh[off] = __floats2half2_rn(z0, z1);
    }
}

// ---------------------------------------------------------------------------
// Launch
// ---------------------------------------------------------------------------
extern "C" void kernel_launch(void* const* d_in, const int* in_sizes, int n_in,
                              void* d_out, int out_size)
{
    const float* x       = (const float*)d_in[0];
    const float* norm1_w = (const float*)d_in[1];
    const float* Wx      = (const float*)d_in[2];
    const float* Wy      = (const float*)d_in[3];
    const float* conv_w  = (const float*)d_in[4];
    const float* conv_b  = (const float*)d_in[5];
    const float* Wi      = (const float*)d_in[6];
    const float* Wa      = (const float*)d_in[7];
    const float* lam     = (const float*)d_in[8];
    const float* Wo      = (const float*)d_in[9];
    const float* norm2_w = (const float*)d_in[10];
    const float* Wg      = (const float*)d_in[11];
    const float* Wu      = (const float*)d_in[12];
    const float* Wd      = (const float*)d_in[13];
    float* out = (float*)d_out;

    float *h1, *sa, *sh;
    __half *ah, *xbh, *ybh, *rl, *il, *lh, *zh, *wh;
    cudaGetSymbolAddress((void**)&h1,  g_h1);
    cudaGetSymbolAddress((void**)&sa,  g_sa);
    cudaGetSymbolAddress((void**)&sh,  g_sh);
    cudaGetSymbolAddress((void**)&ah,  g_ah);
    cudaGetSymbolAddress((void**)&xbh, g_xbh);
    cudaGetSymbolAddress((void**)&ybh, g_ybh);
    cudaGetSymbolAddress((void**)&rl,  g_rl);
    cudaGetSymbolAddress((void**)&il,  g_il);
    cudaGetSymbolAddress((void**)&lh,  g_lh);
    cudaGetSymbolAddress((void**)&zh,  g_zh);
    cudaGetSymbolAddress((void**)&wh,  g_wh);

    cudaFuncSetAttribute(hmma_gemm<0,1,false,false,true>,  cudaFuncAttributeMaxDynamicSharedMemorySize, GEMM_SMEM);
    cudaFuncSetAttribute(hmma_gemm<0,0,false,false,true>,  cudaFuncAttributeMaxDynamicSharedMemorySize, GEMM_SMEM);
    cudaFuncSetAttribute(hmma_gemm<0,0,true,false,false>,  cudaFuncAttributeMaxDynamicSharedMemorySize, GEMM_SMEM);
    cudaFuncSetAttribute(hmma_gemm<0,0,false,true,false>,  cudaFuncAttributeMaxDynamicSharedMemorySize, GEMM_SMEM);

    const dim3 tsb(32, 8);
    const int gMD2 = (int)(((size_t)MM * DD2 + 255) / 256);
    const int gSC2 = (BB * NC * DD2 + 255) / 256;

    const dim3 gemXY(2048 / 128, MM / 256);   // dual Wx|Wy (fp16 out)
    const dim3 gemAI(2048 / 128, MM / 256);   // dual Wa|Wi (fp16 out)
    const dim3 gemGU(8192 / 128, MM / 256);   // interleaved Wg|Wu (gated)
    const dim3 gemO (1024 / 128, MM / 256);   // Wo (K=1024, fp32+res)
    const dim3 gemDn(1024 / 128, MM / 256);   // Wd (K=4096, fp32+res)

    // weight prep (front-loaded) + rmsnorm1
    tsplit5_kernel<<<dim3(32, 32, 5), tsb>>>(Wx, Wy, Wa, Wi, Wo, wh);
    tsplit_kernel<<<dim3(HH/32, DD/32), tsb>>>(Wg, wh + WOFF_GU, DD, HH, 2, 0);
    tsplit_kernel<<<dim3(HH/32, DD/32), tsb>>>(Wu, wh + WOFF_GU, DD, HH, 2, 1);
    tsplit_kernel<<<dim3(DD/32, HH/32), tsb>>>(Wd, wh + WOFF_D, HH, DD, 1, 0);
    rmsnorm_f16_kernel<<<MM, 256>>>(x, norm1_w, ah);
    // xb = t @ Wx ; yb = gelu(t @ Wy)  [dual, fp16 out]
    hmma_gemm<0,1,false,false,true><<<gemXY, 512, GEMM_SMEM>>>(ah, wh + WOFF_X,
        nullptr, nullptr, nullptr, xbh, ybh, nullptr, DD, DD);
    // conv -> ah (fp16)
    conv_f16_kernel<<<gMD2, 256>>>((const __half2*)xbh, conv_w, conv_b, (__half2*)ah);
    // rlin -> rl ; ilin -> il  [dual, fp16 out]
    hmma_gemm<0,0,false,false,true><<<gemAI, 512, GEMM_SMEM>>>(ah, wh + WOFF_A,
        nullptr, nullptr, nullptr, rl, il, nullptr, DD, DD);
    // gates + chunked scan + z = h*yb -> ah (fp16)
    scan1_kernel<<<gSC2, 256>>>((__half2*)rl, (const __half2*)il, (const __half2*)ah,
                                lam, (__half2*)lh, (float2*)sa, (float2*)sh);
    scan2_kernel<<<(BB * DD2 + 255) / 256, 256>>>((const float2*)sa, (float2*)sh);
    scan3_kernel<<<gSC2, 256>>>((const __half2*)rl, (const __half2*)lh,
                                (const float2*)sh, (const __half2*)ybh, (__half2*)ah);
    // h1 = x + z @ Wo
    hmma_gemm<0,0,true,false,false><<<gemO, 512, GEMM_SMEM>>>(ah, wh + WOFF_O,
        x, h1, h1, nullptr, nullptr, nullptr, DD, DD);
    // u = rmsnorm(h1) -> ah
    rmsnorm_f16_kernel<<<MM, 256>>>(h1, norm2_w, ah);
    // ff = gelu(u @ Wg) * (u @ Wu) -> zh  [gated]
    hmma_gemm<0,0,false,true,false><<<gemGU, 512, GEMM_SMEM>>>(ah, wh + WOFF_GU,
        nullptr, nullptr, nullptr, nullptr, nullptr, zh, HH, DD);
    // out = h1 + ff @ Wd
    hmma_gemm<0,0,true,false,false><<<gemDn, 512, GEMM_SMEM>>>(zh, wh + WOFF_D,
        h1, out, out, nullptr, nullptr, nullptr, DD, HH);
}

// round 12
// speedup vs baseline: 7.3916x; 1.0117x over previous
#include <cuda_runtime.h>
#include <cuda_fp16.h>
#include <math.h>
#include <stdint.h>

// Problem dims (fixed by the dataset)
#define BB 4
#define SS 2048
#define DD 1024
#define HH 4096
#define MM (BB*SS)          // 8192 rows
#define NC 32               // scan chunks
#define CL (SS/NC)          // 64 steps per chunk
#define DD2 (DD/2)

// ---------------------------------------------------------------------------
// Scratch (static device globals; no allocation in kernel_launch)
// ---------------------------------------------------------------------------
__device__ __align__(16) float g_h1 [(size_t)MM*DD];    // h1 trunk (fp32)
__device__ __align__(16) float g_sa [(size_t)BB*NC*DD]; // chunk a-products
__device__ __align__(16) float g_sh [(size_t)BB*NC*DD]; // chunk h-carries

// fp16 streams
__device__ __align__(16) __half g_ah [(size_t)MM*DD];  // rmsnorm out / conv out / z
__device__ __align__(16) __half g_xbh[(size_t)MM*DD];  // xb (gemXY C1)
__device__ __align__(16) __half g_ybh[(size_t)MM*DD];  // yb (gemXY C2, gelu)
__device__ __align__(16) __half g_rl [(size_t)MM*DD];  // rlin -> a (in place)
__device__ __align__(16) __half g_il [(size_t)MM*DD];  // ilin
__device__ __align__(16) __half g_lh [(size_t)MM*DD];  // scan local h (fp16)
__device__ __align__(16) __half g_zh [(size_t)MM*HH];  // gated-MLP intermediate
// fp16 transposed weights, packed arena (17M halfs)
#define WOFF_X  ((size_t)0)
#define WOFF_Y  ((size_t)1*1024*1024)   // follows X (dual Wx|Wy)
#define WOFF_A  ((size_t)2*1024*1024)
#define WOFF_I  ((size_t)3*1024*1024)   // follows A (dual Wa|Wi)
#define WOFF_O  ((size_t)4*1024*1024)
#define WOFF_GU ((size_t)5*1024*1024)   // Wg/Wu column-interleaved (8192 rows)
#define WOFF_D  ((size_t)13*1024*1024)
__device__ __align__(16) __half g_wh[(size_t)17*1024*1024];

// ---------------------------------------------------------------------------
// Math helpers
// ---------------------------------------------------------------------------
__device__ __forceinline__ float geluf(float x) {
    const float c = 0.7978845608028654f; // sqrt(2/pi)
    float x3 = x * x * x;
    float t  = tanhf(c * (x + 0.044715f * x3));
    return 0.5f * x * (1.0f + t);
}
__device__ __forceinline__ float sigmoidf(float x) {
    return 1.0f / (1.0f + expf(-x));
}
__device__ __forceinline__ float softplusf(float x) {
    return fmaxf(x, 0.0f) + log1pf(expf(-fabsf(x)));
}

// ---------------------------------------------------------------------------
// PTX helpers (baseline compute_103 features only)
// ---------------------------------------------------------------------------
__device__ __forceinline__ uint32_t smem_u32(const void* p) {
    uint32_t a;
    asm("{ .reg .u64 t; cvta.to.shared.u64 t, %1; cvt.u32.u64 %0, t; }" : "=r"(a) : "l"(p));
    return a;
}
__device__ __forceinline__ void cp_async16(uint32_t dst, const void* src) {
    asm volatile("cp.async.cg.shared.global [%0], [%1], 16;" :: "r"(dst), "l"(src) : "memory");
}
__device__ __forceinline__ void ldm_x4(uint32_t& r0, uint32_t& r1, uint32_t& r2, uint32_t& r3,
                                       uint32_t addr) {
    asm volatile("ldmatrix.sync.aligned.m8n8.x4.shared.b16 {%0,%1,%2,%3}, [%4];"
                 : "=r"(r0), "=r"(r1), "=r"(r2), "=r"(r3) : "r"(addr));
}
__device__ __forceinline__ void mma16816(float* c, const uint32_t* a, const uint32_t* b) {
    asm volatile(
        "mma.sync.aligned.m16n8k16.row.col.f32.f16.f16.f32 "
        "{%0,%1,%2,%3}, {%4,%5,%6,%7}, {%8,%9}, {%0,%1,%2,%3};"
        : "+f"(c[0]), "+f"(c[1]), "+f"(c[2]), "+f"(c[3])
        : "r"(a[0]), "r"(a[1]), "r"(a[2]), "r"(a[3]), "r"(b[0]), "r"(b[1]));
}

// ---------------------------------------------------------------------------
// Single-product fp16 HMMA GEMM: C = act(A @ W^T) (+R).
// CTA 256x128, BK=64, 16 warps (4Mx4N, warp tile 64x32), 4-stage cp.async,
// fill-distance 3, single __syncthreads per chunk, 1 CTA/SM.
// OUT16: outputs written as fp16 (H1o/H2o). GATED: gelu(g)*v -> ZH fp16
// with lane-pair half2 packed stores.
// ---------------------------------------------------------------------------
#define GSTRIDE 144u
#define TILE_A  36864u            // 256 rows * 144B
#define STG_B   55296u            // A(36864) + B(18432)
#define GEMM_SMEM (4*STG_B)       // 221184

template<int ACT1, int ACT2, bool RES, bool GATED, bool OUT16>
__global__ void __launch_bounds__(512, 1)
hmma_gemm(const __half* __restrict__ Ah, const __half* __restrict__ Bh,
          const float* __restrict__ R, float* __restrict__ C1, float* __restrict__ C2,
          __half* __restrict__ H1o, __half* __restrict__ H2o,
          __half* __restrict__ ZH,
          int NH, int K)
{
    extern __shared__ char smem[];
    const uint32_t sb = smem_u32(smem);
    const int tid  = threadIdx.x;
    const int wid  = tid >> 5;
    const int lane = tid & 31;
    const int bm = blockIdx.y * 256;
    const int bn = blockIdx.x * 128;
    const int wr = wid >> 2;          // warp row 0..3 (64 rows each)
    const int wc = wid & 3;           // warp col 0..3 (32 cols each)

    const int nch = K >> 6;           // BK = 64

    auto fill = [&](int ch) {
        const int k0 = ch << 6;
        const uint32_t st = sb + (uint32_t)(ch & 3) * STG_B;
        #pragma unroll
        for (int r = 0; r < 4; r++) {            // A: 2048 16B chunks
            const int c = tid + (r << 9);
            const int row = c >> 3, kc = c & 7;
            const uint32_t dst = (uint32_t)row * GSTRIDE + (uint32_t)(kc << 4);
            cp_async16(st + dst, Ah + (size_t)(bm + row) * K + k0 + (kc << 3));
        }
        #pragma unroll
        for (int r = 0; r < 2; r++) {            // B: 1024 16B chunks
            const int c = tid + (r << 9);
            const int row = c >> 3, kc = c & 7;
            const uint32_t dst = (uint32_t)row * GSTRIDE + (uint32_t)(kc << 4);
            cp_async16(st + TILE_A + dst, Bh + (size_t)(bn + row) * K + k0 + (kc << 3));
        }
        asm volatile("cp.async.commit_group;" ::: "memory");
    };

    float acc[4][4][4];
    #pragma unroll
    for (int i = 0; i < 4; i++)
        #pragma unroll
        for (int j = 0; j < 4; j++)
            #pragma unroll
            for (int q = 0; q < 4; q++) acc[i][j][q] = 0.0f;

    fill(0);
    if (nch > 1) fill(1);
    if (nch > 2) fill(2);

    const int l16  = lane & 15;
    const int ahi  = (lane >> 4) << 4;
    const int brow = ((lane >> 4) << 3) + (lane & 7);
    const int bhi  = ((lane >> 3) & 1) << 4;

    for (int i = 0; i < nch; i++) {
        if      (i + 2 < nch) asm volatile("cp.async.wait_group 2;" ::: "memory");
        else if (i + 1 < nch) asm volatile("cp.async.wait_group 1;" ::: "memory");
        else                  asm volatile("cp.async.wait_group 0;" ::: "memory");
        __syncthreads();   // single barrier per chunk (fill-distance-3, 4 buffers)

        const uint32_t st  = sb + (uint32_t)(i & 3) * STG_B;
        const uint32_t sAh = st;
        const uint32_t sBh = st + TILE_A;

        #pragma unroll
        for (int ks = 0; ks < 4; ks++) {
            uint32_t ah[4][4];
            #pragma unroll
            for (int mt = 0; mt < 4; mt++) {
                const uint32_t ra = (uint32_t)(wr*64 + mt*16 + l16) * GSTRIDE
                                  + (uint32_t)(ks*32 + ahi);
                ldm_x4(ah[mt][0], ah[mt][1], ah[mt][2], ah[mt][3], sAh + ra);
            }
            #pragma unroll
            for (int ntp = 0; ntp < 2; ntp++) {
                uint32_t bq[4];
                const uint32_t rb = (uint32_t)(wc*32 + ntp*16 + brow) * GSTRIDE
                                  + (uint32_t)(ks*32 + bhi);
                ldm_x4(bq[0], bq[1], bq[2], bq[3], sBh + rb);
                #pragma unroll
                for (int mt = 0; mt < 4; mt++) {
                    mma16816(acc[mt][2*ntp],   ah[mt], bq);
                    mma16816(acc[mt][2*ntp+1], ah[mt], bq + 2);
                }
            }
        }
        if (i + 3 < nch) fill(i + 3);
    }

    const int erow = lane >> 2;
    const int ecol = (lane & 3) << 1;

    if constexpr (GATED) {
        // (c0,c1)=(g_j,v_j). Lane quad covers 4 consecutive j; pack lane pairs
        // into half2 stores (even lane of each pair writes 4B).
        #pragma unroll
        for (int mt = 0; mt < 4; mt++) {
            #pragma unroll
            for (int nt = 0; nt < 4; nt++) {
                const int r0 = bm + wr*64 + mt*16 + erow;
                const int j  = ((bn + wc*32 + nt*8 + ecol) >> 1);
                const float f0 = geluf(acc[mt][nt][0]) * acc[mt][nt][1];
                const float f1 = geluf(acc[mt][nt][2]) * acc[mt][nt][3];
                const float f0n = __shfl_down_sync(0xffffffff, f0, 1);
                const float f1n = __shfl_down_sync(0xffffffff, f1, 1);
                if ((lane & 1) == 0) {
                    *(__half2*)(ZH + (size_t)r0     * NH + j) = __floats2half2_rn(f0, f0n);
                    *(__half2*)(ZH + (size_t)(r0+8) * NH + j) = __floats2half2_rn(f1, f1n);
                }
            }
        }
        return;
    }

    if constexpr (OUT16) {
        __half* Hout;
        int act, cb;
        if (bn < NH) { Hout = H1o; act = ACT1; cb = bn; }
        else         { Hout = H2o; act = ACT2; cb = bn - NH; }
        #pragma unroll
        for (int mt = 0; mt < 4; mt++) {
            #pragma unroll
            for (int nt = 0; nt < 4; nt++) {
                const int r0 = bm + wr*64 + mt*16 + erow;
                const int cc = cb + wc*32 + nt*8 + ecol;
                float v0 = acc[mt][nt][0], v1 = acc[mt][nt][1];
                float v2 = acc[mt][nt][2], v3 = acc[mt][nt][3];
                if (act == 1) { v0 = geluf(v0); v1 = geluf(v1); v2 = geluf(v2); v3 = geluf(v3); }
                *(__half2*)(Hout + (size_t)r0     * NH + cc) =
                    __floats2half2_rn(v0, v1);
                *(__half2*)(Hout + (size_t)(r0+8) * NH + cc) =
                    __floats2half2_rn(v2, v3);
            }
        }
        return;
    }

    // fp32 epilogue (with residual)
    float* Cout;
    int act, cb;
    if (bn < NH) { Cout = C1; act = ACT1; cb = bn; }
    else         { Cout = C2; act = ACT2; cb = bn - NH; }

    #pragma unroll
    for (int mt = 0; mt < 4; mt++) {
        #pragma unroll
        for (int nt = 0; nt < 4; nt++) {
            const int r0 = bm + wr*64 + mt*16 + erow;
            const int cc = cb + wc*32 + nt*8 + ecol;
            float v0 = acc[mt][nt][0], v1 = acc[mt][nt][1];
            float v2 = acc[mt][nt][2], v3 = acc[mt][nt][3];
            if (act == 1) { v0 = geluf(v0); v1 = geluf(v1); v2 = geluf(v2); v3 = geluf(v3); }
            if (RES) {
                const float2 ra = *(const float2*)(R + (size_t)r0 * NH + cc);
                const float2 rb = *(const float2*)(R + (size_t)(r0+8) * NH + cc);
                v0 += ra.x; v1 += ra.y; v2 += rb.x; v3 += rb.y;
            }
            *(float2*)(Cout + (size_t)r0     * NH + cc) = make_float2(v0, v1);
            *(float2*)(Cout + (size_t)(r0+8) * NH + cc) = make_float2(v2, v3);
        }
    }
}

// ---------------------------------------------------------------------------
// Weight transpose to fp16: W [Kd, Nd] fp32 -> Th [(n*rstride+roff), Kd] fp16
// Single fused kernel: flattened grid over all 8 transposes.
//   Ranges (32x32 tiles): squares 5*1024, Wg 4096, Wu 4096, Wd 4096 = 17408.
// ---------------------------------------------------------------------------
__device__ __forceinline__ void tsplit_body(const float* __restrict__ W,
                                            __half* __restrict__ Th,
                                            int Kd, int Nd, int rstride, int roff,
                                            int bx, int by)
{
    __shared__ float tile[32][33];
    const int n0 = bx * 32, k0 = by * 32;
    const int tx = threadIdx.x, ty = threadIdx.y;   // (32, 8)
    #pragma unroll
    for (int i = 0; i < 32; i += 8)
        tile[ty + i][tx] = W[(size_t)(k0 + ty + i) * Nd + n0 + tx];
    __syncthreads();
    #pragma unroll
    for (int i = 0; i < 32; i += 8) {
        const float v = tile[tx][ty + i];
        const size_t o = ((size_t)(n0 + ty + i) * rstride + roff) * Kd + k0 + tx;
        Th[o] = __float2half_rn(v);
    }
}

__global__ void prep_all_kernel(const float* __restrict__ Wx, const float* __restrict__ Wy,
                                const float* __restrict__ Wa, const float* __restrict__ Wi,
                                const float* __restrict__ Wo, const float* __restrict__ Wg,
                                const float* __restrict__ Wu, const float* __restrict__ Wd,
                                __half* __restrict__ wh)
{
    int b = blockIdx.x;
    if (b < 5 * 1024) {
        // 5 square DxD transposes: 32x32 grid each
        const int w = b >> 10;
        const int t = b & 1023;
        const float* W;
        size_t off;
        switch (w) {
            case 0:  W = Wx; off = WOFF_X; break;
            case 1:  W = Wy; off = WOFF_Y; break;
            case 2:  W = Wa; off = WOFF_A; break;
            case 3:  W = Wi; off = WOFF_I; break;
            default: W = Wo; off = WOFF_O; break;
        }
        tsplit_body(W, wh + off, DD, DD, 1, 0, t & 31, t >> 5);
        return;
    }
    b -= 5 * 1024;
    if (b < 4096) {        // Wg: [DD, HH] -> interleaved even rows; grid 128 x 32
        tsplit_body(Wg, wh + WOFF_GU, DD, HH, 2, 0, b & 127, b >> 7);
        return;
    }
    b -= 4096;
    if (b < 4096) {        // Wu: odd rows
        tsplit_body(Wu, wh + WOFF_GU, DD, HH, 2, 1, b & 127, b >> 7);
        return;
    }
    b -= 4096;             // Wd: [HH, DD] -> [DD, HH]; grid 32 x 128
    tsplit_body(Wd, wh + WOFF_D, HH, DD, 1, 0, b & 31, b >> 5);
}

// ---------------------------------------------------------------------------
// RMSNorm with fp16 output (float2 / half2 vectorized; D=1024, 256 threads)
// ---------------------------------------------------------------------------
__global__ void rmsnorm_f16_kernel(const float* __restrict__ x,
                                   const float* __restrict__ w,
                                   __half* __restrict__ oh)
{
    const int row = blockIdx.x;
    const float2* xr = (const float2*)(x + (size_t)row * DD);
    const float2* w2 = (const float2*)w;
    float ss = 0.0f;
    float2 v[2];
    #pragma unroll
    for (int r = 0; r < 2; r++) {
        v[r] = xr[threadIdx.x + r * 256];
        ss = fmaf(v[r].x, v[r].x, fmaf(v[r].y, v[r].y, ss));
    }
    #pragma unroll
    for (int off = 16; off > 0; off >>= 1)
        ss += __shfl_xor_sync(0xffffffff, ss, off);
    __shared__ float red[8];
    const int lane = threadIdx.x & 31, wid = threadIdx.x >> 5;
    if (lane == 0) red[wid] = ss;
    __syncthreads();
    if (wid == 0) {
        float s = (lane < 8) ? red[lane] : 0.0f;
        #pragma unroll
        for (int off = 4; off > 0; off >>= 1)
            s += __shfl_xor_sync(0xffffffff, s, off);
        if (lane == 0) red[0] = s;
    }
    __syncthreads();
    const float inv = rsqrtf(red[0] / (float)DD + 1e-6f);
    __half2* o2 = (__half2*)(oh + (size_t)row * DD);
    #pragma unroll
    for (int r = 0; r < 2; r++) {
        const float2 ww = w2[threadIdx.x + r * 256];
        o2[threadIdx.x + r * 256] =
            __floats2half2_rn(v[r].x * inv * ww.x, v[r].y * inv * ww.y);
    }
}

// ---------------------------------------------------------------------------
// Causal depthwise conv (K=4), half2 vectorized (2 channels/thread)
// ---------------------------------------------------------------------------
__global__ void conv_f16_kernel(const __half2* __restrict__ in,
                                const float* __restrict__ cw,
                                const float* __restrict__ cb,
                                __half2* __restrict__ oh)
{
    const size_t idx = (size_t)blockIdx.x * blockDim.x + threadIdx.x;
    if (idx >= (size_t)MM * DD2) return;
    const int d2 = (int)(idx % DD2);
    const int s  = (int)((idx / DD2) % SS);
    float a0 = cb[2*d2], a1 = cb[2*d2 + 1];
    #pragma unroll
    for (int k = 0; k < 4; k++) {
        if (s + k - 3 >= 0) {
            const float2 v = __half22float2(in[idx - (size_t)(3 - k) * DD2]);
            a0 = fmaf(cw[k * DD + 2*d2],     v.x, a0);
            a1 = fmaf(cw[k * DD + 2*d2 + 1], v.y, a1);
        }
    }
    oh[idx] = __floats2half2_rn(a0, a1);
}

// ---------------------------------------------------------------------------
// Scan pass 1 (half2): gates + chunk-local scan.
// ---------------------------------------------------------------------------
__global__ void scan1_kernel(__half2* __restrict__ rlin_a,
                             const __half2* __restrict__ ilin,
                             const __half2* __restrict__ xc,
                             const float* __restrict__ lam,
                             __half2* __restrict__ lh,
                             float2* __restrict__ sa,
                             float2* __restrict__ sh)
{
    const int idx = blockIdx.x * blockDim.x + threadIdx.x;
    if (idx >= BB * NC * DD2) return;
    const int d2    = idx % DD2;
    const int chunk = (idx / DD2) % NC;
    const int batch = idx / (DD2 * NC);
    const float cf0 = -8.0f * softplusf(lam[2*d2]);
    const float cf1 = -8.0f * softplusf(lam[2*d2 + 1]);
    const size_t base = ((size_t)batch * SS + (size_t)chunk * CL) * DD2 + d2;

    float p0 = 1.0f, p1 = 1.0f, h0 = 0.0f, h1 = 0.0f;
    for (int t = 0; t < CL; t++) {
        const size_t off = base + (size_t)t * DD2;
        const float2 rv = __half22float2(rlin_a[off]);
        const float2 iv = __half22float2(ilin[off]);
        const float2 xv = __half22float2(xc[off]);
        const float a0 = expf(cf0 * sigmoidf(rv.x));
        const float a1 = expf(cf1 * sigmoidf(rv.y));
        const float b0 = sqrtf(fmaxf(1.0f - a0*a0, 1e-12f)) * sigmoidf(iv.x) * xv.x;
        const float b1 = sqrtf(fmaxf(1.0f - a1*a1, 1e-12f)) * sigmoidf(iv.y) * xv.y;
        h0 = fmaf(a0, h0, b0);
        h1 = fmaf(a1, h1, b1);
        p0 *= a0; p1 *= a1;
        rlin_a[off] = __floats2half2_rn(a0, a1);
        lh[off]     = __floats2half2_rn(h0, h1);
    }
    sa[idx] = make_float2(p0, p1);
    sh[idx] = make_float2(h0, h1);
}

// ---------------------------------------------------------------------------
// Scan pass 2 (float2): combine chunk carries.
// ---------------------------------------------------------------------------
__global__ void scan2_kernel(const float2* __restrict__ sa, float2* __restrict__ sh)
{
    const int idx = blockIdx.x * blockDim.x + threadIdx.x;
    if (idx >= BB * DD2) return;
    const int d2 = idx % DD2, batch = idx / DD2;
    float H0 = 0.0f, H1 = 0.0f;
    for (int c = 0; c < NC; c++) {
        const size_t o = ((size_t)batch * NC + c) * DD2 + d2;
        const float2 av = sa[o];
        const float2 hv = sh[o];
        H0 = fmaf(av.x, H0, hv.x);
        H1 = fmaf(av.y, H1, hv.y);
        sh[o] = make_float2(H0, H1);
    }
}

// ---------------------------------------------------------------------------
// Scan pass 3 (half2): apply carries, z = h * yb, fp16 out.
// ---------------------------------------------------------------------------
__global__ void scan3_kernel(const __half2* __restrict__ aArr,
                             const __half2* __restrict__ lhArr,
                             const float2* __restrict__ sh,
                             const __half2* __restrict__ yb,
                             __half2* __restrict__ zh)
{
    const int idx = blockIdx.x * blockDim.x + threadIdx.x;
    if (idx >= BB * NC * DD2) return;
    const int d2    = idx % DD2;
    const int chunk = (idx / DD2) % NC;
    const int batch = idx / (DD2 * NC);
    float c0 = 0.0f, c1 = 0.0f;
    if (chunk != 0) {
        const float2 cv = sh[((size_t)batch * NC + chunk - 1) * DD2 + d2];
        c0 = cv.x; c1 = cv.y;
    }
    const size_t base = ((size_t)batch * SS + (size_t)chunk * CL) * DD2 + d2;

    float p0 = 1.0f, p1 = 1.0f;
    for (int t = 0; t < CL; t++) {
        const size_t off = base + (size_t)t * DD2;
        const float2 av = __half22float2(aArr[off]);
        const float2 lv = __half22float2(lhArr[off]);
        const float2 yv = __half22float2(yb[off]);
        p0 *= av.x; p1 *= av.y;
        const float z0 = fmaf(p0, c0, lv.x) * yv.x;
        const float z1 = fmaf(p1, c1, lv.y) * yv.y;
        zh[off] = __floats2half2_rn(z0, z1);
    }
}

// ---------------------------------------------------------------------------
// Launch
// ---------------------------------------------------------------------------
extern "C" void kernel_launch(void* const* d_in, const int* in_sizes, int n_in,
                              void* d_out, int out_size)
{
    const float* x       = (const float*)d_in[0];
    const float* norm1_w = (const float*)d_in[1];
    const float* Wx      = (const float*)d_in[2];
    const float* Wy      = (const float*)d_in[3];
    const float* conv_w  = (const float*)d_in[4];
    const float* conv_b  = (const float*)d_in[5];
    const float* Wi      = (const float*)d_in[6];
    const float* Wa      = (const float*)d_in[7];
    const float* lam     = (const float*)d_in[8];
    const float* Wo      = (const float*)d_in[9];
    const float* norm2_w = (const float*)d_in[10];
    const float* Wg      = (const float*)d_in[11];
    const float* Wu      = (const float*)d_in[12];
    const float* Wd      = (const float*)d_in[13];
    float* out = (float*)d_out;

    float *h1, *sa, *sh;
    __half *ah, *xbh, *ybh, *rl, *il, *lh, *zh, *wh;
    cudaGetSymbolAddress((void**)&h1,  g_h1);
    cudaGetSymbolAddress((void**)&sa,  g_sa);
    cudaGetSymbolAddress((void**)&sh,  g_sh);
    cudaGetSymbolAddress((void**)&ah,  g_ah);
    cudaGetSymbolAddress((void**)&xbh, g_xbh);
    cudaGetSymbolAddress((void**)&ybh, g_ybh);
    cudaGetSymbolAddress((void**)&rl,  g_rl);
    cudaGetSymbolAddress((void**)&il,  g_il);
    cudaGetSymbolAddress((void**)&lh,  g_lh);
    cudaGetSymbolAddress((void**)&zh,  g_zh);
    cudaGetSymbolAddress((void**)&wh,  g_wh);

    cudaFuncSetAttribute(hmma_gemm<0,1,false,false,true>,  cudaFuncAttributeMaxDynamicSharedMemorySize, GEMM_SMEM);
    cudaFuncSetAttribute(hmma_gemm<0,0,false,false,true>,  cudaFuncAttributeMaxDynamicSharedMemorySize, GEMM_SMEM);
    cudaFuncSetAttribute(hmma_gemm<0,0,true,false,false>,  cudaFuncAttributeMaxDynamicSharedMemorySize, GEMM_SMEM);
    cudaFuncSetAttribute(hmma_gemm<0,0,false,true,false>,  cudaFuncAttributeMaxDynamicSharedMemorySize, GEMM_SMEM);

    const dim3 tsb(32, 8);
    const int gMD2 = (int)(((size_t)MM * DD2 + 255) / 256);
    const int gSC2 = (BB * NC * DD2 + 255) / 256;

    const dim3 gemXY(2048 / 128, MM / 256);   // dual Wx|Wy (fp16 out)
    const dim3 gemAI(2048 / 128, MM / 256);   // dual Wa|Wi (fp16 out)
    const dim3 gemGU(8192 / 128, MM / 256);   // interleaved Wg|Wu (gated)
    const dim3 gemO (1024 / 128, MM / 256);   // Wo (K=1024, fp32+res)
    const dim3 gemDn(1024 / 128, MM / 256);   // Wd (K=4096, fp32+res)

    // all weight prep in ONE launch + rmsnorm1
    prep_all_kernel<<<5*1024 + 3*4096, tsb>>>(Wx, Wy, Wa, Wi, Wo, Wg, Wu, Wd, wh);
    rmsnorm_f16_kernel<<<MM, 256>>>(x, norm1_w, ah);
    // xb = t @ Wx ; yb = gelu(t @ Wy)  [dual, fp16 out]
    hmma_gemm<0,1,false,false,true><<<gemXY, 512, GEMM_SMEM>>>(ah, wh + WOFF_X,
        nullptr, nullptr, nullptr, xbh, ybh, nullptr, DD, DD);
    // conv -> ah (fp16)
    conv_f16_kernel<<<gMD2, 256>>>((const __half2*)xbh, conv_w, conv_b, (__half2*)ah);
    // rlin -> rl ; ilin -> il  [dual, fp16 out]
    hmma_gemm<0,0,false,false,true><<<gemAI, 512, GEMM_SMEM>>>(ah, wh + WOFF_A,
        nullptr, nullptr, nullptr, rl, il, nullptr, DD, DD);
    // gates + chunked scan + z = h*yb -> ah (fp16)
    scan1_kernel<<<gSC2, 256>>>((__half2*)rl, (const __half2*)il, (const __half2*)ah,
                                lam, (__half2*)lh, (float2*)sa, (float2*)sh);
    scan2_kernel<<<(BB * DD2 + 255) / 256, 256>>>((const float2*)sa, (float2*)sh);
    scan3_kernel<<<gSC2, 256>>>((const __half2*)rl, (const __half2*)lh,
                                (const float2*)sh, (const __half2*)ybh, (__half2*)ah);
    // h1 = x + z @ Wo
    hmma_gemm<0,0,true,false,false><<<gemO, 512, GEMM_SMEM>>>(ah, wh + WOFF_O,
        x, h1, h1, nullptr, nullptr, nullptr, DD, DD);
    // u = rmsnorm(h1) -> ah
    rmsnorm_f16_kernel<<<MM, 256>>>(h1, norm2_w, ah);
    // ff = gelu(u @ Wg) * (u @ Wu) -> zh  [gated]
    hmma_gemm<0,0,false,true,false><<<gemGU, 512, GEMM_SMEM>>>(ah, wh + WOFF_GU,
        nullptr, nullptr, nullptr, nullptr, nullptr, zh, HH, DD);
    // out = h1 + ff @ Wd
    hmma_gemm<0,0,true,false,false><<<gemDn, 512, GEMM_SMEM>>>(zh, wh + WOFF_D,
        h1, out, out, nullptr, nullptr, nullptr, DD, HH);
}

// round 13
// speedup vs baseline: 7.4268x; 1.0048x over previous
#include <cuda_runtime.h>
#include <cuda_fp16.h>
#include <math.h>
#include <stdint.h>

// Problem dims (fixed by the dataset)
#define BB 4
#define SS 2048
#define DD 1024
#define HH 4096
#define MM (BB*SS)          // 8192 rows
#define NC 32               // scan chunks
#define CL (SS/NC)          // 64 steps per chunk
#define DD2 (DD/2)

// ---------------------------------------------------------------------------
// Scratch (static device globals; no allocation in kernel_launch)
// ---------------------------------------------------------------------------
__device__ __align__(16) float g_h1 [(size_t)MM*DD];    // h1 trunk (fp32)
__device__ __align__(16) float g_sa [(size_t)BB*NC*DD]; // chunk a-products
__device__ __align__(16) float g_sh [(size_t)BB*NC*DD]; // chunk h-carries

// fp16 streams
__device__ __align__(16) __half g_ah [(size_t)MM*DD];  // rmsnorm out / conv out / z
__device__ __align__(16) __half g_xbh[(size_t)MM*DD];  // xb (gemXY C1)
__device__ __align__(16) __half g_ybh[(size_t)MM*DD];  // yb (gemXY C2, gelu)
__device__ __align__(16) __half g_rl [(size_t)MM*DD];  // rlin -> a (in place)
__device__ __align__(16) __half g_il [(size_t)MM*DD];  // ilin
__device__ __align__(16) __half g_lh [(size_t)MM*DD];  // scan local h (fp16)
__device__ __align__(16) __half g_zh [(size_t)MM*HH];  // gated-MLP intermediate
// fp16 transposed weights, packed arena (17M halfs)
#define WOFF_X  ((size_t)0)
#define WOFF_Y  ((size_t)1*1024*1024)   // follows X (dual Wx|Wy)
#define WOFF_A  ((size_t)2*1024*1024)
#define WOFF_I  ((size_t)3*1024*1024)   // follows A (dual Wa|Wi)
#define WOFF_O  ((size_t)4*1024*1024)
#define WOFF_GU ((size_t)5*1024*1024)   // Wg/Wu column-interleaved (8192 rows)
#define WOFF_D  ((size_t)13*1024*1024)
__device__ __align__(16) __half g_wh[(size_t)17*1024*1024];

// ---------------------------------------------------------------------------
// Math helpers
// ---------------------------------------------------------------------------
__device__ __forceinline__ float geluf(float x) {
    const float c = 0.7978845608028654f; // sqrt(2/pi)
    float x3 = x * x * x;
    float t  = tanhf(c * (x + 0.044715f * x3));
    return 0.5f * x * (1.0f + t);
}
__device__ __forceinline__ float sigmoidf(float x) {
    return 1.0f / (1.0f + expf(-x));
}
__device__ __forceinline__ float softplusf(float x) {
    return fmaxf(x, 0.0f) + log1pf(expf(-fabsf(x)));
}

// ---------------------------------------------------------------------------
// PTX helpers (baseline compute_103 features only)
// ---------------------------------------------------------------------------
__device__ __forceinline__ uint32_t smem_u32(const void* p) {
    uint32_t a;
    asm("{ .reg .u64 t; cvta.to.shared.u64 t, %1; cvt.u32.u64 %0, t; }" : "=r"(a) : "l"(p));
    return a;
}
__device__ __forceinline__ void cp_async16(uint32_t dst, const void* src) {
    asm volatile("cp.async.cg.shared.global [%0], [%1], 16;" :: "r"(dst), "l"(src) : "memory");
}
__device__ __forceinline__ void ldm_x4(uint32_t& r0, uint32_t& r1, uint32_t& r2, uint32_t& r3,
                                       uint32_t addr) {
    asm volatile("ldmatrix.sync.aligned.m8n8.x4.shared.b16 {%0,%1,%2,%3}, [%4];"
                 : "=r"(r0), "=r"(r1), "=r"(r2), "=r"(r3) : "r"(addr));
}
__device__ __forceinline__ void mma16816(float* c, const uint32_t* a, const uint32_t* b) {
    asm volatile(
        "mma.sync.aligned.m16n8k16.row.col.f32.f16.f16.f32 "
        "{%0,%1,%2,%3}, {%4,%5,%6,%7}, {%8,%9}, {%0,%1,%2,%3};"
        : "+f"(c[0]), "+f"(c[1]), "+f"(c[2]), "+f"(c[3])
        : "r"(a[0]), "r"(a[1]), "r"(a[2]), "r"(a[3]), "r"(b[0]), "r"(b[1]));
}

// ---------------------------------------------------------------------------
// Single-product fp16 HMMA GEMM: C = act(A @ W^T) (+R).
// CTA 256x128, BK=64, 16 warps (4Mx4N, warp tile 64x32), 4-stage cp.async,
// fill-distance 3, single __syncthreads per chunk, 1 CTA/SM.
// ---------------------------------------------------------------------------
#define GSTRIDE 144u
#define TILE_A  36864u            // 256 rows * 144B
#define STG_B   55296u            // A(36864) + B(18432)
#define GEMM_SMEM (4*STG_B)       // 221184

template<int ACT1, int ACT2, bool RES, bool GATED, bool OUT16>
__global__ void __launch_bounds__(512, 1)
hmma_gemm(const __half* __restrict__ Ah, const __half* __restrict__ Bh,
          const float* __restrict__ R, float* __restrict__ C1, float* __restrict__ C2,
          __half* __restrict__ H1o, __half* __restrict__ H2o,
          __half* __restrict__ ZH,
          int NH, int K)
{
    extern __shared__ char smem[];
    const uint32_t sb = smem_u32(smem);
    const int tid  = threadIdx.x;
    const int wid  = tid >> 5;
    const int lane = tid & 31;
    const int bm = blockIdx.y * 256;
    const int bn = blockIdx.x * 128;
    const int wr = wid >> 2;          // warp row 0..3 (64 rows each)
    const int wc = wid & 3;           // warp col 0..3 (32 cols each)

    const int nch = K >> 6;           // BK = 64

    auto fill = [&](int ch) {
        const int k0 = ch << 6;
        const uint32_t st = sb + (uint32_t)(ch & 3) * STG_B;
        #pragma unroll
        for (int r = 0; r < 4; r++) {            // A: 2048 16B chunks
            const int c = tid + (r << 9);
            const int row = c >> 3, kc = c & 7;
            const uint32_t dst = (uint32_t)row * GSTRIDE + (uint32_t)(kc << 4);
            cp_async16(st + dst, Ah + (size_t)(bm + row) * K + k0 + (kc << 3));
        }
        #pragma unroll
        for (int r = 0; r < 2; r++) {            // B: 1024 16B chunks
            const int c = tid + (r << 9);
            const int row = c >> 3, kc = c & 7;
            const uint32_t dst = (uint32_t)row * GSTRIDE + (uint32_t)(kc << 4);
            cp_async16(st + TILE_A + dst, Bh + (size_t)(bn + row) * K + k0 + (kc << 3));
        }
        asm volatile("cp.async.commit_group;" ::: "memory");
    };

    float acc[4][4][4];
    #pragma unroll
    for (int i = 0; i < 4; i++)
        #pragma unroll
        for (int j = 0; j < 4; j++)
            #pragma unroll
            for (int q = 0; q < 4; q++) acc[i][j][q] = 0.0f;

    fill(0);
    if (nch > 1) fill(1);
    if (nch > 2) fill(2);

    const int l16  = lane & 15;
    const int ahi  = (lane >> 4) << 4;
    const int brow = ((lane >> 4) << 3) + (lane & 7);
    const int bhi  = ((lane >> 3) & 1) << 4;

    for (int i = 0; i < nch; i++) {
        if      (i + 2 < nch) asm volatile("cp.async.wait_group 2;" ::: "memory");
        else if (i + 1 < nch) asm volatile("cp.async.wait_group 1;" ::: "memory");
        else                  asm volatile("cp.async.wait_group 0;" ::: "memory");
        __syncthreads();   // single barrier per chunk (fill-distance-3, 4 buffers)

        const uint32_t st  = sb + (uint32_t)(i & 3) * STG_B;
        const uint32_t sAh = st;
        const uint32_t sBh = st + TILE_A;

        #pragma unroll
        for (int ks = 0; ks < 4; ks++) {
            uint32_t ah[4][4];
            #pragma unroll
            for (int mt = 0; mt < 4; mt++) {
                const uint32_t ra = (uint32_t)(wr*64 + mt*16 + l16) * GSTRIDE
                                  + (uint32_t)(ks*32 + ahi);
                ldm_x4(ah[mt][0], ah[mt][1], ah[mt][2], ah[mt][3], sAh + ra);
            }
            #pragma unroll
            for (int ntp = 0; ntp < 2; ntp++) {
                uint32_t bq[4];
                const uint32_t rb = (uint32_t)(wc*32 + ntp*16 + brow) * GSTRIDE
                                  + (uint32_t)(ks*32 + bhi);
                ldm_x4(bq[0], bq[1], bq[2], bq[3], sBh + rb);
                #pragma unroll
                for (int mt = 0; mt < 4; mt++) {
                    mma16816(acc[mt][2*ntp],   ah[mt], bq);
                    mma16816(acc[mt][2*ntp+1], ah[mt], bq + 2);
                }
            }
        }
        if (i + 3 < nch) fill(i + 3);
    }

    const int erow = lane >> 2;
    const int ecol = (lane & 3) << 1;

    if constexpr (GATED) {
        #pragma unroll
        for (int mt = 0; mt < 4; mt++) {
            #pragma unroll
            for (int nt = 0; nt < 4; nt++) {
                const int r0 = bm + wr*64 + mt*16 + erow;
                const int j  = ((bn + wc*32 + nt*8 + ecol) >> 1);
                const float f0 = geluf(acc[mt][nt][0]) * acc[mt][nt][1];
                const float f1 = geluf(acc[mt][nt][2]) * acc[mt][nt][3];
                const float f0n = __shfl_down_sync(0xffffffff, f0, 1);
                const float f1n = __shfl_down_sync(0xffffffff, f1, 1);
                if ((lane & 1) == 0) {
                    *(__half2*)(ZH + (size_t)r0     * NH + j) = __floats2half2_rn(f0, f0n);
                    *(__half2*)(ZH + (size_t)(r0+8) * NH + j) = __floats2half2_rn(f1, f1n);
                }
            }
        }
        return;
    }

    if constexpr (OUT16) {
        __half* Hout;
        int act, cb;
        if (bn < NH) { Hout = H1o; act = ACT1; cb = bn; }
        else         { Hout = H2o; act = ACT2; cb = bn - NH; }
        #pragma unroll
        for (int mt = 0; mt < 4; mt++) {
            #pragma unroll
            for (int nt = 0; nt < 4; nt++) {
                const int r0 = bm + wr*64 + mt*16 + erow;
                const int cc = cb + wc*32 + nt*8 + ecol;
                float v0 = acc[mt][nt][0], v1 = acc[mt][nt][1];
                float v2 = acc[mt][nt][2], v3 = acc[mt][nt][3];
                if (act == 1) { v0 = geluf(v0); v1 = geluf(v1); v2 = geluf(v2); v3 = geluf(v3); }
                *(__half2*)(Hout + (size_t)r0     * NH + cc) =
                    __floats2half2_rn(v0, v1);
                *(__half2*)(Hout + (size_t)(r0+8) * NH + cc) =
                    __floats2half2_rn(v2, v3);
            }
        }
        return;
    }

    // fp32 epilogue (with residual)
    float* Cout;
    int act, cb;
    if (bn < NH) { Cout = C1; act = ACT1; cb = bn; }
    else         { Cout = C2; act = ACT2; cb = bn - NH; }

    #pragma unroll
    for (int mt = 0; mt < 4; mt++) {
        #pragma unroll
        for (int nt = 0; nt < 4; nt++) {
            const int r0 = bm + wr*64 + mt*16 + erow;
            const int cc = cb + wc*32 + nt*8 + ecol;
            float v0 = acc[mt][nt][0], v1 = acc[mt][nt][1];
            float v2 = acc[mt][nt][2], v3 = acc[mt][nt][3];
            if (act == 1) { v0 = geluf(v0); v1 = geluf(v1); v2 = geluf(v2); v3 = geluf(v3); }
            if (RES) {
                const float2 ra = *(const float2*)(R + (size_t)r0 * NH + cc);
                const float2 rb = *(const float2*)(R + (size_t)(r0+8) * NH + cc);
                v0 += ra.x; v1 += ra.y; v2 += rb.x; v3 += rb.y;
            }
            *(float2*)(Cout + (size_t)r0     * NH + cc) = make_float2(v0, v1);
            *(float2*)(Cout + (size_t)(r0+8) * NH + cc) = make_float2(v2, v3);
        }
    }
}

// ---------------------------------------------------------------------------
// Weight transpose to fp16 with half2-vectorized stores.
// Single fused kernel: flattened grid over all 8 transposes.
// ---------------------------------------------------------------------------
__device__ __forceinline__ void tsplit_body(const float* __restrict__ W,
                                            __half* __restrict__ Th,
                                            int Kd, int Nd, int rstride, int roff,
                                            int bx, int by)
{
    __shared__ float tile[32][33];   // [k_local][n_local]
    const int n0 = bx * 32, k0 = by * 32;
    const int tx = threadIdx.x, ty = threadIdx.y;   // (32, 8)
    #pragma unroll
    for (int i = 0; i < 32; i += 8)
        tile[ty + i][tx] = W[(size_t)(k0 + ty + i) * Nd + n0 + tx];
    __syncthreads();
    // half2-packed stores: lane handles k pair (2*(tx&15)), rows ty + (tx>>4)*8 (+0/+16)
    const int j  = tx & 15;
    const int nn = ty + ((tx >> 4) << 3);
    #pragma unroll
    for (int i = 0; i < 32; i += 16) {
        const float v0 = tile[2*j][nn + i];
        const float v1 = tile[2*j + 1][nn + i];
        const size_t o = ((size_t)(n0 + nn + i) * rstride + roff) * Kd + k0 + 2*j;
        *(__half2*)&Th[o] = __floats2half2_rn(v0, v1);
    }
}

__global__ void prep_all_kernel(const float* __restrict__ Wx, const float* __restrict__ Wy,
                                const float* __restrict__ Wa, const float* __restrict__ Wi,
                                const float* __restrict__ Wo, const float* __restrict__ Wg,
                                const float* __restrict__ Wu, const float* __restrict__ Wd,
                                __half* __restrict__ wh)
{
    int b = blockIdx.x;
    if (b < 5 * 1024) {
        const int w = b >> 10;
        const int t = b & 1023;
        const float* W;
        size_t off;
        switch (w) {
            case 0:  W = Wx; off = WOFF_X; break;
            case 1:  W = Wy; off = WOFF_Y; break;
            case 2:  W = Wa; off = WOFF_A; break;
            case 3:  W = Wi; off = WOFF_I; break;
            default: W = Wo; off = WOFF_O; break;
        }
        tsplit_body(W, wh + off, DD, DD, 1, 0, t & 31, t >> 5);
        return;
    }
    b -= 5 * 1024;
    if (b < 4096) {        // Wg: even interleaved rows
        tsplit_body(Wg, wh + WOFF_GU, DD, HH, 2, 0, b & 127, b >> 7);
        return;
    }
    b -= 4096;
    if (b < 4096) {        // Wu: odd interleaved rows
        tsplit_body(Wu, wh + WOFF_GU, DD, HH, 2, 1, b & 127, b >> 7);
        return;
    }
    b -= 4096;             // Wd
    tsplit_body(Wd, wh + WOFF_D, HH, DD, 1, 0, b & 31, b >> 5);
}

// ---------------------------------------------------------------------------
// RMSNorm with fp16 output (float2 / half2 vectorized; D=1024, 256 threads)
// ---------------------------------------------------------------------------
__global__ void rmsnorm_f16_kernel(const float* __restrict__ x,
                                   const float* __restrict__ w,
                                   __half* __restrict__ oh)
{
    const int row = blockIdx.x;
    const float2* xr = (const float2*)(x + (size_t)row * DD);
    const float2* w2 = (const float2*)w;
    float ss = 0.0f;
    float2 v[2];
    #pragma unroll
    for (int r = 0; r < 2; r++) {
        v[r] = xr[threadIdx.x + r * 256];
        ss = fmaf(v[r].x, v[r].x, fmaf(v[r].y, v[r].y, ss));
    }
    #pragma unroll
    for (int off = 16; off > 0; off >>= 1)
        ss += __shfl_xor_sync(0xffffffff, ss, off);
    __shared__ float red[8];
    const int lane = threadIdx.x & 31, wid = threadIdx.x >> 5;
    if (lane == 0) red[wid] = ss;
    __syncthreads();
    if (wid == 0) {
        float s = (lane < 8) ? red[lane] : 0.0f;
        #pragma unroll
        for (int off = 4; off > 0; off >>= 1)
            s += __shfl_xor_sync(0xffffffff, s, off);
        if (lane == 0) red[0] = s;
    }
    __syncthreads();
    const float inv = rsqrtf(red[0] / (float)DD + 1e-6f);
    __half2* o2 = (__half2*)(oh + (size_t)row * DD);
    #pragma unroll
    for (int r = 0; r < 2; r++) {
        const float2 ww = w2[threadIdx.x + r * 256];
        o2[threadIdx.x + r * 256] =
            __floats2half2_rn(v[r].x * inv * ww.x, v[r].y * inv * ww.y);
    }
}

// ---------------------------------------------------------------------------
// Causal depthwise conv (K=4), half2 vectorized, 4 sequence positions/thread.
// Loads 7 input rows once into registers (vs 4 loads per output before).
// ---------------------------------------------------------------------------
#define S4 (SS/4)
__global__ void conv_f16_kernel(const __half2* __restrict__ in,
                                const float* __restrict__ cw,
                                const float* __restrict__ cb,
                                __half2* __restrict__ oh)
{
    const int idx = blockIdx.x * blockDim.x + threadIdx.x;
    if (idx >= BB * S4 * DD2) return;
    const int d2    = idx % DD2;
    const int s4    = (idx / DD2) % S4;
    const int batch = idx / (DD2 * S4);
    const int s0    = s4 * 4;
    const size_t base = ((size_t)batch * SS + s0) * DD2 + d2;

    // input rows s0-3 .. s0+3  ->  v[0..6]
    float2 v[7];
    #pragma unroll
    for (int i = 0; i < 7; i++) {
        const int s = s0 + i - 3;
        v[i] = (s >= 0) ? __half22float2(in[base + (size_t)(i - 3) * DD2])
                        : make_float2(0.0f, 0.0f);
    }
    float w0[4], w1[4];
    #pragma unroll
    for (int k = 0; k < 4; k++) {
        w0[k] = cw[k * DD + 2*d2];
        w1[k] = cw[k * DD + 2*d2 + 1];
    }
    const float b0 = cb[2*d2], b1 = cb[2*d2 + 1];

    #pragma unroll
    for (int j = 0; j < 4; j++) {
        float a0 = b0, a1 = b1;
        #pragma unroll
        for (int k = 0; k < 4; k++) {
            a0 = fmaf(w0[k], v[j + k].x, a0);
            a1 = fmaf(w1[k], v[j + k].y, a1);
        }
        oh[base + (size_t)j * DD2] = __floats2half2_rn(a0, a1);
    }
}

// ---------------------------------------------------------------------------
// Scan pass 1 (half2): gates + chunk-local scan.
// ---------------------------------------------------------------------------
__global__ void scan1_kernel(__half2* __restrict__ rlin_a,
                             const __half2* __restrict__ ilin,
                             const __half2* __restrict__ xc,
                             const float* __restrict__ lam,
                             __half2* __restrict__ lh,
                             float2* __restrict__ sa,
                             float2* __restrict__ sh)
{
    const int idx = blockIdx.x * blockDim.x + threadIdx.x;
    if (idx >= BB * NC * DD2) return;
    const int d2    = idx % DD2;
    const int chunk = (idx / DD2) % NC;
    const int batch = idx / (DD2 * NC);
    const float cf0 = -8.0f * softplusf(lam[2*d2]);
    const float cf1 = -8.0f * softplusf(lam[2*d2 + 1]);
    const size_t base = ((size_t)batch * SS + (size_t)chunk * CL) * DD2 + d2;

    float p0 = 1.0f, p1 = 1.0f, h0 = 0.0f, h1 = 0.0f;
    for (int t = 0; t < CL; t++) {
        const size_t off = base + (size_t)t * DD2;
        const float2 rv = __half22float2(rlin_a[off]);
        const float2 iv = __half22float2(ilin[off]);
        const float2 xv = __half22float2(xc[off]);
        const float a0 = expf(cf0 * sigmoidf(rv.x));
        const float a1 = expf(cf1 * sigmoidf(rv.y));
        const float b0 = sqrtf(fmaxf(1.0f - a0*a0, 1e-12f)) * sigmoidf(iv.x) * xv.x;
        const float b1 = sqrtf(fmaxf(1.0f - a1*a1, 1e-12f)) * sigmoidf(iv.y) * xv.y;
        h0 = fmaf(a0, h0, b0);
        h1 = fmaf(a1, h1, b1);
        p0 *= a0; p1 *= a1;
        rlin_a[off] = __floats2half2_rn(a0, a1);
        lh[off]     = __floats2half2_rn(h0, h1);
    }
    sa[idx] = make_float2(p0, p1);
    sh[idx] = make_float2(h0, h1);
}

// ---------------------------------------------------------------------------
// Scan pass 2 (float2): combine chunk carries.
// ---------------------------------------------------------------------------
__global__ void scan2_kernel(const float2* __restrict__ sa, float2* __restrict__ sh)
{
    const int idx = blockIdx.x * blockDim.x + threadIdx.x;
    if (idx >= BB * DD2) return;
    const int d2 = idx % DD2, batch = idx / DD2;
    float H0 = 0.0f, H1 = 0.0f;
    for (int c = 0; c < NC; c++) {
        const size_t o = ((size_t)batch * NC + c) * DD2 + d2;
        const float2 av = sa[o];
        const float2 hv = sh[o];
        H0 = fmaf(av.x, H0, hv.x);
        H1 = fmaf(av.y, H1, hv.y);
        sh[o] = make_float2(H0, H1);
    }
}

// ---------------------------------------------------------------------------
// Scan pass 3 (half2): apply carries, z = h * yb, fp16 out.
// ---------------------------------------------------------------------------
__global__ void scan3_kernel(const __half2* __restrict__ aArr,
                             const __half2* __restrict__ lhArr,
                             const float2* __restrict__ sh,
                             const __half2* __restrict__ yb,
                             __half2* __restrict__ zh)
{
    const int idx = blockIdx.x * blockDim.x + threadIdx.x;
    if (idx >= BB * NC * DD2) return;
    const int d2    = idx % DD2;
    const int chunk = (idx / DD2) % NC;
    const int batch = idx / (DD2 * NC);
    float c0 = 0.0f, c1 = 0.0f;
    if (chunk != 0) {
        const float2 cv = sh[((size_t)batch * NC + chunk - 1) * DD2 + d2];
        c0 = cv.x; c1 = cv.y;
    }
    const size_t base = ((size_t)batch * SS + (size_t)chunk * CL) * DD2 + d2;

    float p0 = 1.0f, p1 = 1.0f;
    for (int t = 0; t < CL; t++) {
        const size_t off = base + (size_t)t * DD2;
        const float2 av = __half22float2(aArr[off]);
        const float2 lv = __half22float2(lhArr[off]);
        const float2 yv = __half22float2(yb[off]);
        p0 *= av.x; p1 *= av.y;
        const float z0 = fmaf(p0, c0, lv.x) * yv.x;
        const float z1 = fmaf(p1, c1, lv.y) * yv.y;
        zh[off] = __floats2half2_rn(z0, z1);
    }
}

// ---------------------------------------------------------------------------
// Launch
// ---------------------------------------------------------------------------
extern "C" void kernel_launch(void* const* d_in, const int* in_sizes, int n_in,
                              void* d_out, int out_size)
{
    const float* x       = (const float*)d_in[0];
    const float* norm1_w = (const float*)d_in[1];
    const float* Wx      = (const float*)d_in[2];
    const float* Wy      = (const float*)d_in[3];
    const float* conv_w  = (const float*)d_in[4];
    const float* conv_b  = (const float*)d_in[5];
    const float* Wi      = (const float*)d_in[6];
    const float* Wa      = (const float*)d_in[7];
    const float* lam     = (const float*)d_in[8];
    const float* Wo      = (const float*)d_in[9];
    const float* norm2_w = (const float*)d_in[10];
    const float* Wg      = (const float*)d_in[11];
    const float* Wu      = (const float*)d_in[12];
    const float* Wd      = (const float*)d_in[13];
    float* out = (float*)d_out;

    float *h1, *sa, *sh;
    __half *ah, *xbh, *ybh, *rl, *il, *lh, *zh, *wh;
    cudaGetSymbolAddress((void**)&h1,  g_h1);
    cudaGetSymbolAddress((void**)&sa,  g_sa);
    cudaGetSymbolAddress((void**)&sh,  g_sh);
    cudaGetSymbolAddress((void**)&ah,  g_ah);
    cudaGetSymbolAddress((void**)&xbh, g_xbh);
    cudaGetSymbolAddress((void**)&ybh, g_ybh);
    cudaGetSymbolAddress((void**)&rl,  g_rl);
    cudaGetSymbolAddress((void**)&il,  g_il);
    cudaGetSymbolAddress((void**)&lh,  g_lh);
    cudaGetSymbolAddress((void**)&zh,  g_zh);
    cudaGetSymbolAddress((void**)&wh,  g_wh);

    cudaFuncSetAttribute(hmma_gemm<0,1,false,false,true>,  cudaFuncAttributeMaxDynamicSharedMemorySize, GEMM_SMEM);
    cudaFuncSetAttribute(hmma_gemm<0,0,false,false,true>,  cudaFuncAttributeMaxDynamicSharedMemorySize, GEMM_SMEM);
    cudaFuncSetAttribute(hmma_gemm<0,0,true,false,false>,  cudaFuncAttributeMaxDynamicSharedMemorySize, GEMM_SMEM);
    cudaFuncSetAttribute(hmma_gemm<0,0,false,true,false>,  cudaFuncAttributeMaxDynamicSharedMemorySize, GEMM_SMEM);

    const dim3 tsb(32, 8);
    const int gCV = (BB * S4 * DD2 + 255) / 256;     // conv: 4 s-positions/thread
    const int gSC2 = (BB * NC * DD2 + 255) / 256;

    const dim3 gemXY(2048 / 128, MM / 256);   // dual Wx|Wy (fp16 out)
    const dim3 gemAI(2048 / 128, MM / 256);   // dual Wa|Wi (fp16 out)
    const dim3 gemGU(8192 / 128, MM / 256);   // interleaved Wg|Wu (gated)
    const dim3 gemO (1024 / 128, MM / 256);   // Wo (K=1024, fp32+res)
    const dim3 gemDn(1024 / 128, MM / 256);   // Wd (K=4096, fp32+res)

    // all weight prep in ONE launch + rmsnorm1
    prep_all_kernel<<<5*1024 + 3*4096, tsb>>>(Wx, Wy, Wa, Wi, Wo, Wg, Wu, Wd, wh);
    rmsnorm_f16_kernel<<<MM, 256>>>(x, norm1_w, ah);
    // xb = t @ Wx ; yb = gelu(t @ Wy)  [dual, fp16 out]
    hmma_gemm<0,1,false,false,true><<<gemXY, 512, GEMM_SMEM>>>(ah, wh + WOFF_X,
        nullptr, nullptr, nullptr, xbh, ybh, nullptr, DD, DD);
    // conv -> ah (fp16)
    conv_f16_kernel<<<gCV, 256>>>((const __half2*)xbh, conv_w, conv_b, (__half2*)ah);
    // rlin -> rl ; ilin -> il  [dual, fp16 out]
    hmma_gemm<0,0,false,false,true><<<gemAI, 512, GEMM_SMEM>>>(ah, wh + WOFF_A,
        nullptr, nullptr, nullptr, rl, il, nullptr, DD, DD);
    // gates + chunked scan + z = h*yb -> ah (fp16)
    scan1_kernel<<<gSC2, 256>>>((__half2*)rl, (const __half2*)il, (const __half2*)ah,
                                lam, (__half2*)lh, (float2*)sa, (float2*)sh);
    scan2_kernel<<<(BB * DD2 + 255) / 256, 256>>>((const float2*)sa, (float2*)sh);
    scan3_kernel<<<gSC2, 256>>>((const __half2*)rl, (const __half2*)lh,
                                (const float2*)sh, (const __half2*)ybh, (__half2*)ah);
    // h1 = x + z @ Wo
    hmma_gemm<0,0,true,false,false><<<gemO, 512, GEMM_SMEM>>>(ah, wh + WOFF_O,
        x, h1, h1, nullptr, nullptr, nullptr, DD, DD);
    // u = rmsnorm(h1) -> ah
    rmsnorm_f16_kernel<<<MM, 256>>>(h1, norm2_w, ah);
    // ff = gelu(u @ Wg) * (u @ Wu) -> zh  [gated]
    hmma_gemm<0,0,false,true,false><<<gemGU, 512, GEMM_SMEM>>>(ah, wh + WOFF_GU,
        nullptr, nullptr, nullptr, nullptr, nullptr, zh, HH, DD);
    // out = h1 + ff @ Wd
    hmma_gemm<0,0,true,false,false><<<gemDn, 512, GEMM_SMEM>>>(zh, wh + WOFF_D,
        h1, out, out, nullptr, nullptr, nullptr, DD, HH);
}